// round 5
// baseline (speedup 1.0000x reference)
#include <cuda_runtime.h>
#include <math.h>

#define NN 100000
#define NE 1600000
#define FD 16
#define HD 128
#define TILE 32
#define NT (NN / TILE)   // 3125 exact

// ---------------- scratch (static device globals; no allocation) ----------------
__device__ float g_h[NN * HD];
__device__ float g_hz[NN * HD];
__device__ float g_fz[NN * HD];
__device__ float g_neigh[NN * HD];
__device__ float g_ah[NN];
__device__ float g_af[NN];
__device__ float g_emax[NN];
__device__ float g_esum[NN];
__device__ float g_sbit[NN];
__device__ float g_e[NE];
__device__ float g_ee[NE];
__device__ float g_wha[HD];
__device__ float g_wfa[FD];
__device__ float g_aw;
__device__ float g_ab;

__device__ __forceinline__ void atomicMaxFloat(float* addr, float value) {
    if (value >= 0.0f)
        atomicMax((int*)addr, __float_as_int(value));
    else
        atomicMin((unsigned int*)addr, __float_as_uint(value));
}

// ---------------- K0: fold attn into weights ----------------
// wha[k]  = sum_j W_nm[k][j]      * attn[j]   (k in 0..127, the h-rows)
// wfa[i]  = sum_j W_nm[129+i][j]  * attn[j]   (feat rows)
// aw      = sum_j W_nm[128][j]    * attn[j]   (bit row)
// ab      = sum_j b_nm[j]         * attn[j]
__global__ void precompute_kernel(const float* __restrict__ Wnm,
                                  const float* __restrict__ bnm,
                                  const float* __restrict__ attn) {
    __shared__ float sattn[HD];
    int tid = threadIdx.x;
    if (tid < HD) sattn[tid] = attn[tid];
    __syncthreads();
    if (tid < HD) {
        float s = 0.f;
        #pragma unroll 8
        for (int j = 0; j < HD; j++) s += Wnm[tid * HD + j] * sattn[j];
        g_wha[tid] = s;
    } else if (tid < HD + FD) {
        int i = tid - HD;
        float s = 0.f;
        #pragma unroll 8
        for (int j = 0; j < HD; j++) s += Wnm[(129 + i) * HD + j] * sattn[j];
        g_wfa[i] = s;
    } else if (tid == HD + FD) {
        float s = 0.f;
        for (int j = 0; j < HD; j++) s += Wnm[128 * HD + j] * sattn[j];
        g_aw = s;
    } else if (tid == HD + FD + 1) {
        float s = 0.f;
        for (int j = 0; j < HD; j++) s += bnm[j] * sattn[j];
        g_ab = s;
    }
}

// ---------------- K1a: mlp_self -> g_h, fz -> g_fz, a_f, init accumulators ----------------
// dyn smem layout (floats): W1 1024 | W2 8192 | Wf 2048 | b1 64 | b2 128 | wfa 16 | feat 512 | hid 2048
#define DYN1 ((1024 + 8192 + 2048 + 64 + 128 + 16 + 512 + 2048) * 4)
__global__ void node_pre_kernel(const float* __restrict__ feat,
                                const float* __restrict__ W1, const float* __restrict__ b1,
                                const float* __restrict__ W2, const float* __restrict__ b2,
                                const float* __restrict__ Wnm) {
    extern __shared__ float sm1[];
    float* sW1  = sm1;
    float* sW2  = sW1 + 1024;
    float* sWf  = sW2 + 8192;
    float* sb1  = sWf + 2048;
    float* sb2  = sb1 + 64;
    float* swfa = sb2 + 128;
    float* sfeat = swfa + 16;
    float* shid  = sfeat + 512;

    const int tid = threadIdx.x;
    const int n0 = blockIdx.x * TILE;

    for (int i = tid; i < 1024; i += 256) sW1[i] = W1[i];
    for (int i = tid; i < 8192; i += 256) sW2[i] = W2[i];
    for (int i = tid; i < 2048; i += 256) sWf[i] = Wnm[(129 + (i >> 7)) * HD + (i & 127)];
    if (tid < 64)  sb1[tid] = b1[tid];
    if (tid < 128) sb2[tid] = b2[tid];
    if (tid < 16)  swfa[tid] = g_wfa[tid];
    for (int i = tid; i < TILE * FD; i += 256) sfeat[i] = feat[n0 * FD + i];
    __syncthreads();

    // hidden layer: 32 nodes x 64
    for (int i = tid; i < TILE * 64; i += 256) {
        int n = i >> 6, j = i & 63;
        float acc = sb1[j];
        #pragma unroll
        for (int k = 0; k < FD; k++) acc += sfeat[n * FD + k] * sW1[k * 64 + j];
        shid[i] = (acc >= 0.f) ? acc : 0.1f * acc;
    }
    __syncthreads();

    // h layer + fz + zero neigh
    for (int i = tid; i < TILE * HD; i += 256) {
        int n = i >> 7, j = i & 127;
        int gn = n0 + n;
        float acc = sb2[j];
        #pragma unroll 16
        for (int k = 0; k < 64; k++) acc += shid[n * 64 + k] * sW2[k * HD + j];
        g_h[gn * HD + j] = acc;
        float fa = 0.f;
        #pragma unroll
        for (int k = 0; k < FD; k++) fa += sfeat[n * FD + k] * sWf[k * HD + j];
        g_fz[gn * HD + j] = fa;
        g_neigh[gn * HD + j] = 0.f;
    }
    // per-node scalars + edge accumulator init
    if (tid < TILE) {
        int gn = n0 + tid;
        float af = 0.f;
        #pragma unroll
        for (int k = 0; k < FD; k++) af += sfeat[tid * FD + k] * swfa[k];
        g_af[gn] = af;
        g_esum[gn] = 0.f;
        g_sbit[gn] = 0.f;
        g_emax[gn] = __int_as_float(0xff800000); // -inf
    }
}

// ---------------- K1b: hz = h @ W_nm[0:128], a_h = h . wha ----------------
// dyn smem (floats): Wh 16384 | hT 128*36 = 4608 | wha 128
#define DYN2 ((16384 + 4608 + 128) * 4)
__global__ void hz_kernel(const float* __restrict__ Wnm) {
    extern __shared__ float sm2[];
    float* sWh  = sm2;
    float* hT   = sm2 + 16384;   // [k][n] padded row stride 36
    float* swha = hT + 4608;

    const int tid = threadIdx.x;
    const int n0 = blockIdx.x * TILE;

    for (int i = tid; i < 16384; i += 256) sWh[i] = Wnm[i];
    if (tid < HD) swha[tid] = g_wha[tid];
    for (int i = tid; i < TILE * HD; i += 256) {
        int n = i >> 7, k = i & 127;
        hT[k * 36 + n] = g_h[(n0 + n) * HD + k];
    }
    __syncthreads();

    const int rt = tid >> 5;          // warp id -> row tile (4 rows)
    const int ct = tid & 31;          // lane -> col tile (4 cols)
    const int r0 = rt * 4, c0 = ct * 4;

    float a00=0,a01=0,a02=0,a03=0, a10=0,a11=0,a12=0,a13=0;
    float a20=0,a21=0,a22=0,a23=0, a30=0,a31=0,a32=0,a33=0;
    #pragma unroll 4
    for (int k = 0; k < HD; k++) {
        float4 a = *(const float4*)&hT[k * 36 + r0];
        float4 b = *(const float4*)&sWh[k * HD + c0];
        a00 += a.x*b.x; a01 += a.x*b.y; a02 += a.x*b.z; a03 += a.x*b.w;
        a10 += a.y*b.x; a11 += a.y*b.y; a12 += a.y*b.z; a13 += a.y*b.w;
        a20 += a.z*b.x; a21 += a.z*b.y; a22 += a.z*b.z; a23 += a.z*b.w;
        a30 += a.w*b.x; a31 += a.w*b.y; a32 += a.w*b.z; a33 += a.w*b.w;
    }
    float* o0 = &g_hz[(n0 + r0 + 0) * HD + c0];
    float* o1 = &g_hz[(n0 + r0 + 1) * HD + c0];
    float* o2 = &g_hz[(n0 + r0 + 2) * HD + c0];
    float* o3 = &g_hz[(n0 + r0 + 3) * HD + c0];
    *(float4*)o0 = make_float4(a00,a01,a02,a03);
    *(float4*)o1 = make_float4(a10,a11,a12,a13);
    *(float4*)o2 = make_float4(a20,a21,a22,a23);
    *(float4*)o3 = make_float4(a30,a31,a32,a33);

    if (tid < TILE) {
        float s = 0.f;
        #pragma unroll 8
        for (int k = 0; k < HD; k++) s += hT[k * 36 + tid] * swha[k];
        g_ah[n0 + tid] = s;
    }
}

// ---------------- K2: edge logits + segment max ----------------
__global__ void edge1_kernel(const float* __restrict__ bit,
                             const int* __restrict__ src, const int* __restrict__ dst) {
    int e = blockIdx.x * blockDim.x + threadIdx.x;
    if (e >= NE) return;
    int s = src[e], d = dst[e];
    float v = g_ah[s] + g_af[d] + g_aw * bit[e] + g_ab;
    v = (v >= 0.f) ? v : 0.2f * v;
    g_e[e] = v;
    atomicMaxFloat(&g_emax[d], v);
}

// ---------------- K3: exp + segment sum ----------------
__global__ void edge2_kernel(const int* __restrict__ dst) {
    int e = blockIdx.x * blockDim.x + threadIdx.x;
    if (e >= NE) return;
    int d = dst[e];
    float ee = expf(g_e[e] - g_emax[d]);
    g_ee[e] = ee;
    atomicAdd(&g_esum[d], ee);
}

// ---------------- K4: weighted scatter  neigh[d] += alpha * hz[s],  sbit[d] += alpha*bit ----------------
// one warp per edge; each lane owns 4 of the 128 channels (float4 + vector red)
__global__ void edge3_kernel(const float* __restrict__ bit,
                             const int* __restrict__ src, const int* __restrict__ dst) {
    int w = (blockIdx.x * blockDim.x + threadIdx.x) >> 5;
    int lane = threadIdx.x & 31;
    if (w >= NE) return;
    int s = src[w], d = dst[w];
    float alpha = g_ee[w] / g_esum[d];
    float4 v = *(const float4*)&g_hz[s * HD + lane * 4];
    v.x *= alpha; v.y *= alpha; v.z *= alpha; v.w *= alpha;
    float* p = &g_neigh[d * HD + lane * 4];
    asm volatile("red.global.add.v4.f32 [%0], {%1, %2, %3, %4};"
                 :: "l"(p), "f"(v.x), "f"(v.y), "f"(v.z), "f"(v.w) : "memory");
    if (lane == 0) atomicAdd(&g_sbit[d], alpha * bit[w]);
}

// ---------------- K5: finalize neigh, relu, mlp_out -> out ----------------
// dyn smem (floats): Wo1 16384 | tT 4608 | wbit 128 | bnm 128 | b1 128 | w2 128 | flag 32 | sb 32
#define DYN3 ((16384 + 4608 + 128 + 128 + 128 + 128 + 32 + 32) * 4)
__global__ void out_kernel(const float* __restrict__ Wnm, const float* __restrict__ bnm,
                           const float* __restrict__ Wo1, const float* __restrict__ bo1,
                           const float* __restrict__ Wo2, const float* __restrict__ bo2,
                           float* __restrict__ out) {
    extern __shared__ float sm3[];
    float* sWo   = sm3;
    float* tT    = sm3 + 16384;        // [k][n] stride 36
    float* swbit = tT + 4608;
    float* sbnm  = swbit + 128;
    float* sb1   = sbnm + 128;
    float* sw2   = sb1 + 128;
    float* sflag = sw2 + 128;
    float* ssb   = sflag + 32;

    const int tid = threadIdx.x;
    const int n0 = blockIdx.x * TILE;

    for (int i = tid; i < 16384; i += 256) sWo[i] = Wo1[i];
    if (tid < 128) {
        swbit[tid] = Wnm[128 * HD + tid];
        sbnm[tid]  = bnm[tid];
        sb1[tid]   = bo1[tid];
        sw2[tid]   = Wo2[tid];
    }
    if (tid < TILE) {
        int gn = n0 + tid;
        sflag[tid] = (g_esum[gn] > 0.f) ? 1.f : 0.f;
        ssb[tid]   = g_sbit[gn];
    }
    __syncthreads();

    // build t = relu(neigh_final) transposed into shared
    for (int i = tid; i < TILE * HD; i += 256) {
        int n = i >> 7, k = i & 127;
        int gn = n0 + n;
        float t = 0.f;
        if (sflag[n] != 0.f) {
            t = g_neigh[gn * HD + k] + ssb[n] * swbit[k] + g_fz[gn * HD + k] + sbnm[k];
            t = (t > 0.f) ? t : 0.f;
        }
        tT[k * 36 + n] = t;
    }
    __syncthreads();

    const int rt = tid >> 5;
    const int ct = tid & 31;
    const int r0 = rt * 4, c0 = ct * 4;

    float a00=0,a01=0,a02=0,a03=0, a10=0,a11=0,a12=0,a13=0;
    float a20=0,a21=0,a22=0,a23=0, a30=0,a31=0,a32=0,a33=0;
    #pragma unroll 4
    for (int k = 0; k < HD; k++) {
        float4 a = *(const float4*)&tT[k * 36 + r0];
        float4 b = *(const float4*)&sWo[k * HD + c0];
        a00 += a.x*b.x; a01 += a.x*b.y; a02 += a.x*b.z; a03 += a.x*b.w;
        a10 += a.y*b.x; a11 += a.y*b.y; a12 += a.y*b.z; a13 += a.y*b.w;
        a20 += a.z*b.x; a21 += a.z*b.y; a22 += a.z*b.z; a23 += a.z*b.w;
        a30 += a.w*b.x; a31 += a.w*b.y; a32 += a.w*b.z; a33 += a.w*b.w;
    }

    // lrelu(u, 0.1) dot w2, reduce across lanes (each warp owns 4 rows, lanes span all 128 cols)
    float b2 = bo2[0];
    float p[4];
    {
        float u;
        float w0 = sw2[c0 + 0], w1 = sw2[c0 + 1], w2v = sw2[c0 + 2], w3 = sw2[c0 + 3];
        float c0b = sb1[c0 + 0], c1b = sb1[c0 + 1], c2b = sb1[c0 + 2], c3b = sb1[c0 + 3];
        #define LR(x) ((x) >= 0.f ? (x) : 0.1f * (x))
        u = a00 + c0b; p[0]  = LR(u) * w0;
        u = a01 + c1b; p[0] += LR(u) * w1;
        u = a02 + c2b; p[0] += LR(u) * w2v;
        u = a03 + c3b; p[0] += LR(u) * w3;
        u = a10 + c0b; p[1]  = LR(u) * w0;
        u = a11 + c1b; p[1] += LR(u) * w1;
        u = a12 + c2b; p[1] += LR(u) * w2v;
        u = a13 + c3b; p[1] += LR(u) * w3;
        u = a20 + c0b; p[2]  = LR(u) * w0;
        u = a21 + c1b; p[2] += LR(u) * w1;
        u = a22 + c2b; p[2] += LR(u) * w2v;
        u = a23 + c3b; p[2] += LR(u) * w3;
        u = a30 + c0b; p[3]  = LR(u) * w0;
        u = a31 + c1b; p[3] += LR(u) * w1;
        u = a32 + c2b; p[3] += LR(u) * w2v;
        u = a33 + c3b; p[3] += LR(u) * w3;
        #undef LR
    }
    #pragma unroll
    for (int r = 0; r < 4; r++) {
        float v = p[r];
        #pragma unroll
        for (int o = 16; o > 0; o >>= 1) v += __shfl_down_sync(0xffffffffu, v, o);
        if (ct == 0) out[n0 + r0 + r] = v + b2;
    }
}

// ---------------- launch ----------------
extern "C" void kernel_launch(void* const* d_in, const int* in_sizes, int n_in,
                              void* d_out, int out_size) {
    const float* feat = (const float*)d_in[0];
    const float* bit  = (const float*)d_in[1];
    const int*   src  = (const int*)d_in[2];
    const int*   dst  = (const int*)d_in[3];
    const float* W1   = (const float*)d_in[4];
    const float* b1   = (const float*)d_in[5];
    const float* W2   = (const float*)d_in[6];
    const float* b2   = (const float*)d_in[7];
    const float* Wnm  = (const float*)d_in[8];
    const float* bnm  = (const float*)d_in[9];
    const float* attn = (const float*)d_in[10];
    const float* Wo1  = (const float*)d_in[11];
    const float* bo1  = (const float*)d_in[12];
    const float* Wo2  = (const float*)d_in[13];
    const float* bo2  = (const float*)d_in[14];
    float* out = (float*)d_out;

    cudaFuncSetAttribute(node_pre_kernel, cudaFuncAttributeMaxDynamicSharedMemorySize, DYN1);
    cudaFuncSetAttribute(hz_kernel,       cudaFuncAttributeMaxDynamicSharedMemorySize, DYN2);
    cudaFuncSetAttribute(out_kernel,      cudaFuncAttributeMaxDynamicSharedMemorySize, DYN3);

    precompute_kernel<<<1, 160>>>(Wnm, bnm, attn);
    node_pre_kernel<<<NT, 256, DYN1>>>(feat, W1, b1, W2, b2, Wnm);
    hz_kernel<<<NT, 256, DYN2>>>(Wnm);
    edge1_kernel<<<NE / 256, 256>>>(bit, src, dst);
    edge2_kernel<<<NE / 256, 256>>>(dst);
    edge3_kernel<<<NE / 8, 256>>>(bit, src, dst);
    out_kernel<<<NT, 256, DYN3>>>(Wnm, bnm, Wo1, bo1, Wo2, bo2, out);
}

// round 6
// speedup vs baseline: 1.3010x; 1.3010x over previous
#include <cuda_runtime.h>
#include <math.h>

#define NN 100000
#define NE 1600000
#define FD 16
#define HD 128
#define TILE 32
#define NT (NN / TILE)            // 3125 exact
#define SCAN_T 1024
#define SCAN_NB ((NN + SCAN_T - 1) / SCAN_T)   // 98

// ---------------- scratch (static device globals; no allocation) ----------------
__device__ float g_h[NN * HD];
__device__ float g_hz[NN * HD];
__device__ float g_fz[NN * HD];
__device__ float g_t[NN * HD];        // relu(neigh_final), input to mlp_out
__device__ float g_ah[NN];
__device__ float g_af[NN];
__device__ float g_wha[HD];
__device__ float g_wfa[FD];
__device__ float g_aw;
__device__ float g_ab;
// CSR build
__device__ int   g_deg[NN];
__device__ int   g_off[NN];
__device__ int   g_cursor[NN];
__device__ int   g_bsum[SCAN_NB];
__device__ int   g_bpre[SCAN_NB];
// permuted edges: x = ah[src]+aw*bit+ab, y = bit, z = bits(src), w unused
__device__ float4 g_edge[NE];

// ---------------- K0: fold attn into weights ----------------
__global__ void precompute_kernel(const float* __restrict__ Wnm,
                                  const float* __restrict__ bnm,
                                  const float* __restrict__ attn) {
    __shared__ float sattn[HD];
    int tid = threadIdx.x;
    if (tid < HD) sattn[tid] = attn[tid];
    __syncthreads();
    if (tid < HD) {
        float s = 0.f;
        #pragma unroll 8
        for (int j = 0; j < HD; j++) s += Wnm[tid * HD + j] * sattn[j];
        g_wha[tid] = s;
    } else if (tid < HD + FD) {
        int i = tid - HD;
        float s = 0.f;
        #pragma unroll 8
        for (int j = 0; j < HD; j++) s += Wnm[(129 + i) * HD + j] * sattn[j];
        g_wfa[i] = s;
    } else if (tid == HD + FD) {
        float s = 0.f;
        for (int j = 0; j < HD; j++) s += Wnm[128 * HD + j] * sattn[j];
        g_aw = s;
    } else if (tid == HD + FD + 1) {
        float s = 0.f;
        for (int j = 0; j < HD; j++) s += bnm[j] * sattn[j];
        g_ab = s;
    }
}

// ---------------- K1a: mlp_self -> g_h, fz -> g_fz, a_f, deg=0 ----------------
#define DYN1 ((1024 + 8192 + 2048 + 64 + 128 + 16 + 512 + 2048) * 4)
__global__ void node_pre_kernel(const float* __restrict__ feat,
                                const float* __restrict__ W1, const float* __restrict__ b1,
                                const float* __restrict__ W2, const float* __restrict__ b2,
                                const float* __restrict__ Wnm) {
    extern __shared__ float sm1[];
    float* sW1  = sm1;
    float* sW2  = sW1 + 1024;
    float* sWf  = sW2 + 8192;
    float* sb1  = sWf + 2048;
    float* sb2  = sb1 + 64;
    float* swfa = sb2 + 128;
    float* sfeat = swfa + 16;
    float* shid  = sfeat + 512;

    const int tid = threadIdx.x;
    const int n0 = blockIdx.x * TILE;

    for (int i = tid; i < 1024; i += 256) sW1[i] = W1[i];
    for (int i = tid; i < 8192; i += 256) sW2[i] = W2[i];
    for (int i = tid; i < 2048; i += 256) sWf[i] = Wnm[(129 + (i >> 7)) * HD + (i & 127)];
    if (tid < 64)  sb1[tid] = b1[tid];
    if (tid < 128) sb2[tid] = b2[tid];
    if (tid < 16)  swfa[tid] = g_wfa[tid];
    for (int i = tid; i < TILE * FD; i += 256) sfeat[i] = feat[n0 * FD + i];
    __syncthreads();

    for (int i = tid; i < TILE * 64; i += 256) {
        int n = i >> 6, j = i & 63;
        float acc = sb1[j];
        #pragma unroll
        for (int k = 0; k < FD; k++) acc += sfeat[n * FD + k] * sW1[k * 64 + j];
        shid[i] = (acc >= 0.f) ? acc : 0.1f * acc;
    }
    __syncthreads();

    for (int i = tid; i < TILE * HD; i += 256) {
        int n = i >> 7, j = i & 127;
        int gn = n0 + n;
        float acc = sb2[j];
        #pragma unroll 16
        for (int k = 0; k < 64; k++) acc += shid[n * 64 + k] * sW2[k * HD + j];
        g_h[gn * HD + j] = acc;
        float fa = 0.f;
        #pragma unroll
        for (int k = 0; k < FD; k++) fa += sfeat[n * FD + k] * sWf[k * HD + j];
        g_fz[gn * HD + j] = fa;
    }
    if (tid < TILE) {
        int gn = n0 + tid;
        float af = 0.f;
        #pragma unroll
        for (int k = 0; k < FD; k++) af += sfeat[tid * FD + k] * swfa[k];
        g_af[gn] = af;
        g_deg[gn] = 0;
    }
}

// ---------------- K1b: hz = h @ W_nm[0:128], a_h = h . wha ----------------
#define DYN2 ((16384 + 4608 + 128) * 4)
__global__ void hz_kernel(const float* __restrict__ Wnm) {
    extern __shared__ float sm2[];
    float* sWh  = sm2;
    float* hT   = sm2 + 16384;   // [k][n] stride 36
    float* swha = hT + 4608;

    const int tid = threadIdx.x;
    const int n0 = blockIdx.x * TILE;

    for (int i = tid; i < 16384; i += 256) sWh[i] = Wnm[i];
    if (tid < HD) swha[tid] = g_wha[tid];
    for (int i = tid; i < TILE * HD; i += 256) {
        int n = i >> 7, k = i & 127;
        hT[k * 36 + n] = g_h[(n0 + n) * HD + k];
    }
    __syncthreads();

    const int rt = tid >> 5;
    const int ct = tid & 31;
    const int r0 = rt * 4, c0 = ct * 4;

    float a00=0,a01=0,a02=0,a03=0, a10=0,a11=0,a12=0,a13=0;
    float a20=0,a21=0,a22=0,a23=0, a30=0,a31=0,a32=0,a33=0;
    #pragma unroll 4
    for (int k = 0; k < HD; k++) {
        float4 a = *(const float4*)&hT[k * 36 + r0];
        float4 b = *(const float4*)&sWh[k * HD + c0];
        a00 += a.x*b.x; a01 += a.x*b.y; a02 += a.x*b.z; a03 += a.x*b.w;
        a10 += a.y*b.x; a11 += a.y*b.y; a12 += a.y*b.z; a13 += a.y*b.w;
        a20 += a.z*b.x; a21 += a.z*b.y; a22 += a.z*b.z; a23 += a.z*b.w;
        a30 += a.w*b.x; a31 += a.w*b.y; a32 += a.w*b.z; a33 += a.w*b.w;
    }
    *(float4*)&g_hz[(n0 + r0 + 0) * HD + c0] = make_float4(a00,a01,a02,a03);
    *(float4*)&g_hz[(n0 + r0 + 1) * HD + c0] = make_float4(a10,a11,a12,a13);
    *(float4*)&g_hz[(n0 + r0 + 2) * HD + c0] = make_float4(a20,a21,a22,a23);
    *(float4*)&g_hz[(n0 + r0 + 3) * HD + c0] = make_float4(a30,a31,a32,a33);

    if (tid < TILE) {
        float s = 0.f;
        #pragma unroll 8
        for (int k = 0; k < HD; k++) s += hT[k * 36 + tid] * swha[k];
        g_ah[n0 + tid] = s;
    }
}

// ---------------- K2: degree histogram ----------------
__global__ void hist_kernel(const int* __restrict__ dst) {
    int e = blockIdx.x * blockDim.x + threadIdx.x;
    if (e >= NE) return;
    atomicAdd(&g_deg[dst[e]], 1);
}

// ---------------- K3: block-level exclusive scan of g_deg ----------------
__global__ void scan1_kernel() {
    __shared__ int wsum[32];
    int tid = threadIdx.x, lane = tid & 31, wid = tid >> 5;
    int gid = blockIdx.x * SCAN_T + tid;
    int v = (gid < NN) ? g_deg[gid] : 0;
    int x = v;
    #pragma unroll
    for (int o = 1; o < 32; o <<= 1) {
        int y = __shfl_up_sync(0xffffffffu, x, o);
        if (lane >= o) x += y;
    }
    if (lane == 31) wsum[wid] = x;
    __syncthreads();
    if (wid == 0) {
        int w = wsum[lane];
        #pragma unroll
        for (int o = 1; o < 32; o <<= 1) {
            int y = __shfl_up_sync(0xffffffffu, w, o);
            if (lane >= o) w += y;
        }
        wsum[lane] = w;  // inclusive warp totals
    }
    __syncthreads();
    int wpre = (wid == 0) ? 0 : wsum[wid - 1];
    if (gid < NN) g_off[gid] = wpre + x - v;
    if (tid == SCAN_T - 1) g_bsum[blockIdx.x] = wpre + x;
}

__global__ void scan2_kernel() {
    __shared__ int ws[4];
    int tid = threadIdx.x, lane = tid & 31, wid = tid >> 5;
    int v = (tid < SCAN_NB) ? g_bsum[tid] : 0;
    int x = v;
    #pragma unroll
    for (int o = 1; o < 32; o <<= 1) {
        int y = __shfl_up_sync(0xffffffffu, x, o);
        if (lane >= o) x += y;
    }
    if (lane == 31) ws[wid] = x;
    __syncthreads();
    int wpre = 0;
    #pragma unroll
    for (int i = 0; i < 4; i++) if (i < wid) wpre += ws[i];
    if (tid < SCAN_NB) g_bpre[tid] = wpre + x - v;
}

__global__ void scan3_kernel() {
    int gid = blockIdx.x * SCAN_T + threadIdx.x;
    if (gid < NN) {
        int o = g_off[gid] + g_bpre[gid >> 10];
        g_off[gid] = o;
        g_cursor[gid] = o;
    }
}

// ---------------- K4: permute edges into CSR order (packed 16B records) ----------------
__global__ void scatter_kernel(const float* __restrict__ bit,
                               const int* __restrict__ src, const int* __restrict__ dst) {
    int e = blockIdx.x * blockDim.x + threadIdx.x;
    if (e >= NE) return;
    int s = src[e], d = dst[e];
    float b = bit[e];
    float ep = g_ah[s] + g_aw * b + g_ab;      // af[d] added later, lrelu later
    int pos = atomicAdd(&g_cursor[d], 1);
    g_edge[pos] = make_float4(ep, b, __int_as_float(s), 0.f);
}

// ---------------- K5: fused softmax + weighted gather + finalize + relu ----------------
// one warp per destination node; lanes own 4 channels each
__global__ void agg_kernel(const float* __restrict__ Wnm, const float* __restrict__ bnm) {
    int gw = (blockIdx.x * blockDim.x + threadIdx.x) >> 5;
    int lane = threadIdx.x & 31;
    if (gw >= NN) return;
    const int c4 = lane * 4;

    int deg = g_deg[gw];
    float* tp = &g_t[gw * HD + c4];
    if (deg == 0) {
        *(float4*)tp = make_float4(0.f, 0.f, 0.f, 0.f);
        return;
    }
    int start = g_off[gw];
    float afd = g_af[gw];

    // pass 1: segment max of lrelu_0.2 logits
    float m = -INFINITY;
    for (int i = lane; i < deg; i += 32) {
        float v = g_edge[start + i].x + afd;
        v = (v >= 0.f) ? v : 0.2f * v;
        m = fmaxf(m, v);
    }
    #pragma unroll
    for (int o = 16; o; o >>= 1) m = fmaxf(m, __shfl_xor_sync(0xffffffffu, m, o));

    // pass 2: sum of exp, and sum(exp * bit)
    float s = 0.f, sb = 0.f;
    for (int i = lane; i < deg; i += 32) {
        float4 ed = g_edge[start + i];
        float v = ed.x + afd;
        v = (v >= 0.f) ? v : 0.2f * v;
        float ee = __expf(v - m);
        s += ee;
        sb += ee * ed.y;
    }
    #pragma unroll
    for (int o = 16; o; o >>= 1) {
        s  += __shfl_xor_sync(0xffffffffu, s, o);
        sb += __shfl_xor_sync(0xffffffffu, sb, o);
    }
    float inv = 1.f / s;

    // pass 3: acc += alpha * hz[src]  (coalesced 512B row gather per edge)
    float ax = 0.f, ay = 0.f, az = 0.f, aw = 0.f;
    #pragma unroll 2
    for (int e = 0; e < deg; e++) {
        float4 ed = g_edge[start + e];
        float v = ed.x + afd;
        v = (v >= 0.f) ? v : 0.2f * v;
        float w = __expf(v - m) * inv;
        int sidx = __float_as_int(ed.z);
        float4 hv = *(const float4*)&g_hz[sidx * HD + c4];
        ax += w * hv.x; ay += w * hv.y; az += w * hv.z; aw += w * hv.w;
    }

    // finalize: neigh + (sum alpha*bit)*w_bit + fz + b_nm, then relu
    float sbm = sb * inv;
    float4 wb = *(const float4*)&Wnm[128 * HD + c4];
    float4 bn = *(const float4*)&bnm[c4];
    float4 fzv = *(const float4*)&g_fz[gw * HD + c4];
    float tx = ax + sbm * wb.x + fzv.x + bn.x;
    float ty = ay + sbm * wb.y + fzv.y + bn.y;
    float tz = az + sbm * wb.z + fzv.z + bn.z;
    float tw = aw + sbm * wb.w + fzv.w + bn.w;
    *(float4*)tp = make_float4(fmaxf(tx, 0.f), fmaxf(ty, 0.f),
                               fmaxf(tz, 0.f), fmaxf(tw, 0.f));
}

// ---------------- K6: mlp_out GEMM on g_t -> out ----------------
#define DYN3 ((16384 + 4608 + 128 + 128) * 4)
__global__ void out_kernel(const float* __restrict__ Wo1, const float* __restrict__ bo1,
                           const float* __restrict__ Wo2, const float* __restrict__ bo2,
                           float* __restrict__ out) {
    extern __shared__ float sm3[];
    float* sWo = sm3;
    float* tT  = sm3 + 16384;        // [k][n] stride 36
    float* sb1 = tT + 4608;
    float* sw2 = sb1 + 128;

    const int tid = threadIdx.x;
    const int n0 = blockIdx.x * TILE;

    for (int i = tid; i < 16384; i += 256) sWo[i] = Wo1[i];
    if (tid < 128) {
        sb1[tid] = bo1[tid];
        sw2[tid] = Wo2[tid];
    }
    for (int i = tid; i < TILE * HD; i += 256) {
        int n = i >> 7, k = i & 127;
        tT[k * 36 + n] = g_t[(n0 + n) * HD + k];
    }
    __syncthreads();

    const int rt = tid >> 5;
    const int ct = tid & 31;
    const int r0 = rt * 4, c0 = ct * 4;

    float a00=0,a01=0,a02=0,a03=0, a10=0,a11=0,a12=0,a13=0;
    float a20=0,a21=0,a22=0,a23=0, a30=0,a31=0,a32=0,a33=0;
    #pragma unroll 4
    for (int k = 0; k < HD; k++) {
        float4 a = *(const float4*)&tT[k * 36 + r0];
        float4 b = *(const float4*)&sWo[k * HD + c0];
        a00 += a.x*b.x; a01 += a.x*b.y; a02 += a.x*b.z; a03 += a.x*b.w;
        a10 += a.y*b.x; a11 += a.y*b.y; a12 += a.y*b.z; a13 += a.y*b.w;
        a20 += a.z*b.x; a21 += a.z*b.y; a22 += a.z*b.z; a23 += a.z*b.w;
        a30 += a.w*b.x; a31 += a.w*b.y; a32 += a.w*b.z; a33 += a.w*b.w;
    }

    float b2 = bo2[0];
    float p[4];
    {
        float u;
        float w0 = sw2[c0 + 0], w1 = sw2[c0 + 1], w2v = sw2[c0 + 2], w3 = sw2[c0 + 3];
        float c0b = sb1[c0 + 0], c1b = sb1[c0 + 1], c2b = sb1[c0 + 2], c3b = sb1[c0 + 3];
        #define LR(x) ((x) >= 0.f ? (x) : 0.1f * (x))
        u = a00 + c0b; p[0]  = LR(u) * w0;
        u = a01 + c1b; p[0] += LR(u) * w1;
        u = a02 + c2b; p[0] += LR(u) * w2v;
        u = a03 + c3b; p[0] += LR(u) * w3;
        u = a10 + c0b; p[1]  = LR(u) * w0;
        u = a11 + c1b; p[1] += LR(u) * w1;
        u = a12 + c2b; p[1] += LR(u) * w2v;
        u = a13 + c3b; p[1] += LR(u) * w3;
        u = a20 + c0b; p[2]  = LR(u) * w0;
        u = a21 + c1b; p[2] += LR(u) * w1;
        u = a22 + c2b; p[2] += LR(u) * w2v;
        u = a23 + c3b; p[2] += LR(u) * w3;
        u = a30 + c0b; p[3]  = LR(u) * w0;
        u = a31 + c1b; p[3] += LR(u) * w1;
        u = a32 + c2b; p[3] += LR(u) * w2v;
        u = a33 + c3b; p[3] += LR(u) * w3;
        #undef LR
    }
    #pragma unroll
    for (int r = 0; r < 4; r++) {
        float v = p[r];
        #pragma unroll
        for (int o = 16; o > 0; o >>= 1) v += __shfl_down_sync(0xffffffffu, v, o);
        if (ct == 0) out[n0 + r0 + r] = v + b2;
    }
}

// ---------------- launch ----------------
extern "C" void kernel_launch(void* const* d_in, const int* in_sizes, int n_in,
                              void* d_out, int out_size) {
    const float* feat = (const float*)d_in[0];
    const float* bit  = (const float*)d_in[1];
    const int*   src  = (const int*)d_in[2];
    const int*   dst  = (const int*)d_in[3];
    const float* W1   = (const float*)d_in[4];
    const float* b1   = (const float*)d_in[5];
    const float* W2   = (const float*)d_in[6];
    const float* b2   = (const float*)d_in[7];
    const float* Wnm  = (const float*)d_in[8];
    const float* bnm  = (const float*)d_in[9];
    const float* attn = (const float*)d_in[10];
    const float* Wo1  = (const float*)d_in[11];
    const float* bo1  = (const float*)d_in[12];
    const float* Wo2  = (const float*)d_in[13];
    const float* bo2  = (const float*)d_in[14];
    float* out = (float*)d_out;

    cudaFuncSetAttribute(node_pre_kernel, cudaFuncAttributeMaxDynamicSharedMemorySize, DYN1);
    cudaFuncSetAttribute(hz_kernel,       cudaFuncAttributeMaxDynamicSharedMemorySize, DYN2);
    cudaFuncSetAttribute(out_kernel,      cudaFuncAttributeMaxDynamicSharedMemorySize, DYN3);

    precompute_kernel<<<1, 160>>>(Wnm, bnm, attn);
    node_pre_kernel<<<NT, 256, DYN1>>>(feat, W1, b1, W2, b2, Wnm);
    hz_kernel<<<NT, 256, DYN2>>>(Wnm);
    hist_kernel<<<NE / 256, 256>>>(dst);
    scan1_kernel<<<SCAN_NB, SCAN_T>>>();
    scan2_kernel<<<1, 128>>>();
    scan3_kernel<<<SCAN_NB, SCAN_T>>>();
    scatter_kernel<<<NE / 256, 256>>>(bit, src, dst);
    agg_kernel<<<(NN + 7) / 8, 256>>>(Wnm, bnm);
    out_kernel<<<NT, 256, DYN3>>>(Wo1, bo1, Wo2, bo2, out);
}

// round 7
// speedup vs baseline: 2.4811x; 1.9071x over previous
#include <cuda_runtime.h>
#include <math.h>

#define NN 100000
#define NE 1600000
#define FD 16
#define HD 128
#define TILE 32
#define NT (NN / TILE)            // 3125 exact
#define NB64 1563                 // ceil(NN/64)
#define SCAN_T 1024
#define SCAN_NB ((NN + SCAN_T - 1) / SCAN_T)   // 98

// ---------------- scratch (static device globals; no allocation) ----------------
__device__ float g_hid[(NN + 64) * 64];    // lrelu(feat@W1+b1), padded rows
__device__ float g_hz[(NN + 64) * HD];
__device__ float g_fz[(NN + 64) * HD];
__device__ float g_t[(NN + 64) * HD];
__device__ float g_ah[NN];
__device__ float g_af[NN];
__device__ float g_wcomb[64 * HD];   // W2 @ Wh
__device__ float g_bcomb[HD];        // b2 @ Wh
__device__ float g_vah[64];          // W2 @ wha
__device__ float g_vahb;             // b2 . wha
__device__ float g_wha[HD];
__device__ float g_wfa[FD];
__device__ float g_aw;
__device__ float g_ab;
// CSR build
__device__ int   g_deg[NN];
__device__ int   g_off[NN];
__device__ int   g_cursor[NN];
__device__ int   g_bsum[SCAN_NB];
__device__ int   g_bpre[SCAN_NB];
// permuted edges: x = ah[src]+aw*bit+ab, y = bit, z = bits(src), w unused (+4 pad records)
__device__ float4 g_edge[NE + 4];

// ---------------- tf32 / mma helpers ----------------
__device__ __forceinline__ unsigned f2tf32(float x) {
    unsigned r;
    asm("cvt.rna.tf32.f32 %0, %1;" : "=r"(r) : "f"(x));
    return r;
}
__device__ __forceinline__ void mma_tf32(float c[4], const unsigned a[4], const unsigned b[2]) {
    asm("mma.sync.aligned.m16n8k8.row.col.f32.tf32.tf32.f32 "
        "{%0,%1,%2,%3},{%4,%5,%6,%7},{%8,%9},{%0,%1,%2,%3};"
        : "+f"(c[0]), "+f"(c[1]), "+f"(c[2]), "+f"(c[3])
        : "r"(a[0]), "r"(a[1]), "r"(a[2]), "r"(a[3]), "r"(b[0]), "r"(b[1]));
}

// ---------------- K0: fold attn into weights + derived vectors ----------------
__global__ void precompute_kernel(const float* __restrict__ Wnm,
                                  const float* __restrict__ bnm,
                                  const float* __restrict__ attn,
                                  const float* __restrict__ W2,
                                  const float* __restrict__ b2) {
    __shared__ float sattn[HD];
    __shared__ float swha[HD];
    int tid = threadIdx.x;
    if (tid < HD) sattn[tid] = attn[tid];
    __syncthreads();
    if (tid < HD) {
        float s = 0.f;
        #pragma unroll 8
        for (int j = 0; j < HD; j++) s += Wnm[tid * HD + j] * sattn[j];
        g_wha[tid] = s;
        swha[tid] = s;
    } else if (tid < HD + FD) {
        int i = tid - HD;
        float s = 0.f;
        #pragma unroll 8
        for (int j = 0; j < HD; j++) s += Wnm[(129 + i) * HD + j] * sattn[j];
        g_wfa[i] = s;
    } else if (tid == HD + FD) {
        float s = 0.f;
        for (int j = 0; j < HD; j++) s += Wnm[128 * HD + j] * sattn[j];
        g_aw = s;
    } else if (tid == HD + FD + 1) {
        float s = 0.f;
        for (int j = 0; j < HD; j++) s += bnm[j] * sattn[j];
        g_ab = s;
    } else if (tid < HD + FD + 6) {
        g_edge[NE + (tid - HD - FD - 2)] = make_float4(0.f, 0.f, 0.f, 0.f);
    }
    __syncthreads();
    if (tid < 64) {
        float s = 0.f;
        #pragma unroll 8
        for (int k = 0; k < HD; k++) s += W2[tid * HD + k] * swha[k];
        g_vah[tid] = s;
    } else if (tid == 64) {
        float s = 0.f;
        for (int k = 0; k < HD; k++) s += b2[k] * swha[k];
        g_vahb = s;
    }
    if (tid < HD) {
        float s = 0.f;
        #pragma unroll 8
        for (int k = 0; k < HD; k++) s += b2[k] * Wnm[k * HD + tid];
        g_bcomb[tid] = s;
    }
}

// ---------------- K0b: Wcomb = W2 @ Wh ----------------
__global__ void wcomb_kernel(const float* __restrict__ W2, const float* __restrict__ Wnm) {
    int r = blockIdx.x;          // 0..63
    int c = threadIdx.x;         // 0..127
    float s = 0.f;
    #pragma unroll 8
    for (int k = 0; k < HD; k++) s += W2[r * HD + k] * Wnm[k * HD + c];
    g_wcomb[r * HD + c] = s;
}

// ---------------- K1: hid = lrelu(feat@W1+b1), a_h, a_f, deg=0 ----------------
__global__ void node_pre_kernel(const float* __restrict__ feat,
                                const float* __restrict__ W1, const float* __restrict__ b1) {
    __shared__ float sW1[1024];
    __shared__ float sb1[64];
    __shared__ float sfeat[TILE * FD];
    __shared__ float sv[64];
    __shared__ float swfa[FD];
    __shared__ float sah[TILE];

    const int tid = threadIdx.x;
    const int n0 = blockIdx.x * TILE;
    const int lane = tid & 31;

    for (int i = tid; i < 1024; i += 256) sW1[i] = W1[i];
    if (tid < 64) { sb1[tid] = b1[tid]; sv[tid] = g_vah[tid]; }
    if (tid < FD) swfa[tid] = g_wfa[tid];
    for (int i = tid; i < TILE * FD; i += 256) sfeat[i] = feat[n0 * FD + i];
    if (tid < TILE) sah[tid] = 0.f;
    __syncthreads();

    #pragma unroll
    for (int p = 0; p < 8; p++) {
        int i = tid + p * 256;
        int n = i >> 6, j = i & 63;
        float acc = sb1[j];
        #pragma unroll
        for (int k = 0; k < FD; k++) acc += sfeat[n * FD + k] * sW1[k * 64 + j];
        acc = (acc >= 0.f) ? acc : 0.1f * acc;
        g_hid[(n0 + n) * 64 + j] = acc;
        float pa = acc * sv[j];
        #pragma unroll
        for (int o = 16; o; o >>= 1) pa += __shfl_xor_sync(0xffffffffu, pa, o);
        if (lane == 0) atomicAdd(&sah[n], pa);
    }
    __syncthreads();
    if (tid < TILE) {
        int gn = n0 + tid;
        g_ah[gn] = sah[tid] + g_vahb;
        float af = 0.f;
        #pragma unroll
        for (int k = 0; k < FD; k++) af += sfeat[tid * FD + k] * swfa[k];
        g_af[gn] = af;
        g_deg[gn] = 0;
    }
}

// ---------------- K2: tf32 GEMMs: hz = hid@Wcomb + bcomb ; fz = feat@Wf ----------------
// smem words: As1 64x68=4352 | As2 64x20=1280 | Ws1 64x136=8704 | Ws2 16x136=2176 | sbc 128
#define DYN_HZ ((4352 + 1280 + 8704 + 2176 + 128) * 4)
__global__ void hzfz_kernel(const float* __restrict__ feat, const float* __restrict__ Wnm) {
    extern __shared__ unsigned smu[];
    unsigned* As1 = smu;
    unsigned* As2 = As1 + 4352;
    unsigned* Ws1 = As2 + 1280;
    unsigned* Ws2 = Ws1 + 8704;
    float*    sbc = (float*)(Ws2 + 2176);

    const int tid = threadIdx.x;
    const int n0 = blockIdx.x * 64;

    for (int i = tid; i < 64 * 64; i += 256) {
        int r = i >> 6, k = i & 63;
        As1[r * 68 + k] = f2tf32(g_hid[(n0 + r) * 64 + k]);
    }
    for (int i = tid; i < 64 * 16; i += 256) {
        int r = i >> 4, k = i & 15;
        int gr = n0 + r;
        float v = (gr < NN) ? feat[gr * FD + k] : 0.f;
        As2[r * 20 + k] = f2tf32(v);
    }
    for (int i = tid; i < 64 * 128; i += 256) {
        int k = i >> 7, c = i & 127;
        Ws1[k * 136 + c] = f2tf32(g_wcomb[k * HD + c]);
    }
    for (int i = tid; i < 16 * 128; i += 256) {
        int k = i >> 7, c = i & 127;
        Ws2[k * 136 + c] = f2tf32(Wnm[(129 + k) * HD + c]);
    }
    if (tid < 128) sbc[tid] = g_bcomb[tid];
    __syncthreads();

    const int w = tid >> 5, lane = tid & 31;
    const int gy = lane >> 2, gx = lane & 3;
    const int mtb = (w >> 2) * 2;        // 2 M-tiles of 16
    const int ntb = (w & 3) * 4;         // 4 N-tiles of 8

    float c[2][4][4];
    unsigned a[2][4], b[4][2];

    // ---- hz ----
    #pragma unroll
    for (int t = 0; t < 2; t++)
        #pragma unroll
        for (int j = 0; j < 4; j++) {
            int col = (ntb + j) * 8 + 2 * gx;
            c[t][j][0] = sbc[col];  c[t][j][1] = sbc[col + 1];
            c[t][j][2] = sbc[col];  c[t][j][3] = sbc[col + 1];
        }
    #pragma unroll
    for (int ks = 0; ks < 8; ks++) {
        int k0 = ks * 8;
        #pragma unroll
        for (int t = 0; t < 2; t++) {
            int m0 = (mtb + t) * 16;
            a[t][0] = As1[(m0 + gy) * 68 + k0 + gx];
            a[t][1] = As1[(m0 + gy + 8) * 68 + k0 + gx];
            a[t][2] = As1[(m0 + gy) * 68 + k0 + gx + 4];
            a[t][3] = As1[(m0 + gy + 8) * 68 + k0 + gx + 4];
        }
        #pragma unroll
        for (int j = 0; j < 4; j++) {
            int nn0 = (ntb + j) * 8;
            b[j][0] = Ws1[(k0 + gx) * 136 + nn0 + gy];
            b[j][1] = Ws1[(k0 + gx + 4) * 136 + nn0 + gy];
        }
        #pragma unroll
        for (int t = 0; t < 2; t++)
            #pragma unroll
            for (int j = 0; j < 4; j++) mma_tf32(c[t][j], a[t], b[j]);
    }
    #pragma unroll
    for (int t = 0; t < 2; t++)
        #pragma unroll
        for (int j = 0; j < 4; j++) {
            int r = (mtb + t) * 16 + gy;
            int col = (ntb + j) * 8 + 2 * gx;
            *(float2*)&g_hz[(n0 + r) * HD + col]     = make_float2(c[t][j][0], c[t][j][1]);
            *(float2*)&g_hz[(n0 + r + 8) * HD + col] = make_float2(c[t][j][2], c[t][j][3]);
        }

    // ---- fz ----
    #pragma unroll
    for (int t = 0; t < 2; t++)
        #pragma unroll
        for (int j = 0; j < 4; j++) {
            c[t][j][0] = 0.f; c[t][j][1] = 0.f; c[t][j][2] = 0.f; c[t][j][3] = 0.f;
        }
    #pragma unroll
    for (int ks = 0; ks < 2; ks++) {
        int k0 = ks * 8;
        #pragma unroll
        for (int t = 0; t < 2; t++) {
            int m0 = (mtb + t) * 16;
            a[t][0] = As2[(m0 + gy) * 20 + k0 + gx];
            a[t][1] = As2[(m0 + gy + 8) * 20 + k0 + gx];
            a[t][2] = As2[(m0 + gy) * 20 + k0 + gx + 4];
            a[t][3] = As2[(m0 + gy + 8) * 20 + k0 + gx + 4];
        }
        #pragma unroll
        for (int j = 0; j < 4; j++) {
            int nn0 = (ntb + j) * 8;
            b[j][0] = Ws2[(k0 + gx) * 136 + nn0 + gy];
            b[j][1] = Ws2[(k0 + gx + 4) * 136 + nn0 + gy];
        }
        #pragma unroll
        for (int t = 0; t < 2; t++)
            #pragma unroll
            for (int j = 0; j < 4; j++) mma_tf32(c[t][j], a[t], b[j]);
    }
    #pragma unroll
    for (int t = 0; t < 2; t++)
        #pragma unroll
        for (int j = 0; j < 4; j++) {
            int r = (mtb + t) * 16 + gy;
            int col = (ntb + j) * 8 + 2 * gx;
            *(float2*)&g_fz[(n0 + r) * HD + col]     = make_float2(c[t][j][0], c[t][j][1]);
            *(float2*)&g_fz[(n0 + r + 8) * HD + col] = make_float2(c[t][j][2], c[t][j][3]);
        }
}

// ---------------- K3: degree histogram ----------------
__global__ void hist_kernel(const int* __restrict__ dst) {
    int e = blockIdx.x * blockDim.x + threadIdx.x;
    if (e >= NE) return;
    atomicAdd(&g_deg[dst[e]], 1);
}

// ---------------- K4: exclusive scan of g_deg ----------------
__global__ void scan1_kernel() {
    __shared__ int wsum[32];
    int tid = threadIdx.x, lane = tid & 31, wid = tid >> 5;
    int gid = blockIdx.x * SCAN_T + tid;
    int v = (gid < NN) ? g_deg[gid] : 0;
    int x = v;
    #pragma unroll
    for (int o = 1; o < 32; o <<= 1) {
        int y = __shfl_up_sync(0xffffffffu, x, o);
        if (lane >= o) x += y;
    }
    if (lane == 31) wsum[wid] = x;
    __syncthreads();
    if (wid == 0) {
        int w = wsum[lane];
        #pragma unroll
        for (int o = 1; o < 32; o <<= 1) {
            int y = __shfl_up_sync(0xffffffffu, w, o);
            if (lane >= o) w += y;
        }
        wsum[lane] = w;
    }
    __syncthreads();
    int wpre = (wid == 0) ? 0 : wsum[wid - 1];
    if (gid < NN) g_off[gid] = wpre + x - v;
    if (tid == SCAN_T - 1) g_bsum[blockIdx.x] = wpre + x;
}

__global__ void scan2_kernel() {
    __shared__ int ws[4];
    int tid = threadIdx.x, lane = tid & 31, wid = tid >> 5;
    int v = (tid < SCAN_NB) ? g_bsum[tid] : 0;
    int x = v;
    #pragma unroll
    for (int o = 1; o < 32; o <<= 1) {
        int y = __shfl_up_sync(0xffffffffu, x, o);
        if (lane >= o) x += y;
    }
    if (lane == 31) ws[wid] = x;
    __syncthreads();
    int wpre = 0;
    #pragma unroll
    for (int i = 0; i < 4; i++) if (i < wid) wpre += ws[i];
    if (tid < SCAN_NB) g_bpre[tid] = wpre + x - v;
}

__global__ void scan3_kernel() {
    int gid = blockIdx.x * SCAN_T + threadIdx.x;
    if (gid < NN) {
        int o = g_off[gid] + g_bpre[gid >> 10];
        g_off[gid] = o;
        g_cursor[gid] = o;
    }
}

// ---------------- K5: permute edges into CSR order ----------------
__global__ void scatter_kernel(const float* __restrict__ bit,
                               const int* __restrict__ src, const int* __restrict__ dst) {
    int e = blockIdx.x * blockDim.x + threadIdx.x;
    if (e >= NE) return;
    int s = src[e], d = dst[e];
    float b = bit[e];
    float ep = g_ah[s] + g_aw * b + g_ab;
    int pos = atomicAdd(&g_cursor[d], 1);
    g_edge[pos] = make_float4(ep, b, __int_as_float(s), 0.f);
}

// ---------------- K6: fused softmax + weighted gather + finalize + relu ----------------
__global__ void agg_kernel(const float* __restrict__ Wnm, const float* __restrict__ bnm) {
    int gw = (blockIdx.x * blockDim.x + threadIdx.x) >> 5;
    int lane = threadIdx.x & 31;
    if (gw >= NN) return;
    const int c4 = lane * 4;

    int deg = g_deg[gw];
    float* tp = &g_t[gw * HD + c4];
    if (deg == 0) {
        *(float4*)tp = make_float4(0.f, 0.f, 0.f, 0.f);
        return;
    }
    int start = g_off[gw];
    float afd = g_af[gw];
    const float4* eb = &g_edge[start];

    // pass 1: segment max of lrelu_0.2 logits
    float m = -INFINITY;
    for (int i = lane; i < deg; i += 32) {
        float v = eb[i].x + afd;
        v = (v >= 0.f) ? v : 0.2f * v;
        m = fmaxf(m, v);
    }
    #pragma unroll
    for (int o = 16; o; o >>= 1) m = fmaxf(m, __shfl_xor_sync(0xffffffffu, m, o));

    // pass 2: sum exp, sum(exp*bit)
    float s = 0.f, sb = 0.f;
    for (int i = lane; i < deg; i += 32) {
        float4 ed = eb[i];
        float v = ed.x + afd;
        v = (v >= 0.f) ? v : 0.2f * v;
        float ee = __expf(v - m);
        s += ee;
        sb += ee * ed.y;
    }
    #pragma unroll
    for (int o = 16; o; o >>= 1) {
        s  += __shfl_xor_sync(0xffffffffu, s, o);
        sb += __shfl_xor_sync(0xffffffffu, sb, o);
    }
    float inv = 1.f / s;

    // pass 3: acc += alpha * hz[src], chunk-of-4 pipelined
    float ax = 0.f, ay = 0.f, az = 0.f, aww = 0.f;
    for (int base = 0; base < deg; base += 4) {
        float4 E0 = eb[base];
        float4 E1 = eb[base + 1];
        float4 E2 = eb[base + 2];
        float4 E3 = eb[base + 3];
        float4 H0 = *(const float4*)&g_hz[__float_as_int(E0.z) * HD + c4];
        float4 H1 = *(const float4*)&g_hz[__float_as_int(E1.z) * HD + c4];
        float4 H2 = *(const float4*)&g_hz[__float_as_int(E2.z) * HD + c4];
        float4 H3 = *(const float4*)&g_hz[__float_as_int(E3.z) * HD + c4];
        float v0 = E0.x + afd; v0 = (v0 >= 0.f) ? v0 : 0.2f * v0;
        float v1 = E1.x + afd; v1 = (v1 >= 0.f) ? v1 : 0.2f * v1;
        float v2 = E2.x + afd; v2 = (v2 >= 0.f) ? v2 : 0.2f * v2;
        float v3 = E3.x + afd; v3 = (v3 >= 0.f) ? v3 : 0.2f * v3;
        float w0 = __expf(v0 - m) * inv;
        float w1 = (base + 1 < deg) ? __expf(v1 - m) * inv : 0.f;
        float w2 = (base + 2 < deg) ? __expf(v2 - m) * inv : 0.f;
        float w3 = (base + 3 < deg) ? __expf(v3 - m) * inv : 0.f;
        ax += w0 * H0.x + w1 * H1.x + w2 * H2.x + w3 * H3.x;
        ay += w0 * H0.y + w1 * H1.y + w2 * H2.y + w3 * H3.y;
        az += w0 * H0.z + w1 * H1.z + w2 * H2.z + w3 * H3.z;
        aww += w0 * H0.w + w1 * H1.w + w2 * H2.w + w3 * H3.w;
    }

    float sbm = sb * inv;
    float4 wb = *(const float4*)&Wnm[128 * HD + c4];
    float4 bn = *(const float4*)&bnm[c4];
    float4 fzv = *(const float4*)&g_fz[gw * HD + c4];
    float tx = ax + sbm * wb.x + fzv.x + bn.x;
    float ty = ay + sbm * wb.y + fzv.y + bn.y;
    float tz = az + sbm * wb.z + fzv.z + bn.z;
    float tw = aww + sbm * wb.w + fzv.w + bn.w;
    *(float4*)tp = make_float4(fmaxf(tx, 0.f), fmaxf(ty, 0.f),
                               fmaxf(tz, 0.f), fmaxf(tw, 0.f));
}

// ---------------- K7: tf32 mlp_out on g_t -> out ----------------
// smem words: sA 64x132=8448 | W 128x136=17408 | sb1o 128 | sw2o 128
#define DYN_OUT ((8448 + 17408 + 128 + 128) * 4)
__global__ void out_kernel(const float* __restrict__ Wo1, const float* __restrict__ bo1,
                           const float* __restrict__ Wo2, const float* __restrict__ bo2,
                           float* __restrict__ out) {
    extern __shared__ unsigned smo[];
    unsigned* sA   = smo;              // tf32 A; later reused as fp32 U
    unsigned* sW   = sA + 8448;
    float*    sb1o = (float*)(sW + 17408);
    float*    sw2o = sb1o + 128;

    const int tid = threadIdx.x;
    const int n0 = blockIdx.x * 64;

    for (int i = tid; i < 64 * 128; i += 256) {
        int r = i >> 7, c = i & 127;
        sA[r * 132 + c] = f2tf32(g_t[(n0 + r) * HD + c]);
    }
    for (int i = tid; i < 128 * 128; i += 256) {
        int k = i >> 7, c = i & 127;
        sW[k * 136 + c] = f2tf32(Wo1[k * HD + c]);
    }
    if (tid < 128) { sb1o[tid] = bo1[tid]; sw2o[tid] = Wo2[tid]; }
    __syncthreads();

    const int w = tid >> 5, lane = tid & 31;
    const int gy = lane >> 2, gx = lane & 3;
    const int mtb = (w >> 2) * 2;
    const int ntb = (w & 3) * 4;

    float c[2][4][4];
    unsigned a[2][4], b[4][2];
    #pragma unroll
    for (int t = 0; t < 2; t++)
        #pragma unroll
        for (int j = 0; j < 4; j++) {
            int col = (ntb + j) * 8 + 2 * gx;
            c[t][j][0] = sb1o[col];  c[t][j][1] = sb1o[col + 1];
            c[t][j][2] = sb1o[col];  c[t][j][3] = sb1o[col + 1];
        }
    #pragma unroll
    for (int ks = 0; ks < 16; ks++) {
        int k0 = ks * 8;
        #pragma unroll
        for (int t = 0; t < 2; t++) {
            int m0 = (mtb + t) * 16;
            a[t][0] = sA[(m0 + gy) * 132 + k0 + gx];
            a[t][1] = sA[(m0 + gy + 8) * 132 + k0 + gx];
            a[t][2] = sA[(m0 + gy) * 132 + k0 + gx + 4];
            a[t][3] = sA[(m0 + gy + 8) * 132 + k0 + gx + 4];
        }
        #pragma unroll
        for (int j = 0; j < 4; j++) {
            int nn0 = (ntb + j) * 8;
            b[j][0] = sW[(k0 + gx) * 136 + nn0 + gy];
            b[j][1] = sW[(k0 + gx + 4) * 136 + nn0 + gy];
        }
        #pragma unroll
        for (int t = 0; t < 2; t++)
            #pragma unroll
            for (int j = 0; j < 4; j++) mma_tf32(c[t][j], a[t], b[j]);
    }
    __syncthreads();   // all mma reads of sA done; reuse as fp32 U

    float* U = (float*)sA;
    #define LR(x) ((x) >= 0.f ? (x) : 0.1f * (x))
    #pragma unroll
    for (int t = 0; t < 2; t++)
        #pragma unroll
        for (int j = 0; j < 4; j++) {
            int r = (mtb + t) * 16 + gy;
            int col = (ntb + j) * 8 + 2 * gx;
            *(float2*)&U[r * 132 + col]       = make_float2(LR(c[t][j][0]), LR(c[t][j][1]));
            *(float2*)&U[(r + 8) * 132 + col] = make_float2(LR(c[t][j][2]), LR(c[t][j][3]));
        }
    #undef LR
    __syncthreads();

    float b2v = bo2[0];
    #pragma unroll
    for (int rr = 0; rr < 8; rr++) {
        int r = w * 8 + rr;
        float p = U[r * 132 + lane]       * sw2o[lane]
                + U[r * 132 + lane + 32]  * sw2o[lane + 32]
                + U[r * 132 + lane + 64]  * sw2o[lane + 64]
                + U[r * 132 + lane + 96]  * sw2o[lane + 96];
        #pragma unroll
        for (int o = 16; o; o >>= 1) p += __shfl_xor_sync(0xffffffffu, p, o);
        int gr = n0 + r;
        if (lane == 0 && gr < NN) out[gr] = p + b2v;
    }
}

// ---------------- launch ----------------
extern "C" void kernel_launch(void* const* d_in, const int* in_sizes, int n_in,
                              void* d_out, int out_size) {
    const float* feat = (const float*)d_in[0];
    const float* bit  = (const float*)d_in[1];
    const int*   src  = (const int*)d_in[2];
    const int*   dst  = (const int*)d_in[3];
    const float* W1   = (const float*)d_in[4];
    const float* b1   = (const float*)d_in[5];
    const float* W2   = (const float*)d_in[6];
    const float* b2   = (const float*)d_in[7];
    const float* Wnm  = (const float*)d_in[8];
    const float* bnm  = (const float*)d_in[9];
    const float* attn = (const float*)d_in[10];
    const float* Wo1  = (const float*)d_in[11];
    const float* bo1  = (const float*)d_in[12];
    const float* Wo2  = (const float*)d_in[13];
    const float* bo2  = (const float*)d_in[14];
    float* out = (float*)d_out;

    cudaFuncSetAttribute(hzfz_kernel, cudaFuncAttributeMaxDynamicSharedMemorySize, DYN_HZ);
    cudaFuncSetAttribute(out_kernel,  cudaFuncAttributeMaxDynamicSharedMemorySize, DYN_OUT);

    precompute_kernel<<<1, 256>>>(Wnm, bnm, attn, W2, b2);
    wcomb_kernel<<<64, 128>>>(W2, Wnm);
    node_pre_kernel<<<NT, 256>>>(feat, W1, b1);
    hzfz_kernel<<<NB64, 256, DYN_HZ>>>(feat, Wnm);
    hist_kernel<<<NE / 256, 256>>>(dst);
    scan1_kernel<<<SCAN_NB, SCAN_T>>>();
    scan2_kernel<<<1, 128>>>();
    scan3_kernel<<<SCAN_NB, SCAN_T>>>();
    scatter_kernel<<<NE / 256, 256>>>(bit, src, dst);
    agg_kernel<<<(NN + 7) / 8, 256>>>(Wnm, bnm);
    out_kernel<<<NB64, 256, DYN_OUT>>>(Wo1, bo1, Wo2, bo2, out);
}

// round 8
// speedup vs baseline: 2.8505x; 1.1489x over previous
#include <cuda_runtime.h>
#include <math.h>

#define NN 100000
#define NE 1600000
#define FD 16
#define HD 128
#define NB64 1563                 // ceil(NN/64)
#define SCAN_T 1024
#define SCAN_NB ((NN + SCAN_T - 1) / SCAN_T)   // 98

// ---------------- scratch (static device globals; no allocation) ----------------
__device__ float g_hz[(NN + 64) * HD];
__device__ float g_fz[(NN + 64) * HD];
__device__ float g_t[(NN + 64) * HD];
__device__ float g_ah[NN];
__device__ float g_af[NN];
__device__ unsigned g_wcomb_tf[64 * HD];   // tf32(W2 @ Wh)
__device__ unsigned g_wf_tf[FD * HD];      // tf32(Wnm feat rows)
__device__ unsigned g_wo1_tf[HD * HD];     // tf32(Wo1)
__device__ float g_bcomb[HD];              // b2 @ Wh
__device__ float g_vah[64];                // W2 @ wha
__device__ float g_vahb;                   // b2 . wha
__device__ float g_wfa[FD];
__device__ float g_aw;
__device__ float g_ab;
// CSR build
__device__ int   g_deg[NN];
__device__ int   g_off[NN];
__device__ int   g_cursor[NN];
__device__ int   g_bsum[SCAN_NB];
__device__ int   g_bpre[SCAN_NB];
// permuted edges: x = ah[src]+aw*bit+ab, y = bit, z = bits(src), w unused (+4 pad records)
__device__ float4 g_edge[NE + 4];

// ---------------- tf32 / mma helpers ----------------
__device__ __forceinline__ unsigned f2tf32(float x) {
    unsigned r;
    asm("cvt.rna.tf32.f32 %0, %1;" : "=r"(r) : "f"(x));
    return r;
}
__device__ __forceinline__ void mma_tf32(float c[4], const unsigned a[4], const unsigned b[2]) {
    asm("mma.sync.aligned.m16n8k8.row.col.f32.tf32.tf32.f32 "
        "{%0,%1,%2,%3},{%4,%5,%6,%7},{%8,%9},{%0,%1,%2,%3};"
        : "+f"(c[0]), "+f"(c[1]), "+f"(c[2]), "+f"(c[3])
        : "r"(a[0]), "r"(a[1]), "r"(a[2]), "r"(a[3]), "r"(b[0]), "r"(b[1]));
}

// ---------------- K0: fold attn into weights + derived vectors + tf32 feat-W ----------------
__global__ void precompute_kernel(const float* __restrict__ Wnm,
                                  const float* __restrict__ bnm,
                                  const float* __restrict__ attn,
                                  const float* __restrict__ W2,
                                  const float* __restrict__ b2) {
    __shared__ float sattn[HD];
    __shared__ float swha[HD];
    int tid = threadIdx.x;
    if (tid < HD) sattn[tid] = attn[tid];
    __syncthreads();
    if (tid < HD) {
        float s = 0.f;
        #pragma unroll 8
        for (int j = 0; j < HD; j++) s += Wnm[tid * HD + j] * sattn[j];
        swha[tid] = s;
    } else if (tid < HD + FD) {
        int i = tid - HD;
        float s = 0.f;
        #pragma unroll 8
        for (int j = 0; j < HD; j++) s += Wnm[(129 + i) * HD + j] * sattn[j];
        g_wfa[i] = s;
    } else if (tid == HD + FD) {
        float s = 0.f;
        for (int j = 0; j < HD; j++) s += Wnm[128 * HD + j] * sattn[j];
        g_aw = s;
    } else if (tid == HD + FD + 1) {
        float s = 0.f;
        for (int j = 0; j < HD; j++) s += bnm[j] * sattn[j];
        g_ab = s;
    } else if (tid < HD + FD + 6) {
        g_edge[NE + (tid - HD - FD - 2)] = make_float4(0.f, 0.f, 0.f, 0.f);
    }
    __syncthreads();
    if (tid < 64) {
        float s = 0.f;
        #pragma unroll 8
        for (int k = 0; k < HD; k++) s += W2[tid * HD + k] * swha[k];
        g_vah[tid] = s;
    } else if (tid == 64) {
        float s = 0.f;
        for (int k = 0; k < HD; k++) s += b2[k] * swha[k];
        g_vahb = s;
    }
    if (tid < HD) {
        float s = 0.f;
        #pragma unroll 8
        for (int k = 0; k < HD; k++) s += b2[k] * Wnm[k * HD + tid];
        g_bcomb[tid] = s;
    }
    // tf32 copy of feat rows of Wnm (rows 129..144)
    for (int i = tid; i < FD * HD; i += 256)
        g_wf_tf[i] = f2tf32(Wnm[(129 + (i >> 7)) * HD + (i & 127)]);
}

// ---------------- K0b: Wcomb = tf32(W2 @ Wh) ----------------
__global__ void wcomb_kernel(const float* __restrict__ W2, const float* __restrict__ Wnm) {
    int r = blockIdx.x;          // 0..63
    int c = threadIdx.x;         // 0..127
    float s = 0.f;
    #pragma unroll 8
    for (int k = 0; k < HD; k++) s += W2[r * HD + k] * Wnm[k * HD + c];
    g_wcomb_tf[r * HD + c] = f2tf32(s);
}

// ---------------- K0c: tf32 copy of Wo1 ----------------
__global__ void wo1tf_kernel(const float* __restrict__ Wo1) {
    int i = blockIdx.x * 256 + threadIdx.x;
    g_wo1_tf[i] = f2tf32(Wo1[i]);
}

// ---------------- K1: fused node kernel ----------------
// hid = lrelu(feat@W1+b1) in smem -> hz = hid@Wcomb + bcomb (tf32 mma, B from gmem)
// fz = feat@Wf (tf32 mma), a_h, a_f, deg=0
__global__ void __launch_bounds__(256) node_kernel(const float* __restrict__ feat,
                            const float* __restrict__ W1, const float* __restrict__ b1) {
    __shared__ float sW1[1024];
    __shared__ float sb1[64];
    __shared__ float sv[64];
    __shared__ float swfa[FD];
    __shared__ float sbc[HD];
    __shared__ float sfeat[64 * FD];
    __shared__ float sah[64];
    __shared__ unsigned As1[64 * 68];   // tf32 hid
    __shared__ unsigned As2[64 * 20];   // tf32 feat

    const int tid = threadIdx.x;
    const int n0 = blockIdx.x * 64;
    const int lane = tid & 31;

    for (int i = tid; i < 1024; i += 256) sW1[i] = W1[i];
    if (tid < 64) { sb1[tid] = b1[tid]; sv[tid] = g_vah[tid]; sah[tid] = 0.f; }
    if (tid < FD) swfa[tid] = g_wfa[tid];
    if (tid < HD) sbc[tid] = g_bcomb[tid];
    for (int i = tid; i < 64 * FD; i += 256) {
        int gr = n0 + (i >> 4);
        float v = (gr < NN) ? feat[gr * FD + (i & 15)] : 0.f;
        sfeat[i] = v;
        As2[(i >> 4) * 20 + (i & 15)] = f2tf32(v);
    }
    __syncthreads();

    // hid: 64 rows x 64 cols; also ah partial dot
    #pragma unroll
    for (int p = 0; p < 16; p++) {
        int i = tid + p * 256;
        int n = i >> 6, j = i & 63;
        float acc = sb1[j];
        #pragma unroll
        for (int k = 0; k < FD; k++) acc += sfeat[n * FD + k] * sW1[k * 64 + j];
        acc = (acc >= 0.f) ? acc : 0.1f * acc;
        As1[n * 68 + j] = f2tf32(acc);
        float pa = acc * sv[j];
        #pragma unroll
        for (int o = 16; o; o >>= 1) pa += __shfl_xor_sync(0xffffffffu, pa, o);
        if (lane == 0) atomicAdd(&sah[n], pa);
    }
    __syncthreads();

    if (tid < 64) {
        int gn = n0 + tid;
        if (gn < NN) {
            g_ah[gn] = sah[tid] + g_vahb;
            float af = 0.f;
            #pragma unroll
            for (int k = 0; k < FD; k++) af += sfeat[tid * FD + k] * swfa[k];
            g_af[gn] = af;
            g_deg[gn] = 0;
        }
    }

    const int w = tid >> 5;
    const int gy = lane >> 2, gx = lane & 3;
    const int mtb = (w >> 2) * 2;        // 2 M-tiles of 16
    const int ntb = (w & 3) * 4;         // 4 N-tiles of 8

    float c[2][4][4];
    unsigned a[2][4], b[4][2];

    // ---- hz = hid @ Wcomb + bcomb ----
    #pragma unroll
    for (int t = 0; t < 2; t++)
        #pragma unroll
        for (int j = 0; j < 4; j++) {
            int col = (ntb + j) * 8 + 2 * gx;
            c[t][j][0] = sbc[col];  c[t][j][1] = sbc[col + 1];
            c[t][j][2] = sbc[col];  c[t][j][3] = sbc[col + 1];
        }
    #pragma unroll
    for (int ks = 0; ks < 8; ks++) {
        int k0 = ks * 8;
        #pragma unroll
        for (int t = 0; t < 2; t++) {
            int m0 = (mtb + t) * 16;
            a[t][0] = As1[(m0 + gy) * 68 + k0 + gx];
            a[t][1] = As1[(m0 + gy + 8) * 68 + k0 + gx];
            a[t][2] = As1[(m0 + gy) * 68 + k0 + gx + 4];
            a[t][3] = As1[(m0 + gy + 8) * 68 + k0 + gx + 4];
        }
        #pragma unroll
        for (int j = 0; j < 4; j++) {
            int nn0 = (ntb + j) * 8;
            b[j][0] = __ldg(&g_wcomb_tf[(k0 + gx) * HD + nn0 + gy]);
            b[j][1] = __ldg(&g_wcomb_tf[(k0 + gx + 4) * HD + nn0 + gy]);
        }
        #pragma unroll
        for (int t = 0; t < 2; t++)
            #pragma unroll
            for (int j = 0; j < 4; j++) mma_tf32(c[t][j], a[t], b[j]);
    }
    #pragma unroll
    for (int t = 0; t < 2; t++)
        #pragma unroll
        for (int j = 0; j < 4; j++) {
            int r = (mtb + t) * 16 + gy;
            int col = (ntb + j) * 8 + 2 * gx;
            *(float2*)&g_hz[(n0 + r) * HD + col]     = make_float2(c[t][j][0], c[t][j][1]);
            *(float2*)&g_hz[(n0 + r + 8) * HD + col] = make_float2(c[t][j][2], c[t][j][3]);
        }

    // ---- fz = feat @ Wf ----
    #pragma unroll
    for (int t = 0; t < 2; t++)
        #pragma unroll
        for (int j = 0; j < 4; j++) {
            c[t][j][0] = 0.f; c[t][j][1] = 0.f; c[t][j][2] = 0.f; c[t][j][3] = 0.f;
        }
    #pragma unroll
    for (int ks = 0; ks < 2; ks++) {
        int k0 = ks * 8;
        #pragma unroll
        for (int t = 0; t < 2; t++) {
            int m0 = (mtb + t) * 16;
            a[t][0] = As2[(m0 + gy) * 20 + k0 + gx];
            a[t][1] = As2[(m0 + gy + 8) * 20 + k0 + gx];
            a[t][2] = As2[(m0 + gy) * 20 + k0 + gx + 4];
            a[t][3] = As2[(m0 + gy + 8) * 20 + k0 + gx + 4];
        }
        #pragma unroll
        for (int j = 0; j < 4; j++) {
            int nn0 = (ntb + j) * 8;
            b[j][0] = __ldg(&g_wf_tf[(k0 + gx) * HD + nn0 + gy]);
            b[j][1] = __ldg(&g_wf_tf[(k0 + gx + 4) * HD + nn0 + gy]);
        }
        #pragma unroll
        for (int t = 0; t < 2; t++)
            #pragma unroll
            for (int j = 0; j < 4; j++) mma_tf32(c[t][j], a[t], b[j]);
    }
    #pragma unroll
    for (int t = 0; t < 2; t++)
        #pragma unroll
        for (int j = 0; j < 4; j++) {
            int r = (mtb + t) * 16 + gy;
            int col = (ntb + j) * 8 + 2 * gx;
            *(float2*)&g_fz[(n0 + r) * HD + col]     = make_float2(c[t][j][0], c[t][j][1]);
            *(float2*)&g_fz[(n0 + r + 8) * HD + col] = make_float2(c[t][j][2], c[t][j][3]);
        }
}

// ---------------- K3: degree histogram ----------------
__global__ void hist_kernel(const int* __restrict__ dst) {
    int e = blockIdx.x * blockDim.x + threadIdx.x;
    if (e >= NE) return;
    atomicAdd(&g_deg[dst[e]], 1);
}

// ---------------- K4: exclusive scan of g_deg ----------------
__global__ void scan1_kernel() {
    __shared__ int wsum[32];
    int tid = threadIdx.x, lane = tid & 31, wid = tid >> 5;
    int gid = blockIdx.x * SCAN_T + tid;
    int v = (gid < NN) ? g_deg[gid] : 0;
    int x = v;
    #pragma unroll
    for (int o = 1; o < 32; o <<= 1) {
        int y = __shfl_up_sync(0xffffffffu, x, o);
        if (lane >= o) x += y;
    }
    if (lane == 31) wsum[wid] = x;
    __syncthreads();
    if (wid == 0) {
        int w = wsum[lane];
        #pragma unroll
        for (int o = 1; o < 32; o <<= 1) {
            int y = __shfl_up_sync(0xffffffffu, w, o);
            if (lane >= o) w += y;
        }
        wsum[lane] = w;
    }
    __syncthreads();
    int wpre = (wid == 0) ? 0 : wsum[wid - 1];
    if (gid < NN) g_off[gid] = wpre + x - v;
    if (tid == SCAN_T - 1) g_bsum[blockIdx.x] = wpre + x;
}

__global__ void scan2_kernel() {
    __shared__ int ws[4];
    int tid = threadIdx.x, lane = tid & 31, wid = tid >> 5;
    int v = (tid < SCAN_NB) ? g_bsum[tid] : 0;
    int x = v;
    #pragma unroll
    for (int o = 1; o < 32; o <<= 1) {
        int y = __shfl_up_sync(0xffffffffu, x, o);
        if (lane >= o) x += y;
    }
    if (lane == 31) ws[wid] = x;
    __syncthreads();
    int wpre = 0;
    #pragma unroll
    for (int i = 0; i < 4; i++) if (i < wid) wpre += ws[i];
    if (tid < SCAN_NB) g_bpre[tid] = wpre + x - v;
}

__global__ void scan3_kernel() {
    int gid = blockIdx.x * SCAN_T + threadIdx.x;
    if (gid < NN) {
        int o = g_off[gid] + g_bpre[gid >> 10];
        g_off[gid] = o;
        g_cursor[gid] = o;
    }
}

// ---------------- K5: permute edges into CSR order ----------------
__global__ void scatter_kernel(const float* __restrict__ bit,
                               const int* __restrict__ src, const int* __restrict__ dst) {
    int e = blockIdx.x * blockDim.x + threadIdx.x;
    if (e >= NE) return;
    int s = src[e], d = dst[e];
    float b = bit[e];
    float ep = g_ah[s] + g_aw * b + g_ab;
    int pos = atomicAdd(&g_cursor[d], 1);
    g_edge[pos] = make_float4(ep, b, __int_as_float(s), 0.f);
}

// ---------------- K6: fused softmax + weighted gather + finalize + relu ----------------
__global__ void agg_kernel(const float* __restrict__ Wnm, const float* __restrict__ bnm) {
    int gw = (blockIdx.x * blockDim.x + threadIdx.x) >> 5;
    int lane = threadIdx.x & 31;
    if (gw >= NN) return;
    const int c4 = lane * 4;

    int deg = g_deg[gw];
    float* tp = &g_t[gw * HD + c4];
    if (deg == 0) {
        *(float4*)tp = make_float4(0.f, 0.f, 0.f, 0.f);
        return;
    }
    int start = g_off[gw];
    float afd = g_af[gw];
    const float4* eb = &g_edge[start];

    // pass 1: segment max of lrelu_0.2 logits
    float m = -INFINITY;
    for (int i = lane; i < deg; i += 32) {
        float v = eb[i].x + afd;
        v = (v >= 0.f) ? v : 0.2f * v;
        m = fmaxf(m, v);
    }
    #pragma unroll
    for (int o = 16; o; o >>= 1) m = fmaxf(m, __shfl_xor_sync(0xffffffffu, m, o));

    // pass 2: sum exp, sum(exp*bit)
    float s = 0.f, sb = 0.f;
    for (int i = lane; i < deg; i += 32) {
        float4 ed = eb[i];
        float v = ed.x + afd;
        v = (v >= 0.f) ? v : 0.2f * v;
        float ee = __expf(v - m);
        s += ee;
        sb += ee * ed.y;
    }
    #pragma unroll
    for (int o = 16; o; o >>= 1) {
        s  += __shfl_xor_sync(0xffffffffu, s, o);
        sb += __shfl_xor_sync(0xffffffffu, sb, o);
    }
    float inv = 1.f / s;

    // pass 3: acc += alpha * hz[src], chunk-of-4 pipelined
    float ax = 0.f, ay = 0.f, az = 0.f, aww = 0.f;
    for (int base = 0; base < deg; base += 4) {
        float4 E0 = eb[base];
        float4 E1 = eb[base + 1];
        float4 E2 = eb[base + 2];
        float4 E3 = eb[base + 3];
        float4 H0 = *(const float4*)&g_hz[__float_as_int(E0.z) * HD + c4];
        float4 H1 = *(const float4*)&g_hz[__float_as_int(E1.z) * HD + c4];
        float4 H2 = *(const float4*)&g_hz[__float_as_int(E2.z) * HD + c4];
        float4 H3 = *(const float4*)&g_hz[__float_as_int(E3.z) * HD + c4];
        float v0 = E0.x + afd; v0 = (v0 >= 0.f) ? v0 : 0.2f * v0;
        float v1 = E1.x + afd; v1 = (v1 >= 0.f) ? v1 : 0.2f * v1;
        float v2 = E2.x + afd; v2 = (v2 >= 0.f) ? v2 : 0.2f * v2;
        float v3 = E3.x + afd; v3 = (v3 >= 0.f) ? v3 : 0.2f * v3;
        float w0 = __expf(v0 - m) * inv;
        float w1 = (base + 1 < deg) ? __expf(v1 - m) * inv : 0.f;
        float w2 = (base + 2 < deg) ? __expf(v2 - m) * inv : 0.f;
        float w3 = (base + 3 < deg) ? __expf(v3 - m) * inv : 0.f;
        ax += w0 * H0.x + w1 * H1.x + w2 * H2.x + w3 * H3.x;
        ay += w0 * H0.y + w1 * H1.y + w2 * H2.y + w3 * H3.y;
        az += w0 * H0.z + w1 * H1.z + w2 * H2.z + w3 * H3.z;
        aww += w0 * H0.w + w1 * H1.w + w2 * H2.w + w3 * H3.w;
    }

    float sbm = sb * inv;
    float4 wb = *(const float4*)&Wnm[128 * HD + c4];
    float4 bn = *(const float4*)&bnm[c4];
    float4 fzv = *(const float4*)&g_fz[gw * HD + c4];
    float tx = ax + sbm * wb.x + fzv.x + bn.x;
    float ty = ay + sbm * wb.y + fzv.y + bn.y;
    float tz = az + sbm * wb.z + fzv.z + bn.z;
    float tw = aww + sbm * wb.w + fzv.w + bn.w;
    *(float4*)tp = make_float4(fmaxf(tx, 0.f), fmaxf(ty, 0.f),
                               fmaxf(tz, 0.f), fmaxf(tw, 0.f));
}

// ---------------- K7: tf32 mlp_out on g_t -> out (B from global tf32) ----------------
__global__ void __launch_bounds__(256) out_kernel(const float* __restrict__ bo1,
                           const float* __restrict__ Wo2, const float* __restrict__ bo2,
                           float* __restrict__ out) {
    __shared__ unsigned sA[64 * 132];   // tf32 A; reused as fp32 U
    __shared__ float sb1o[128];
    __shared__ float sw2o[128];

    const int tid = threadIdx.x;
    const int n0 = blockIdx.x * 64;

    for (int i = tid; i < 64 * 128; i += 256) {
        int r = i >> 7, c = i & 127;
        sA[r * 132 + c] = f2tf32(g_t[(n0 + r) * HD + c]);
    }
    if (tid < 128) { sb1o[tid] = bo1[tid]; sw2o[tid] = Wo2[tid]; }
    __syncthreads();

    const int w = tid >> 5, lane = tid & 31;
    const int gy = lane >> 2, gx = lane & 3;
    const int mtb = (w >> 2) * 2;
    const int ntb = (w & 3) * 4;

    float c[2][4][4];
    unsigned a[2][4], b[4][2];
    #pragma unroll
    for (int t = 0; t < 2; t++)
        #pragma unroll
        for (int j = 0; j < 4; j++) {
            int col = (ntb + j) * 8 + 2 * gx;
            c[t][j][0] = sb1o[col];  c[t][j][1] = sb1o[col + 1];
            c[t][j][2] = sb1o[col];  c[t][j][3] = sb1o[col + 1];
        }
    #pragma unroll
    for (int ks = 0; ks < 16; ks++) {
        int k0 = ks * 8;
        #pragma unroll
        for (int t = 0; t < 2; t++) {
            int m0 = (mtb + t) * 16;
            a[t][0] = sA[(m0 + gy) * 132 + k0 + gx];
            a[t][1] = sA[(m0 + gy + 8) * 132 + k0 + gx];
            a[t][2] = sA[(m0 + gy) * 132 + k0 + gx + 4];
            a[t][3] = sA[(m0 + gy + 8) * 132 + k0 + gx + 4];
        }
        #pragma unroll
        for (int j = 0; j < 4; j++) {
            int nn0 = (ntb + j) * 8;
            b[j][0] = __ldg(&g_wo1_tf[(k0 + gx) * HD + nn0 + gy]);
            b[j][1] = __ldg(&g_wo1_tf[(k0 + gx + 4) * HD + nn0 + gy]);
        }
        #pragma unroll
        for (int t = 0; t < 2; t++)
            #pragma unroll
            for (int j = 0; j < 4; j++) mma_tf32(c[t][j], a[t], b[j]);
    }
    __syncthreads();   // all mma reads of sA done; reuse as fp32 U

    float* U = (float*)sA;
    #define LR(x) ((x) >= 0.f ? (x) : 0.1f * (x))
    #pragma unroll
    for (int t = 0; t < 2; t++)
        #pragma unroll
        for (int j = 0; j < 4; j++) {
            int r = (mtb + t) * 16 + gy;
            int col = (ntb + j) * 8 + 2 * gx;
            *(float2*)&U[r * 132 + col]       = make_float2(LR(c[t][j][0]), LR(c[t][j][1]));
            *(float2*)&U[(r + 8) * 132 + col] = make_float2(LR(c[t][j][2]), LR(c[t][j][3]));
        }
    #undef LR
    __syncthreads();

    float b2v = bo2[0];
    #pragma unroll
    for (int rr = 0; rr < 8; rr++) {
        int r = w * 8 + rr;
        float p = U[r * 132 + lane]       * sw2o[lane]
                + U[r * 132 + lane + 32]  * sw2o[lane + 32]
                + U[r * 132 + lane + 64]  * sw2o[lane + 64]
                + U[r * 132 + lane + 96]  * sw2o[lane + 96];
        #pragma unroll
        for (int o = 16; o; o >>= 1) p += __shfl_xor_sync(0xffffffffu, p, o);
        int gr = n0 + r;
        if (lane == 0 && gr < NN) out[gr] = p + b2v;
    }
}

// ---------------- launch ----------------
extern "C" void kernel_launch(void* const* d_in, const int* in_sizes, int n_in,
                              void* d_out, int out_size) {
    const float* feat = (const float*)d_in[0];
    const float* bit  = (const float*)d_in[1];
    const int*   src  = (const int*)d_in[2];
    const int*   dst  = (const int*)d_in[3];
    const float* W1   = (const float*)d_in[4];
    const float* b1   = (const float*)d_in[5];
    const float* W2   = (const float*)d_in[6];
    const float* b2   = (const float*)d_in[7];
    const float* Wnm  = (const float*)d_in[8];
    const float* bnm  = (const float*)d_in[9];
    const float* attn = (const float*)d_in[10];
    const float* Wo1  = (const float*)d_in[11];
    const float* bo1  = (const float*)d_in[12];
    const float* Wo2  = (const float*)d_in[13];
    const float* bo2  = (const float*)d_in[14];
    float* out = (float*)d_out;

    precompute_kernel<<<1, 256>>>(Wnm, bnm, attn, W2, b2);
    wcomb_kernel<<<64, 128>>>(W2, Wnm);
    wo1tf_kernel<<<64, 256>>>(Wo1);
    node_kernel<<<NB64, 256>>>(feat, W1, b1);
    hist_kernel<<<NE / 256, 256>>>(dst);
    scan1_kernel<<<SCAN_NB, SCAN_T>>>();
    scan2_kernel<<<1, 128>>>();
    scan3_kernel<<<SCAN_NB, SCAN_T>>>();
    scatter_kernel<<<NE / 256, 256>>>(bit, src, dst);
    agg_kernel<<<(NN + 7) / 8, 256>>>(Wnm, bnm);
    out_kernel<<<NB64, 256>>>(bo1, Wo2, bo2, out);
}

// round 10
// speedup vs baseline: 3.2870x; 1.1531x over previous
#include <cuda_runtime.h>
#include <math.h>

#define NN 100000
#define NE 1600000
#define FD 16
#define HD 128
#define NB64 1563                 // ceil(NN/64)
#define SCAN_T 1024
#define SCAN_NB ((NN + SCAN_T - 1) / SCAN_T)   // 98

// ---------------- scratch (static device globals; no allocation) ----------------
__device__ float g_hz[(NN + 64) * HD];
__device__ float g_fz[(NN + 64) * HD];
__device__ float g_t[(NN + 64) * HD];
__device__ float g_ah[NN];
__device__ float g_af[NN];
__device__ unsigned g_wcomb_tf[64 * HD];   // tf32(W2 @ Wh)
__device__ unsigned g_wf_tf[FD * HD];      // tf32(Wnm feat rows)
__device__ unsigned g_wo1_tf[HD * HD];     // tf32(Wo1)
__device__ float g_bcomb[HD];              // b2 @ Wh
__device__ float g_vah[64];                // W2 @ wha
__device__ float g_vahb;                   // b2 . wha
__device__ float g_wfa[FD];
__device__ float g_aw;
__device__ float g_ab;
// CSR build
__device__ int   g_deg[NN];
__device__ int   g_off[NN];
__device__ int   g_cursor[NN];
__device__ int   g_bsum[SCAN_NB];
__device__ int   g_bpre[SCAN_NB];
// permuted edges: x = ah[src]+aw*bit+ab, y = bit, z = bits(src), w unused (+4 pad records)
__device__ float4 g_edge[NE + 4];

// ---------------- tf32 / mma helpers ----------------
__device__ __forceinline__ unsigned f2tf32(float x) {
    unsigned r;
    asm("cvt.rna.tf32.f32 %0, %1;" : "=r"(r) : "f"(x));
    return r;
}
__device__ __forceinline__ void mma_tf32(float c[4], const unsigned a[4], const unsigned b[2]) {
    asm("mma.sync.aligned.m16n8k8.row.col.f32.tf32.tf32.f32 "
        "{%0,%1,%2,%3},{%4,%5,%6,%7},{%8,%9},{%0,%1,%2,%3};"
        : "+f"(c[0]), "+f"(c[1]), "+f"(c[2]), "+f"(c[3])
        : "r"(a[0]), "r"(a[1]), "r"(a[2]), "r"(a[3]), "r"(b[0]), "r"(b[1]));
}

// ---------------- K0: fold attn into weights + derived vectors + tf32 feat-W ----------------
__global__ void precompute_kernel(const float* __restrict__ Wnm,
                                  const float* __restrict__ bnm,
                                  const float* __restrict__ attn,
                                  const float* __restrict__ W2,
                                  const float* __restrict__ b2) {
    __shared__ float sattn[HD];
    __shared__ float swha[HD];
    int tid = threadIdx.x;
    if (tid < HD) sattn[tid] = attn[tid];
    __syncthreads();
    if (tid < HD) {
        float s = 0.f;
        #pragma unroll 8
        for (int j = 0; j < HD; j++) s += Wnm[tid * HD + j] * sattn[j];
        swha[tid] = s;
    } else if (tid < HD + FD) {
        int i = tid - HD;
        float s = 0.f;
        #pragma unroll 8
        for (int j = 0; j < HD; j++) s += Wnm[(129 + i) * HD + j] * sattn[j];
        g_wfa[i] = s;
    } else if (tid == HD + FD) {
        float s = 0.f;
        for (int j = 0; j < HD; j++) s += Wnm[128 * HD + j] * sattn[j];
        g_aw = s;
    } else if (tid == HD + FD + 1) {
        float s = 0.f;
        for (int j = 0; j < HD; j++) s += bnm[j] * sattn[j];
        g_ab = s;
    } else if (tid < HD + FD + 6) {
        g_edge[NE + (tid - HD - FD - 2)] = make_float4(0.f, 0.f, 0.f, 0.f);
    }
    __syncthreads();
    if (tid < 64) {
        float s = 0.f;
        #pragma unroll 8
        for (int k = 0; k < HD; k++) s += W2[tid * HD + k] * swha[k];
        g_vah[tid] = s;
    } else if (tid == 64) {
        float s = 0.f;
        for (int k = 0; k < HD; k++) s += b2[k] * swha[k];
        g_vahb = s;
    }
    if (tid < HD) {
        float s = 0.f;
        #pragma unroll 8
        for (int k = 0; k < HD; k++) s += b2[k] * Wnm[k * HD + tid];
        g_bcomb[tid] = s;
    }
    for (int i = tid; i < FD * HD; i += 256)
        g_wf_tf[i] = f2tf32(Wnm[(129 + (i >> 7)) * HD + (i & 127)]);
}

// ---------------- K0b: Wcomb = tf32(W2 @ Wh) ----------------
__global__ void wcomb_kernel(const float* __restrict__ W2, const float* __restrict__ Wnm) {
    int r = blockIdx.x;          // 0..63
    int c = threadIdx.x;         // 0..127
    float s = 0.f;
    #pragma unroll 8
    for (int k = 0; k < HD; k++) s += W2[r * HD + k] * Wnm[k * HD + c];
    g_wcomb_tf[r * HD + c] = f2tf32(s);
}

// ---------------- K0c: tf32 copy of Wo1 ----------------
__global__ void wo1tf_kernel(const float* __restrict__ Wo1) {
    int i = blockIdx.x * 256 + threadIdx.x;
    g_wo1_tf[i] = f2tf32(Wo1[i]);
}

// ---------------- K1: fused node kernel ----------------
// hid = lrelu(feat@W1+b1) (row-per-thread, conflict-free LDS.128)
// -> hz = hid@Wcomb + bcomb (tf32 mma, B from gmem), fz = feat@Wf, a_h, a_f, deg=0
__global__ void __launch_bounds__(256) node_kernel(const float* __restrict__ feat,
                            const float* __restrict__ W1, const float* __restrict__ b1) {
    __shared__ float sW1t[64 * 20];     // transposed W1: sW1t[j*20+k]
    __shared__ float sb1[64];
    __shared__ float sv[64];
    __shared__ float swfa[FD];
    __shared__ float sbc[HD];
    __shared__ float sfeat[64 * FD];
    __shared__ unsigned As1[64 * 68];   // tf32 hid
    __shared__ unsigned As2[64 * 20];   // tf32 feat

    const int tid = threadIdx.x;
    const int n0 = blockIdx.x * 64;
    const int lane = tid & 31;

    for (int i = tid; i < 1024; i += 256) sW1t[(i & 63) * 20 + (i >> 6)] = W1[i];
    if (tid < 64) { sb1[tid] = b1[tid]; sv[tid] = g_vah[tid]; }
    if (tid < FD) swfa[tid] = g_wfa[tid];
    if (tid < HD) sbc[tid] = g_bcomb[tid];
    for (int i = tid; i < 64 * FD; i += 256) {
        int gr = n0 + (i >> 4);
        float v = (gr < NN) ? feat[gr * FD + (i & 15)] : 0.f;
        sfeat[i] = v;
        As2[(i >> 4) * 20 + (i & 15)] = f2tf32(v);
    }
    __syncthreads();

    // hid: thread owns row r, quarter q (j = 4i+q)
    {
        const int r = tid >> 2, q = tid & 3;
        const float4 f0 = *(const float4*)&sfeat[r * 16];
        const float4 f1 = *(const float4*)&sfeat[r * 16 + 4];
        const float4 f2 = *(const float4*)&sfeat[r * 16 + 8];
        const float4 f3 = *(const float4*)&sfeat[r * 16 + 12];
        float pa = 0.f;
        #pragma unroll
        for (int i = 0; i < 16; i++) {
            int j = 4 * i + q;
            const float4* wp = (const float4*)&sW1t[j * 20];
            float4 w0 = wp[0], w1 = wp[1], w2 = wp[2], w3 = wp[3];
            float acc = sb1[j]
                + f0.x*w0.x + f0.y*w0.y + f0.z*w0.z + f0.w*w0.w
                + f1.x*w1.x + f1.y*w1.y + f1.z*w1.z + f1.w*w1.w
                + f2.x*w2.x + f2.y*w2.y + f2.z*w2.z + f2.w*w2.w
                + f3.x*w3.x + f3.y*w3.y + f3.z*w3.z + f3.w*w3.w;
            acc = (acc >= 0.f) ? acc : 0.1f * acc;
            As1[r * 68 + j] = f2tf32(acc);
            pa += acc * sv[j];
        }
        pa += __shfl_xor_sync(0xffffffffu, pa, 1);
        pa += __shfl_xor_sync(0xffffffffu, pa, 2);
        int gn = n0 + r;
        if (gn < NN) {
            if (q == 0) g_ah[gn] = pa + g_vahb;
            else if (q == 1) {
                float af = f0.x*swfa[0] + f0.y*swfa[1] + f0.z*swfa[2] + f0.w*swfa[3]
                         + f1.x*swfa[4] + f1.y*swfa[5] + f1.z*swfa[6] + f1.w*swfa[7]
                         + f2.x*swfa[8] + f2.y*swfa[9] + f2.z*swfa[10] + f2.w*swfa[11]
                         + f3.x*swfa[12] + f3.y*swfa[13] + f3.z*swfa[14] + f3.w*swfa[15];
                g_af[gn] = af;
            } else if (q == 2) g_deg[gn] = 0;
        }
    }
    __syncthreads();

    const int w = tid >> 5;
    const int gy = lane >> 2, gx = lane & 3;
    const int mtb = (w >> 2) * 2;        // 2 M-tiles of 16
    const int ntb = (w & 3) * 4;         // 4 N-tiles of 8

    float c[2][4][4];
    unsigned a[2][4], b[4][2];

    // ---- hz = hid @ Wcomb + bcomb ----
    #pragma unroll
    for (int t = 0; t < 2; t++)
        #pragma unroll
        for (int j = 0; j < 4; j++) {
            int col = (ntb + j) * 8 + 2 * gx;
            c[t][j][0] = sbc[col];  c[t][j][1] = sbc[col + 1];
            c[t][j][2] = sbc[col];  c[t][j][3] = sbc[col + 1];
        }
    #pragma unroll
    for (int ks = 0; ks < 8; ks++) {
        int k0 = ks * 8;
        #pragma unroll
        for (int t = 0; t < 2; t++) {
            int m0 = (mtb + t) * 16;
            a[t][0] = As1[(m0 + gy) * 68 + k0 + gx];
            a[t][1] = As1[(m0 + gy + 8) * 68 + k0 + gx];
            a[t][2] = As1[(m0 + gy) * 68 + k0 + gx + 4];
            a[t][3] = As1[(m0 + gy + 8) * 68 + k0 + gx + 4];
        }
        #pragma unroll
        for (int j = 0; j < 4; j++) {
            int nn0 = (ntb + j) * 8;
            b[j][0] = __ldg(&g_wcomb_tf[(k0 + gx) * HD + nn0 + gy]);
            b[j][1] = __ldg(&g_wcomb_tf[(k0 + gx + 4) * HD + nn0 + gy]);
        }
        #pragma unroll
        for (int t = 0; t < 2; t++)
            #pragma unroll
            for (int j = 0; j < 4; j++) mma_tf32(c[t][j], a[t], b[j]);
    }
    #pragma unroll
    for (int t = 0; t < 2; t++)
        #pragma unroll
        for (int j = 0; j < 4; j++) {
            int r = (mtb + t) * 16 + gy;
            int col = (ntb + j) * 8 + 2 * gx;
            *(float2*)&g_hz[(n0 + r) * HD + col]     = make_float2(c[t][j][0], c[t][j][1]);
            *(float2*)&g_hz[(n0 + r + 8) * HD + col] = make_float2(c[t][j][2], c[t][j][3]);
        }

    // ---- fz = feat @ Wf ----
    #pragma unroll
    for (int t = 0; t < 2; t++)
        #pragma unroll
        for (int j = 0; j < 4; j++) {
            c[t][j][0] = 0.f; c[t][j][1] = 0.f; c[t][j][2] = 0.f; c[t][j][3] = 0.f;
        }
    #pragma unroll
    for (int ks = 0; ks < 2; ks++) {
        int k0 = ks * 8;
        #pragma unroll
        for (int t = 0; t < 2; t++) {
            int m0 = (mtb + t) * 16;
            a[t][0] = As2[(m0 + gy) * 20 + k0 + gx];
            a[t][1] = As2[(m0 + gy + 8) * 20 + k0 + gx];
            a[t][2] = As2[(m0 + gy) * 20 + k0 + gx + 4];
            a[t][3] = As2[(m0 + gy + 8) * 20 + k0 + gx + 4];
        }
        #pragma unroll
        for (int j = 0; j < 4; j++) {
            int nn0 = (ntb + j) * 8;
            b[j][0] = __ldg(&g_wf_tf[(k0 + gx) * HD + nn0 + gy]);
            b[j][1] = __ldg(&g_wf_tf[(k0 + gx + 4) * HD + nn0 + gy]);
        }
        #pragma unroll
        for (int t = 0; t < 2; t++)
            #pragma unroll
            for (int j = 0; j < 4; j++) mma_tf32(c[t][j], a[t], b[j]);
    }
    #pragma unroll
    for (int t = 0; t < 2; t++)
        #pragma unroll
        for (int j = 0; j < 4; j++) {
            int r = (mtb + t) * 16 + gy;
            int col = (ntb + j) * 8 + 2 * gx;
            *(float2*)&g_fz[(n0 + r) * HD + col]     = make_float2(c[t][j][0], c[t][j][1]);
            *(float2*)&g_fz[(n0 + r + 8) * HD + col] = make_float2(c[t][j][2], c[t][j][3]);
        }
}

// ---------------- K3: degree histogram ----------------
__global__ void hist_kernel(const int* __restrict__ dst) {
    int e = blockIdx.x * blockDim.x + threadIdx.x;
    if (e >= NE) return;
    atomicAdd(&g_deg[dst[e]], 1);
}

// ---------------- K4: exclusive scan of g_deg ----------------
__global__ void scan1_kernel() {
    __shared__ int wsum[32];
    int tid = threadIdx.x, lane = tid & 31, wid = tid >> 5;
    int gid = blockIdx.x * SCAN_T + tid;
    int v = (gid < NN) ? g_deg[gid] : 0;
    int x = v;
    #pragma unroll
    for (int o = 1; o < 32; o <<= 1) {
        int y = __shfl_up_sync(0xffffffffu, x, o);
        if (lane >= o) x += y;
    }
    if (lane == 31) wsum[wid] = x;
    __syncthreads();
    if (wid == 0) {
        int w = wsum[lane];
        #pragma unroll
        for (int o = 1; o < 32; o <<= 1) {
            int y = __shfl_up_sync(0xffffffffu, w, o);
            if (lane >= o) w += y;
        }
        wsum[lane] = w;
    }
    __syncthreads();
    int wpre = (wid == 0) ? 0 : wsum[wid - 1];
    if (gid < NN) g_off[gid] = wpre + x - v;
    if (tid == SCAN_T - 1) g_bsum[blockIdx.x] = wpre + x;
}

__global__ void scan2_kernel() {
    __shared__ int ws[4];
    int tid = threadIdx.x, lane = tid & 31, wid = tid >> 5;
    int v = (tid < SCAN_NB) ? g_bsum[tid] : 0;
    int x = v;
    #pragma unroll
    for (int o = 1; o < 32; o <<= 1) {
        int y = __shfl_up_sync(0xffffffffu, x, o);
        if (lane >= o) x += y;
    }
    if (lane == 31) ws[wid] = x;
    __syncthreads();
    int wpre = 0;
    #pragma unroll
    for (int i = 0; i < 4; i++) if (i < wid) wpre += ws[i];
    if (tid < SCAN_NB) g_bpre[tid] = wpre + x - v;
}

__global__ void scan3_kernel() {
    int gid = blockIdx.x * SCAN_T + threadIdx.x;
    if (gid < NN) {
        int o = g_off[gid] + g_bpre[gid >> 10];
        g_off[gid] = o;
        g_cursor[gid] = o;
    }
}

// ---------------- K5: permute edges into CSR order ----------------
__global__ void scatter_kernel(const float* __restrict__ bit,
                               const int* __restrict__ src, const int* __restrict__ dst) {
    int e = blockIdx.x * blockDim.x + threadIdx.x;
    if (e >= NE) return;
    int s = src[e], d = dst[e];
    float b = bit[e];
    float ep = g_ah[s] + g_aw * b + g_ab;
    int pos = atomicAdd(&g_cursor[d], 1);
    g_edge[pos] = make_float4(ep, b, __int_as_float(s), 0.f);
}

// ---------------- K6: fused softmax + weighted gather + finalize + relu ----------------
// one warp per destination; fast path caches edge records in registers (deg<=32)
__global__ void agg_kernel(const float* __restrict__ Wnm, const float* __restrict__ bnm) {
    int gw = (blockIdx.x * blockDim.x + threadIdx.x) >> 5;
    int lane = threadIdx.x & 31;
    if (gw >= NN) return;
    const int c4 = lane * 4;

    int deg = g_deg[gw];
    float* tp = &g_t[gw * HD + c4];
    if (deg == 0) {
        *(float4*)tp = make_float4(0.f, 0.f, 0.f, 0.f);
        return;
    }
    int start = g_off[gw];
    float afd = g_af[gw];
    const float4* eb = &g_edge[start];

    float ax = 0.f, ay = 0.f, az = 0.f, aww = 0.f;
    float sbm;

    if (deg <= 32) {
        // lane i caches edge i (invalid lanes duplicate edge 0 with weight 0)
        float4 ed = eb[lane < deg ? lane : 0];
        float v = ed.x + afd;
        v = (v >= 0.f) ? v : 0.2f * v;
        float m = v;
        #pragma unroll
        for (int o = 16; o; o >>= 1) m = fmaxf(m, __shfl_xor_sync(0xffffffffu, m, o));
        float ee = (lane < deg) ? __expf(v - m) : 0.f;
        float s = ee, sb = ee * ed.y;
        #pragma unroll
        for (int o = 16; o; o >>= 1) {
            s  += __shfl_xor_sync(0xffffffffu, s, o);
            sb += __shfl_xor_sync(0xffffffffu, sb, o);
        }
        float inv = 1.f / s;
        float wgt = ee * inv;
        int si = __float_as_int(ed.z) * HD;

        for (int base = 0; base < deg; base += 4) {
            float w0 = __shfl_sync(0xffffffffu, wgt, base);
            float w1 = __shfl_sync(0xffffffffu, wgt, base + 1);
            float w2 = __shfl_sync(0xffffffffu, wgt, base + 2);
            float w3 = __shfl_sync(0xffffffffu, wgt, base + 3);
            int s0 = __shfl_sync(0xffffffffu, si, base);
            int s1 = __shfl_sync(0xffffffffu, si, base + 1);
            int s2 = __shfl_sync(0xffffffffu, si, base + 2);
            int s3 = __shfl_sync(0xffffffffu, si, base + 3);
            float4 H0 = *(const float4*)&g_hz[s0 + c4];
            float4 H1 = *(const float4*)&g_hz[s1 + c4];
            float4 H2 = *(const float4*)&g_hz[s2 + c4];
            float4 H3 = *(const float4*)&g_hz[s3 + c4];
            ax += w0 * H0.x + w1 * H1.x + w2 * H2.x + w3 * H3.x;
            ay += w0 * H0.y + w1 * H1.y + w2 * H2.y + w3 * H3.y;
            az += w0 * H0.z + w1 * H1.z + w2 * H2.z + w3 * H3.z;
            aww += w0 * H0.w + w1 * H1.w + w2 * H2.w + w3 * H3.w;
        }
        sbm = sb * inv;
    } else {
        // slow path: 3-pass (rare)
        float m = -INFINITY;
        for (int i = lane; i < deg; i += 32) {
            float v = eb[i].x + afd;
            v = (v >= 0.f) ? v : 0.2f * v;
            m = fmaxf(m, v);
        }
        #pragma unroll
        for (int o = 16; o; o >>= 1) m = fmaxf(m, __shfl_xor_sync(0xffffffffu, m, o));
        float s = 0.f, sb = 0.f;
        for (int i = lane; i < deg; i += 32) {
            float4 ed = eb[i];
            float v = ed.x + afd;
            v = (v >= 0.f) ? v : 0.2f * v;
            float ee = __expf(v - m);
            s += ee;
            sb += ee * ed.y;
        }
        #pragma unroll
        for (int o = 16; o; o >>= 1) {
            s  += __shfl_xor_sync(0xffffffffu, s, o);
            sb += __shfl_xor_sync(0xffffffffu, sb, o);
        }
        float inv = 1.f / s;
        for (int base = 0; base < deg; base += 4) {
            float4 E0 = eb[base];
            float4 E1 = eb[base + 1];
            float4 E2 = eb[base + 2];
            float4 E3 = eb[base + 3];
            float4 H0 = *(const float4*)&g_hz[__float_as_int(E0.z) * HD + c4];
            float4 H1 = *(const float4*)&g_hz[__float_as_int(E1.z) * HD + c4];
            float4 H2 = *(const float4*)&g_hz[__float_as_int(E2.z) * HD + c4];
            float4 H3 = *(const float4*)&g_hz[__float_as_int(E3.z) * HD + c4];
            float v0 = E0.x + afd; v0 = (v0 >= 0.f) ? v0 : 0.2f * v0;
            float v1 = E1.x + afd; v1 = (v1 >= 0.f) ? v1 : 0.2f * v1;
            float v2 = E2.x + afd; v2 = (v2 >= 0.f) ? v2 : 0.2f * v2;
            float v3 = E3.x + afd; v3 = (v3 >= 0.f) ? v3 : 0.2f * v3;
            float w0 = __expf(v0 - m) * inv;
            float w1 = (base + 1 < deg) ? __expf(v1 - m) * inv : 0.f;
            float w2 = (base + 2 < deg) ? __expf(v2 - m) * inv : 0.f;
            float w3 = (base + 3 < deg) ? __expf(v3 - m) * inv : 0.f;
            ax += w0 * H0.x + w1 * H1.x + w2 * H2.x + w3 * H3.x;
            ay += w0 * H0.y + w1 * H1.y + w2 * H2.y + w3 * H3.y;
            az += w0 * H0.z + w1 * H1.z + w2 * H2.z + w3 * H3.z;
            aww += w0 * H0.w + w1 * H1.w + w2 * H2.w + w3 * H3.w;
        }
        sbm = sb * inv;
    }

    float4 wb = *(const float4*)&Wnm[128 * HD + c4];
    float4 bn = *(const float4*)&bnm[c4];
    float4 fzv = *(const float4*)&g_fz[gw * HD + c4];
    float tx = ax + sbm * wb.x + fzv.x + bn.x;
    float ty = ay + sbm * wb.y + fzv.y + bn.y;
    float tz = az + sbm * wb.z + fzv.z + bn.z;
    float tw = aww + sbm * wb.w + fzv.w + bn.w;
    *(float4*)tp = make_float4(fmaxf(tx, 0.f), fmaxf(ty, 0.f),
                               fmaxf(tz, 0.f), fmaxf(tw, 0.f));
}

// ---------------- K7: tf32 mlp_out on g_t -> out (B from global tf32) ----------------
__global__ void __launch_bounds__(256) out_kernel(const float* __restrict__ bo1,
                           const float* __restrict__ Wo2, const float* __restrict__ bo2,
                           float* __restrict__ out) {
    __shared__ unsigned sA[64 * 132];   // tf32 A; reused as fp32 U
    __shared__ float sb1o[128];
    __shared__ float sw2o[128];

    const int tid = threadIdx.x;
    const int n0 = blockIdx.x * 64;

    for (int i = tid; i < 64 * 128; i += 256) {
        int r = i >> 7, c = i & 127;
        sA[r * 132 + c] = f2tf32(g_t[(n0 + r) * HD + c]);
    }
    if (tid < 128) { sb1o[tid] = bo1[tid]; sw2o[tid] = Wo2[tid]; }
    __syncthreads();

    const int w = tid >> 5, lane = tid & 31;
    const int gy = lane >> 2, gx = lane & 3;
    const int mtb = (w >> 2) * 2;
    const int ntb = (w & 3) * 4;

    float c[2][4][4];
    unsigned a[2][4], b[4][2];
    #pragma unroll
    for (int t = 0; t < 2; t++)
        #pragma unroll
        for (int j = 0; j < 4; j++) {
            int col = (ntb + j) * 8 + 2 * gx;
            c[t][j][0] = sb1o[col];  c[t][j][1] = sb1o[col + 1];
            c[t][j][2] = sb1o[col];  c[t][j][3] = sb1o[col + 1];
        }
    #pragma unroll
    for (int ks = 0; ks < 16; ks++) {
        int k0 = ks * 8;
        #pragma unroll
        for (int t = 0; t < 2; t++) {
            int m0 = (mtb + t) * 16;
            a[t][0] = sA[(m0 + gy) * 132 + k0 + gx];
            a[t][1] = sA[(m0 + gy + 8) * 132 + k0 + gx];
            a[t][2] = sA[(m0 + gy) * 132 + k0 + gx + 4];
            a[t][3] = sA[(m0 + gy + 8) * 132 + k0 + gx + 4];
        }
        #pragma unroll
        for (int j = 0; j < 4; j++) {
            int nn0 = (ntb + j) * 8;
            b[j][0] = __ldg(&g_wo1_tf[(k0 + gx) * HD + nn0 + gy]);
            b[j][1] = __ldg(&g_wo1_tf[(k0 + gx + 4) * HD + nn0 + gy]);
        }
        #pragma unroll
        for (int t = 0; t < 2; t++)
            #pragma unroll
            for (int j = 0; j < 4; j++) mma_tf32(c[t][j], a[t], b[j]);
    }
    __syncthreads();   // all mma reads of sA done; reuse as fp32 U

    float* U = (float*)sA;
    #define LR(x) ((x) >= 0.f ? (x) : 0.1f * (x))
    #pragma unroll
    for (int t = 0; t < 2; t++)
        #pragma unroll
        for (int j = 0; j < 4; j++) {
            int r = (mtb + t) * 16 + gy;
            int col = (ntb + j) * 8 + 2 * gx;
            *(float2*)&U[r * 132 + col]       = make_float2(LR(c[t][j][0]), LR(c[t][j][1]));
            *(float2*)&U[(r + 8) * 132 + col] = make_float2(LR(c[t][j][2]), LR(c[t][j][3]));
        }
    #undef LR
    __syncthreads();

    float b2v = bo2[0];
    #pragma unroll
    for (int rr = 0; rr < 8; rr++) {
        int r = w * 8 + rr;
        float p = U[r * 132 + lane]       * sw2o[lane]
                + U[r * 132 + lane + 32]  * sw2o[lane + 32]
                + U[r * 132 + lane + 64]  * sw2o[lane + 64]
                + U[r * 132 + lane + 96]  * sw2o[lane + 96];
        #pragma unroll
        for (int o = 16; o; o >>= 1) p += __shfl_xor_sync(0xffffffffu, p, o);
        int gr = n0 + r;
        if (lane == 0 && gr < NN) out[gr] = p + b2v;
    }
}

// ---------------- launch ----------------
extern "C" void kernel_launch(void* const* d_in, const int* in_sizes, int n_in,
                              void* d_out, int out_size) {
    const float* feat = (const float*)d_in[0];
    const float* bit  = (const float*)d_in[1];
    const int*   src  = (const int*)d_in[2];
    const int*   dst  = (const int*)d_in[3];
    const float* W1   = (const float*)d_in[4];
    const float* b1   = (const float*)d_in[5];
    const float* W2   = (const float*)d_in[6];
    const float* b2   = (const float*)d_in[7];
    const float* Wnm  = (const float*)d_in[8];
    const float* bnm  = (const float*)d_in[9];
    const float* attn = (const float*)d_in[10];
    const float* Wo1  = (const float*)d_in[11];
    const float* bo1  = (const float*)d_in[12];
    const float* Wo2  = (const float*)d_in[13];
    const float* bo2  = (const float*)d_in[14];
    float* out = (float*)d_out;

    precompute_kernel<<<1, 256>>>(Wnm, bnm, attn, W2, b2);
    wcomb_kernel<<<64, 128>>>(W2, Wnm);
    wo1tf_kernel<<<64, 256>>>(Wo1);
    node_kernel<<<NB64, 256>>>(feat, W1, b1);
    hist_kernel<<<NE / 256, 256>>>(dst);
    scan1_kernel<<<SCAN_NB, SCAN_T>>>();
    scan2_kernel<<<1, 128>>>();
    scan3_kernel<<<SCAN_NB, SCAN_T>>>();
    scatter_kernel<<<NE / 256, 256>>>(bit, src, dst);
    agg_kernel<<<(NN + 7) / 8, 256>>>(Wnm, bnm);
    out_kernel<<<NB64, 256>>>(bo1, Wo2, bo2, out);
}

// round 11
// speedup vs baseline: 3.6599x; 1.1135x over previous
#include <cuda_runtime.h>
#include <cuda_fp16.h>
#include <math.h>

#define NN 100000
#define NE 1600000
#define FD 16
#define HD 128
#define NB64 1563                 // ceil(NN/64)
#define SCAN_T 1024
#define SCAN_NB ((NN + SCAN_T - 1) / SCAN_T)   // 98

// ---------------- scratch (static device globals; no allocation) ----------------
__device__ __half g_hz_h[(NN + 64) * HD];   // fp16 hz payload for the gather
__device__ float g_fz[(NN + 64) * HD];
__device__ float g_t[(NN + 64) * HD];
__device__ float g_ah[NN];
__device__ float g_af[NN];
__device__ unsigned g_wcomb_tf[64 * HD];   // tf32(W2 @ Wh)
__device__ unsigned g_wf_tf[FD * HD];      // tf32(Wnm feat rows)
__device__ unsigned g_wo1_tf[HD * HD];     // tf32(Wo1)
__device__ float g_bcomb[HD];              // b2 @ Wh
__device__ float g_vah[64];                // W2 @ wha
__device__ float g_vahb;                   // b2 . wha
__device__ float g_wfa[FD];
__device__ float g_aw;
__device__ float g_ab;
// CSR build
__device__ int   g_deg[NN];
__device__ int   g_off[NN];
__device__ int   g_cursor[NN];
__device__ int   g_bsum[SCAN_NB];
__device__ int   g_bpre[SCAN_NB];
// permuted edges (8B): x = logit (fp32, exact bit folded in), y = bits{src:17 | bitq:15<<17}
__device__ float2 g_edge[NE + 4];

// ---------------- tf32 / mma helpers ----------------
__device__ __forceinline__ unsigned f2tf32(float x) {
    unsigned r;
    asm("cvt.rna.tf32.f32 %0, %1;" : "=r"(r) : "f"(x));
    return r;
}
__device__ __forceinline__ void mma_tf32(float c[4], const unsigned a[4], const unsigned b[2]) {
    asm("mma.sync.aligned.m16n8k8.row.col.f32.tf32.tf32.f32 "
        "{%0,%1,%2,%3},{%4,%5,%6,%7},{%8,%9},{%0,%1,%2,%3};"
        : "+f"(c[0]), "+f"(c[1]), "+f"(c[2]), "+f"(c[3])
        : "r"(a[0]), "r"(a[1]), "r"(a[2]), "r"(a[3]), "r"(b[0]), "r"(b[1]));
}

// ---------------- K0: fold attn into weights + derived vectors + tf32 feat-W ----------------
__global__ void precompute_kernel(const float* __restrict__ Wnm,
                                  const float* __restrict__ bnm,
                                  const float* __restrict__ attn,
                                  const float* __restrict__ W2,
                                  const float* __restrict__ b2) {
    __shared__ float sattn[HD];
    __shared__ float swha[HD];
    int tid = threadIdx.x;
    if (tid < HD) sattn[tid] = attn[tid];
    __syncthreads();
    if (tid < HD) {
        float s = 0.f;
        #pragma unroll 8
        for (int j = 0; j < HD; j++) s += Wnm[tid * HD + j] * sattn[j];
        swha[tid] = s;
    } else if (tid < HD + FD) {
        int i = tid - HD;
        float s = 0.f;
        #pragma unroll 8
        for (int j = 0; j < HD; j++) s += Wnm[(129 + i) * HD + j] * sattn[j];
        g_wfa[i] = s;
    } else if (tid == HD + FD) {
        float s = 0.f;
        for (int j = 0; j < HD; j++) s += Wnm[128 * HD + j] * sattn[j];
        g_aw = s;
    } else if (tid == HD + FD + 1) {
        float s = 0.f;
        for (int j = 0; j < HD; j++) s += bnm[j] * sattn[j];
        g_ab = s;
    } else if (tid < HD + FD + 6) {
        g_edge[NE + (tid - HD - FD - 2)] = make_float2(0.f, 0.f);
    }
    __syncthreads();
    if (tid < 64) {
        float s = 0.f;
        #pragma unroll 8
        for (int k = 0; k < HD; k++) s += W2[tid * HD + k] * swha[k];
        g_vah[tid] = s;
    } else if (tid == 64) {
        float s = 0.f;
        for (int k = 0; k < HD; k++) s += b2[k] * swha[k];
        g_vahb = s;
    }
    if (tid < HD) {
        float s = 0.f;
        #pragma unroll 8
        for (int k = 0; k < HD; k++) s += b2[k] * Wnm[k * HD + tid];
        g_bcomb[tid] = s;
    }
    for (int i = tid; i < FD * HD; i += 256)
        g_wf_tf[i] = f2tf32(Wnm[(129 + (i >> 7)) * HD + (i & 127)]);
}

// ---------------- K0b: Wcomb = tf32(W2 @ Wh) ----------------
__global__ void wcomb_kernel(const float* __restrict__ W2, const float* __restrict__ Wnm) {
    int r = blockIdx.x;          // 0..63
    int c = threadIdx.x;         // 0..127
    float s = 0.f;
    #pragma unroll 8
    for (int k = 0; k < HD; k++) s += W2[r * HD + k] * Wnm[k * HD + c];
    g_wcomb_tf[r * HD + c] = f2tf32(s);
}

// ---------------- K0c: tf32 copy of Wo1 ----------------
__global__ void wo1tf_kernel(const float* __restrict__ Wo1) {
    int i = blockIdx.x * 256 + threadIdx.x;
    g_wo1_tf[i] = f2tf32(Wo1[i]);
}

// ---------------- K1: fused node kernel ----------------
__global__ void __launch_bounds__(256) node_kernel(const float* __restrict__ feat,
                            const float* __restrict__ W1, const float* __restrict__ b1) {
    __shared__ float sW1t[64 * 20];     // transposed W1: sW1t[j*20+k]
    __shared__ float sb1[64];
    __shared__ float sv[64];
    __shared__ float swfa[FD];
    __shared__ float sbc[HD];
    __shared__ float sfeat[64 * FD];
    __shared__ unsigned As1[64 * 68];   // tf32 hid
    __shared__ unsigned As2[64 * 20];   // tf32 feat

    const int tid = threadIdx.x;
    const int n0 = blockIdx.x * 64;
    const int lane = tid & 31;

    for (int i = tid; i < 1024; i += 256) sW1t[(i & 63) * 20 + (i >> 6)] = W1[i];
    if (tid < 64) { sb1[tid] = b1[tid]; sv[tid] = g_vah[tid]; }
    if (tid < FD) swfa[tid] = g_wfa[tid];
    if (tid < HD) sbc[tid] = g_bcomb[tid];
    for (int i = tid; i < 64 * FD; i += 256) {
        int gr = n0 + (i >> 4);
        float v = (gr < NN) ? feat[gr * FD + (i & 15)] : 0.f;
        sfeat[i] = v;
        As2[(i >> 4) * 20 + (i & 15)] = f2tf32(v);
    }
    __syncthreads();

    // hid: thread owns row r, quarter q (j = 4i+q)
    {
        const int r = tid >> 2, q = tid & 3;
        const float4 f0 = *(const float4*)&sfeat[r * 16];
        const float4 f1 = *(const float4*)&sfeat[r * 16 + 4];
        const float4 f2 = *(const float4*)&sfeat[r * 16 + 8];
        const float4 f3 = *(const float4*)&sfeat[r * 16 + 12];
        float pa = 0.f;
        #pragma unroll
        for (int i = 0; i < 16; i++) {
            int j = 4 * i + q;
            const float4* wp = (const float4*)&sW1t[j * 20];
            float4 w0 = wp[0], w1 = wp[1], w2 = wp[2], w3 = wp[3];
            float acc = sb1[j]
                + f0.x*w0.x + f0.y*w0.y + f0.z*w0.z + f0.w*w0.w
                + f1.x*w1.x + f1.y*w1.y + f1.z*w1.z + f1.w*w1.w
                + f2.x*w2.x + f2.y*w2.y + f2.z*w2.z + f2.w*w2.w
                + f3.x*w3.x + f3.y*w3.y + f3.z*w3.z + f3.w*w3.w;
            acc = (acc >= 0.f) ? acc : 0.1f * acc;
            As1[r * 68 + j] = f2tf32(acc);
            pa += acc * sv[j];
        }
        pa += __shfl_xor_sync(0xffffffffu, pa, 1);
        pa += __shfl_xor_sync(0xffffffffu, pa, 2);
        int gn = n0 + r;
        if (gn < NN) {
            if (q == 0) g_ah[gn] = pa + g_vahb;
            else if (q == 1) {
                float af = f0.x*swfa[0] + f0.y*swfa[1] + f0.z*swfa[2] + f0.w*swfa[3]
                         + f1.x*swfa[4] + f1.y*swfa[5] + f1.z*swfa[6] + f1.w*swfa[7]
                         + f2.x*swfa[8] + f2.y*swfa[9] + f2.z*swfa[10] + f2.w*swfa[11]
                         + f3.x*swfa[12] + f3.y*swfa[13] + f3.z*swfa[14] + f3.w*swfa[15];
                g_af[gn] = af;
            } else if (q == 2) g_deg[gn] = 0;
        }
    }
    __syncthreads();

    const int w = tid >> 5;
    const int gy = lane >> 2, gx = lane & 3;
    const int mtb = (w >> 2) * 2;        // 2 M-tiles of 16
    const int ntb = (w & 3) * 4;         // 4 N-tiles of 8

    float c[2][4][4];
    unsigned a[2][4], b[4][2];

    // ---- hz = hid @ Wcomb + bcomb  (stored fp16) ----
    #pragma unroll
    for (int t = 0; t < 2; t++)
        #pragma unroll
        for (int j = 0; j < 4; j++) {
            int col = (ntb + j) * 8 + 2 * gx;
            c[t][j][0] = sbc[col];  c[t][j][1] = sbc[col + 1];
            c[t][j][2] = sbc[col];  c[t][j][3] = sbc[col + 1];
        }
    #pragma unroll
    for (int ks = 0; ks < 8; ks++) {
        int k0 = ks * 8;
        #pragma unroll
        for (int t = 0; t < 2; t++) {
            int m0 = (mtb + t) * 16;
            a[t][0] = As1[(m0 + gy) * 68 + k0 + gx];
            a[t][1] = As1[(m0 + gy + 8) * 68 + k0 + gx];
            a[t][2] = As1[(m0 + gy) * 68 + k0 + gx + 4];
            a[t][3] = As1[(m0 + gy + 8) * 68 + k0 + gx + 4];
        }
        #pragma unroll
        for (int j = 0; j < 4; j++) {
            int nn0 = (ntb + j) * 8;
            b[j][0] = __ldg(&g_wcomb_tf[(k0 + gx) * HD + nn0 + gy]);
            b[j][1] = __ldg(&g_wcomb_tf[(k0 + gx + 4) * HD + nn0 + gy]);
        }
        #pragma unroll
        for (int t = 0; t < 2; t++)
            #pragma unroll
            for (int j = 0; j < 4; j++) mma_tf32(c[t][j], a[t], b[j]);
    }
    #pragma unroll
    for (int t = 0; t < 2; t++)
        #pragma unroll
        for (int j = 0; j < 4; j++) {
            int r = (mtb + t) * 16 + gy;
            int col = (ntb + j) * 8 + 2 * gx;
            *(__half2*)&g_hz_h[(n0 + r) * HD + col]     = __floats2half2_rn(c[t][j][0], c[t][j][1]);
            *(__half2*)&g_hz_h[(n0 + r + 8) * HD + col] = __floats2half2_rn(c[t][j][2], c[t][j][3]);
        }

    // ---- fz = feat @ Wf ----
    #pragma unroll
    for (int t = 0; t < 2; t++)
        #pragma unroll
        for (int j = 0; j < 4; j++) {
            c[t][j][0] = 0.f; c[t][j][1] = 0.f; c[t][j][2] = 0.f; c[t][j][3] = 0.f;
        }
    #pragma unroll
    for (int ks = 0; ks < 2; ks++) {
        int k0 = ks * 8;
        #pragma unroll
        for (int t = 0; t < 2; t++) {
            int m0 = (mtb + t) * 16;
            a[t][0] = As2[(m0 + gy) * 20 + k0 + gx];
            a[t][1] = As2[(m0 + gy + 8) * 20 + k0 + gx];
            a[t][2] = As2[(m0 + gy) * 20 + k0 + gx + 4];
            a[t][3] = As2[(m0 + gy + 8) * 20 + k0 + gx + 4];
        }
        #pragma unroll
        for (int j = 0; j < 4; j++) {
            int nn0 = (ntb + j) * 8;
            b[j][0] = __ldg(&g_wf_tf[(k0 + gx) * HD + nn0 + gy]);
            b[j][1] = __ldg(&g_wf_tf[(k0 + gx + 4) * HD + nn0 + gy]);
        }
        #pragma unroll
        for (int t = 0; t < 2; t++)
            #pragma unroll
            for (int j = 0; j < 4; j++) mma_tf32(c[t][j], a[t], b[j]);
    }
    #pragma unroll
    for (int t = 0; t < 2; t++)
        #pragma unroll
        for (int j = 0; j < 4; j++) {
            int r = (mtb + t) * 16 + gy;
            int col = (ntb + j) * 8 + 2 * gx;
            *(float2*)&g_fz[(n0 + r) * HD + col]     = make_float2(c[t][j][0], c[t][j][1]);
            *(float2*)&g_fz[(n0 + r + 8) * HD + col] = make_float2(c[t][j][2], c[t][j][3]);
        }
}

// ---------------- K3: degree histogram ----------------
__global__ void hist_kernel(const int* __restrict__ dst) {
    int e = blockIdx.x * blockDim.x + threadIdx.x;
    if (e >= NE) return;
    atomicAdd(&g_deg[dst[e]], 1);
}

// ---------------- K4: exclusive scan of g_deg ----------------
__global__ void scan1_kernel() {
    __shared__ int wsum[32];
    int tid = threadIdx.x, lane = tid & 31, wid = tid >> 5;
    int gid = blockIdx.x * SCAN_T + tid;
    int v = (gid < NN) ? g_deg[gid] : 0;
    int x = v;
    #pragma unroll
    for (int o = 1; o < 32; o <<= 1) {
        int y = __shfl_up_sync(0xffffffffu, x, o);
        if (lane >= o) x += y;
    }
    if (lane == 31) wsum[wid] = x;
    __syncthreads();
    if (wid == 0) {
        int w = wsum[lane];
        #pragma unroll
        for (int o = 1; o < 32; o <<= 1) {
            int y = __shfl_up_sync(0xffffffffu, w, o);
            if (lane >= o) w += y;
        }
        wsum[lane] = w;
    }
    __syncthreads();
    int wpre = (wid == 0) ? 0 : wsum[wid - 1];
    if (gid < NN) g_off[gid] = wpre + x - v;
    if (tid == SCAN_T - 1) g_bsum[blockIdx.x] = wpre + x;
}

__global__ void scan2_kernel() {
    __shared__ int ws[4];
    int tid = threadIdx.x, lane = tid & 31, wid = tid >> 5;
    int v = (tid < SCAN_NB) ? g_bsum[tid] : 0;
    int x = v;
    #pragma unroll
    for (int o = 1; o < 32; o <<= 1) {
        int y = __shfl_up_sync(0xffffffffu, x, o);
        if (lane >= o) x += y;
    }
    if (lane == 31) ws[wid] = x;
    __syncthreads();
    int wpre = 0;
    #pragma unroll
    for (int i = 0; i < 4; i++) if (i < wid) wpre += ws[i];
    if (tid < SCAN_NB) g_bpre[tid] = wpre + x - v;
}

__global__ void scan3_kernel() {
    int gid = blockIdx.x * SCAN_T + threadIdx.x;
    if (gid < NN) {
        int o = g_off[gid] + g_bpre[gid >> 10];
        g_off[gid] = o;
        g_cursor[gid] = o;
    }
}

// ---------------- K5: permute edges into CSR order (8B records) ----------------
__global__ void scatter_kernel(const float* __restrict__ bit,
                               const int* __restrict__ src, const int* __restrict__ dst) {
    int e = blockIdx.x * blockDim.x + threadIdx.x;
    if (e >= NE) return;
    int s = src[e], d = dst[e];
    float b = bit[e];
    float ep = g_ah[s] + g_aw * b + g_ab;          // exact fp32 logit (pre-lrelu, pre-af)
    unsigned bq = (unsigned)(b * 32768.f);          // floor quantize, 15 bits (b < 1)
    if (bq > 32767u) bq = 32767u;
    unsigned packed = (unsigned)s | (bq << 17);
    int pos = atomicAdd(&g_cursor[d], 1);
    g_edge[pos] = make_float2(ep, __uint_as_float(packed));
}

// ---------------- K6: fused softmax + weighted fp16 gather + finalize + relu ----------------
__global__ void agg_kernel(const float* __restrict__ Wnm, const float* __restrict__ bnm) {
    int gw = (blockIdx.x * blockDim.x + threadIdx.x) >> 5;
    int lane = threadIdx.x & 31;
    if (gw >= NN) return;
    const int c4 = lane * 4;

    int deg = g_deg[gw];
    float* tp = &g_t[gw * HD + c4];
    if (deg == 0) {
        *(float4*)tp = make_float4(0.f, 0.f, 0.f, 0.f);
        return;
    }
    int start = g_off[gw];
    float afd = g_af[gw];
    const float2* eb = &g_edge[start];

    float ax = 0.f, ay = 0.f, az = 0.f, aww = 0.f;
    float sbm;

    if (deg <= 32) {
        float2 ed = eb[lane < deg ? lane : 0];
        unsigned u = __float_as_uint(ed.y);
        float bitf = (float)(u >> 17) * (1.0f / 32768.0f);
        int si = (int)(u & 0x1FFFFu) * HD;
        float v = ed.x + afd;
        v = (v >= 0.f) ? v : 0.2f * v;
        float m = v;
        #pragma unroll
        for (int o = 16; o; o >>= 1) m = fmaxf(m, __shfl_xor_sync(0xffffffffu, m, o));
        float ee = (lane < deg) ? __expf(v - m) : 0.f;
        float s = ee, sb = ee * bitf;
        #pragma unroll
        for (int o = 16; o; o >>= 1) {
            s  += __shfl_xor_sync(0xffffffffu, s, o);
            sb += __shfl_xor_sync(0xffffffffu, sb, o);
        }
        float inv = 1.f / s;
        float wgt = ee * inv;

        for (int base = 0; base < deg; base += 4) {
            float w0 = __shfl_sync(0xffffffffu, wgt, base);
            float w1 = __shfl_sync(0xffffffffu, wgt, base + 1);
            float w2 = __shfl_sync(0xffffffffu, wgt, base + 2);
            float w3 = __shfl_sync(0xffffffffu, wgt, base + 3);
            int s0 = __shfl_sync(0xffffffffu, si, base);
            int s1 = __shfl_sync(0xffffffffu, si, base + 1);
            int s2 = __shfl_sync(0xffffffffu, si, base + 2);
            int s3 = __shfl_sync(0xffffffffu, si, base + 3);
            uint2 q0 = *(const uint2*)&g_hz_h[s0 + c4];
            uint2 q1 = *(const uint2*)&g_hz_h[s1 + c4];
            uint2 q2 = *(const uint2*)&g_hz_h[s2 + c4];
            uint2 q3 = *(const uint2*)&g_hz_h[s3 + c4];
            float2 a0 = __half22float2(*(__half2*)&q0.x), b0 = __half22float2(*(__half2*)&q0.y);
            float2 a1 = __half22float2(*(__half2*)&q1.x), b1 = __half22float2(*(__half2*)&q1.y);
            float2 a2 = __half22float2(*(__half2*)&q2.x), b2 = __half22float2(*(__half2*)&q2.y);
            float2 a3 = __half22float2(*(__half2*)&q3.x), b3 = __half22float2(*(__half2*)&q3.y);
            ax += w0 * a0.x + w1 * a1.x + w2 * a2.x + w3 * a3.x;
            ay += w0 * a0.y + w1 * a1.y + w2 * a2.y + w3 * a3.y;
            az += w0 * b0.x + w1 * b1.x + w2 * b2.x + w3 * b3.x;
            aww += w0 * b0.y + w1 * b1.y + w2 * b2.y + w3 * b3.y;
        }
        sbm = sb * inv;
    } else {
        // slow path (rare: deg > 32)
        float m = -INFINITY;
        for (int i = lane; i < deg; i += 32) {
            float v = eb[i].x + afd;
            v = (v >= 0.f) ? v : 0.2f * v;
            m = fmaxf(m, v);
        }
        #pragma unroll
        for (int o = 16; o; o >>= 1) m = fmaxf(m, __shfl_xor_sync(0xffffffffu, m, o));
        float s = 0.f, sb = 0.f;
        for (int i = lane; i < deg; i += 32) {
            float2 ed = eb[i];
            float v = ed.x + afd;
            v = (v >= 0.f) ? v : 0.2f * v;
            float ee = __expf(v - m);
            s += ee;
            sb += ee * ((float)(__float_as_uint(ed.y) >> 17) * (1.0f / 32768.0f));
        }
        #pragma unroll
        for (int o = 16; o; o >>= 1) {
            s  += __shfl_xor_sync(0xffffffffu, s, o);
            sb += __shfl_xor_sync(0xffffffffu, sb, o);
        }
        float inv = 1.f / s;
        for (int base = 0; base < deg; base += 4) {
            float2 E0 = eb[base];
            float2 E1 = eb[base + 1];
            float2 E2 = eb[base + 2];
            float2 E3 = eb[base + 3];
            int s0 = (int)(__float_as_uint(E0.y) & 0x1FFFFu) * HD;
            int s1 = (int)(__float_as_uint(E1.y) & 0x1FFFFu) * HD;
            int s2 = (int)(__float_as_uint(E2.y) & 0x1FFFFu) * HD;
            int s3 = (int)(__float_as_uint(E3.y) & 0x1FFFFu) * HD;
            uint2 q0 = *(const uint2*)&g_hz_h[s0 + c4];
            uint2 q1 = *(const uint2*)&g_hz_h[s1 + c4];
            uint2 q2 = *(const uint2*)&g_hz_h[s2 + c4];
            uint2 q3 = *(const uint2*)&g_hz_h[s3 + c4];
            float v0 = E0.x + afd; v0 = (v0 >= 0.f) ? v0 : 0.2f * v0;
            float v1 = E1.x + afd; v1 = (v1 >= 0.f) ? v1 : 0.2f * v1;
            float v2 = E2.x + afd; v2 = (v2 >= 0.f) ? v2 : 0.2f * v2;
            float v3 = E3.x + afd; v3 = (v3 >= 0.f) ? v3 : 0.2f * v3;
            float w0 = __expf(v0 - m) * inv;
            float w1 = (base + 1 < deg) ? __expf(v1 - m) * inv : 0.f;
            float w2 = (base + 2 < deg) ? __expf(v2 - m) * inv : 0.f;
            float w3 = (base + 3 < deg) ? __expf(v3 - m) * inv : 0.f;
            float2 a0 = __half22float2(*(__half2*)&q0.x), b0 = __half22float2(*(__half2*)&q0.y);
            float2 a1 = __half22float2(*(__half2*)&q1.x), b1 = __half22float2(*(__half2*)&q1.y);
            float2 a2 = __half22float2(*(__half2*)&q2.x), b2 = __half22float2(*(__half2*)&q2.y);
            float2 a3 = __half22float2(*(__half2*)&q3.x), b3 = __half22float2(*(__half2*)&q3.y);
            ax += w0 * a0.x + w1 * a1.x + w2 * a2.x + w3 * a3.x;
            ay += w0 * a0.y + w1 * a1.y + w2 * a2.y + w3 * a3.y;
            az += w0 * b0.x + w1 * b1.x + w2 * b2.x + w3 * b3.x;
            aww += w0 * b0.y + w1 * b1.y + w2 * b2.y + w3 * b3.y;
        }
        sbm = sb * inv;
    }

    float4 wb = *(const float4*)&Wnm[128 * HD + c4];
    float4 bn = *(const float4*)&bnm[c4];
    float4 fzv = *(const float4*)&g_fz[gw * HD + c4];
    float tx = ax + sbm * wb.x + fzv.x + bn.x;
    float ty = ay + sbm * wb.y + fzv.y + bn.y;
    float tz = az + sbm * wb.z + fzv.z + bn.z;
    float tw = aww + sbm * wb.w + fzv.w + bn.w;
    *(float4*)tp = make_float4(fmaxf(tx, 0.f), fmaxf(ty, 0.f),
                               fmaxf(tz, 0.f), fmaxf(tw, 0.f));
}

// ---------------- K7: tf32 mlp_out on g_t -> out (B from global tf32) ----------------
__global__ void __launch_bounds__(256) out_kernel(const float* __restrict__ bo1,
                           const float* __restrict__ Wo2, const float* __restrict__ bo2,
                           float* __restrict__ out) {
    __shared__ unsigned sA[64 * 132];   // tf32 A; reused as fp32 U
    __shared__ float sb1o[128];
    __shared__ float sw2o[128];

    const int tid = threadIdx.x;
    const int n0 = blockIdx.x * 64;

    for (int i = tid; i < 64 * 128; i += 256) {
        int r = i >> 7, c = i & 127;
        sA[r * 132 + c] = f2tf32(g_t[(n0 + r) * HD + c]);
    }
    if (tid < 128) { sb1o[tid] = bo1[tid]; sw2o[tid] = Wo2[tid]; }
    __syncthreads();

    const int w = tid >> 5, lane = tid & 31;
    const int gy = lane >> 2, gx = lane & 3;
    const int mtb = (w >> 2) * 2;
    const int ntb = (w & 3) * 4;

    float c[2][4][4];
    unsigned a[2][4], b[4][2];
    #pragma unroll
    for (int t = 0; t < 2; t++)
        #pragma unroll
        for (int j = 0; j < 4; j++) {
            int col = (ntb + j) * 8 + 2 * gx;
            c[t][j][0] = sb1o[col];  c[t][j][1] = sb1o[col + 1];
            c[t][j][2] = sb1o[col];  c[t][j][3] = sb1o[col + 1];
        }
    #pragma unroll
    for (int ks = 0; ks < 16; ks++) {
        int k0 = ks * 8;
        #pragma unroll
        for (int t = 0; t < 2; t++) {
            int m0 = (mtb + t) * 16;
            a[t][0] = sA[(m0 + gy) * 132 + k0 + gx];
            a[t][1] = sA[(m0 + gy + 8) * 132 + k0 + gx];
            a[t][2] = sA[(m0 + gy) * 132 + k0 + gx + 4];
            a[t][3] = sA[(m0 + gy + 8) * 132 + k0 + gx + 4];
        }
        #pragma unroll
        for (int j = 0; j < 4; j++) {
            int nn0 = (ntb + j) * 8;
            b[j][0] = __ldg(&g_wo1_tf[(k0 + gx) * HD + nn0 + gy]);
            b[j][1] = __ldg(&g_wo1_tf[(k0 + gx + 4) * HD + nn0 + gy]);
        }
        #pragma unroll
        for (int t = 0; t < 2; t++)
            #pragma unroll
            for (int j = 0; j < 4; j++) mma_tf32(c[t][j], a[t], b[j]);
    }
    __syncthreads();   // all mma reads of sA done; reuse as fp32 U

    float* U = (float*)sA;
    #define LR(x) ((x) >= 0.f ? (x) : 0.1f * (x))
    #pragma unroll
    for (int t = 0; t < 2; t++)
        #pragma unroll
        for (int j = 0; j < 4; j++) {
            int r = (mtb + t) * 16 + gy;
            int col = (ntb + j) * 8 + 2 * gx;
            *(float2*)&U[r * 132 + col]       = make_float2(LR(c[t][j][0]), LR(c[t][j][1]));
            *(float2*)&U[(r + 8) * 132 + col] = make_float2(LR(c[t][j][2]), LR(c[t][j][3]));
        }
    #undef LR
    __syncthreads();

    float b2v = bo2[0];
    #pragma unroll
    for (int rr = 0; rr < 8; rr++) {
        int r = w * 8 + rr;
        float p = U[r * 132 + lane]       * sw2o[lane]
                + U[r * 132 + lane + 32]  * sw2o[lane + 32]
                + U[r * 132 + lane + 64]  * sw2o[lane + 64]
                + U[r * 132 + lane + 96]  * sw2o[lane + 96];
        #pragma unroll
        for (int o = 16; o; o >>= 1) p += __shfl_xor_sync(0xffffffffu, p, o);
        int gr = n0 + r;
        if (lane == 0 && gr < NN) out[gr] = p + b2v;
    }
}

// ---------------- launch ----------------
extern "C" void kernel_launch(void* const* d_in, const int* in_sizes, int n_in,
                              void* d_out, int out_size) {
    const float* feat = (const float*)d_in[0];
    const float* bit  = (const float*)d_in[1];
    const int*   src  = (const int*)d_in[2];
    const int*   dst  = (const int*)d_in[3];
    const float* W1   = (const float*)d_in[4];
    const float* b1   = (const float*)d_in[5];
    const float* W2   = (const float*)d_in[6];
    const float* b2   = (const float*)d_in[7];
    const float* Wnm  = (const float*)d_in[8];
    const float* bnm  = (const float*)d_in[9];
    const float* attn = (const float*)d_in[10];
    const float* Wo1  = (const float*)d_in[11];
    const float* bo1  = (const float*)d_in[12];
    const float* Wo2  = (const float*)d_in[13];
    const float* bo2  = (const float*)d_in[14];
    float* out = (float*)d_out;

    precompute_kernel<<<1, 256>>>(Wnm, bnm, attn, W2, b2);
    wcomb_kernel<<<64, 128>>>(W2, Wnm);
    wo1tf_kernel<<<64, 256>>>(Wo1);
    node_kernel<<<NB64, 256>>>(feat, W1, b1);
    hist_kernel<<<NE / 256, 256>>>(dst);
    scan1_kernel<<<SCAN_NB, SCAN_T>>>();
    scan2_kernel<<<1, 128>>>();
    scan3_kernel<<<SCAN_NB, SCAN_T>>>();
    scatter_kernel<<<NE / 256, 256>>>(bit, src, dst);
    agg_kernel<<<(NN + 7) / 8, 256>>>(Wnm, bnm);
    out_kernel<<<NB64, 256>>>(bo1, Wo2, bo2, out);
}

// round 12
// speedup vs baseline: 3.7491x; 1.0244x over previous
#include <cuda_runtime.h>
#include <cuda_fp16.h>
#include <math.h>

#define NN 100000
#define NE 1600000
#define FD 16
#define HD 128
#define NB64 1563                 // ceil(NN/64)
#define SCAN_T 1024
#define SCAN_NB ((NN + SCAN_T - 1) / SCAN_T)   // 98

// ---------------- scratch (static device globals; no allocation) ----------------
__device__ __half g_hz_h[(NN + 64) * HD];   // fp16 hz payload for the gather
__device__ __half g_fz_h[(NN + 64) * HD];   // fp16 fz
__device__ __half g_t_h[(NN + 64) * HD];    // fp16 t (relu'd neigh final)
__device__ float g_ah[NN];
__device__ float g_af[NN];
__device__ unsigned g_wcomb_tf[64 * HD];   // tf32(W2 @ Wh)
__device__ unsigned g_wf_tf[FD * HD];      // tf32(Wnm feat rows)
__device__ unsigned g_wo1_tf[HD * HD];     // tf32(Wo1)
__device__ float g_bcomb[HD];              // b2 @ Wh
__device__ float g_vah[64];                // W2 @ wha
__device__ float g_vahb;                   // b2 . wha
__device__ float g_wfa[FD];
__device__ float g_aw;
__device__ float g_ab;
// CSR build
__device__ int   g_deg[NN];
__device__ int   g_off[NN];
__device__ int   g_cursor[NN];
__device__ int   g_bsum[SCAN_NB];
__device__ int   g_bpre[SCAN_NB];
// permuted edges (8B): x = logit (fp32, exact bit folded in), y = bits{src:17 | bitq:15<<17}
__device__ float2 g_edge[NE + 8];

// ---------------- tf32 / mma helpers ----------------
__device__ __forceinline__ unsigned f2tf32(float x) {
    unsigned r;
    asm("cvt.rna.tf32.f32 %0, %1;" : "=r"(r) : "f"(x));
    return r;
}
__device__ __forceinline__ void mma_tf32(float c[4], const unsigned a[4], const unsigned b[2]) {
    asm("mma.sync.aligned.m16n8k8.row.col.f32.tf32.tf32.f32 "
        "{%0,%1,%2,%3},{%4,%5,%6,%7},{%8,%9},{%0,%1,%2,%3};"
        : "+f"(c[0]), "+f"(c[1]), "+f"(c[2]), "+f"(c[3])
        : "r"(a[0]), "r"(a[1]), "r"(a[2]), "r"(a[3]), "r"(b[0]), "r"(b[1]));
}

// ---------------- K0: fold attn into weights + derived vectors + tf32 feat-W ----------------
__global__ void precompute_kernel(const float* __restrict__ Wnm,
                                  const float* __restrict__ bnm,
                                  const float* __restrict__ attn,
                                  const float* __restrict__ W2,
                                  const float* __restrict__ b2) {
    __shared__ float sattn[HD];
    __shared__ float swha[HD];
    int tid = threadIdx.x;
    if (tid < HD) sattn[tid] = attn[tid];
    __syncthreads();
    if (tid < HD) {
        float s = 0.f;
        #pragma unroll 8
        for (int j = 0; j < HD; j++) s += Wnm[tid * HD + j] * sattn[j];
        swha[tid] = s;
    } else if (tid < HD + FD) {
        int i = tid - HD;
        float s = 0.f;
        #pragma unroll 8
        for (int j = 0; j < HD; j++) s += Wnm[(129 + i) * HD + j] * sattn[j];
        g_wfa[i] = s;
    } else if (tid == HD + FD) {
        float s = 0.f;
        for (int j = 0; j < HD; j++) s += Wnm[128 * HD + j] * sattn[j];
        g_aw = s;
    } else if (tid == HD + FD + 1) {
        float s = 0.f;
        for (int j = 0; j < HD; j++) s += bnm[j] * sattn[j];
        g_ab = s;
    } else if (tid < HD + FD + 10) {
        g_edge[NE + (tid - HD - FD - 2)] = make_float2(0.f, 0.f);
    }
    __syncthreads();
    if (tid < 64) {
        float s = 0.f;
        #pragma unroll 8
        for (int k = 0; k < HD; k++) s += W2[tid * HD + k] * swha[k];
        g_vah[tid] = s;
    } else if (tid == 64) {
        float s = 0.f;
        for (int k = 0; k < HD; k++) s += b2[k] * swha[k];
        g_vahb = s;
    }
    if (tid < HD) {
        float s = 0.f;
        #pragma unroll 8
        for (int k = 0; k < HD; k++) s += b2[k] * Wnm[k * HD + tid];
        g_bcomb[tid] = s;
    }
    for (int i = tid; i < FD * HD; i += 256)
        g_wf_tf[i] = f2tf32(Wnm[(129 + (i >> 7)) * HD + (i & 127)]);
}

// ---------------- K0b: Wcomb = tf32(W2 @ Wh) ----------------
__global__ void wcomb_kernel(const float* __restrict__ W2, const float* __restrict__ Wnm) {
    int r = blockIdx.x;          // 0..63
    int c = threadIdx.x;         // 0..127
    float s = 0.f;
    #pragma unroll 8
    for (int k = 0; k < HD; k++) s += W2[r * HD + k] * Wnm[k * HD + c];
    g_wcomb_tf[r * HD + c] = f2tf32(s);
}

// ---------------- K0c: tf32 copy of Wo1 ----------------
__global__ void wo1tf_kernel(const float* __restrict__ Wo1) {
    int i = blockIdx.x * 256 + threadIdx.x;
    g_wo1_tf[i] = f2tf32(Wo1[i]);
}

// ---------------- K1: fused node kernel ----------------
__global__ void __launch_bounds__(256, 4) node_kernel(const float* __restrict__ feat,
                            const float* __restrict__ W1, const float* __restrict__ b1) {
    __shared__ float sW1t[64 * 20];     // transposed W1: sW1t[j*20+k]
    __shared__ float sb1[64];
    __shared__ float sv[64];
    __shared__ float swfa[FD];
    __shared__ float sbc[HD];
    __shared__ float sfeat[64 * FD];
    __shared__ unsigned As1[64 * 68];   // tf32 hid
    __shared__ unsigned As2[64 * 20];   // tf32 feat

    const int tid = threadIdx.x;
    const int n0 = blockIdx.x * 64;
    const int lane = tid & 31;

    for (int i = tid; i < 1024; i += 256) sW1t[(i & 63) * 20 + (i >> 6)] = W1[i];
    if (tid < 64) { sb1[tid] = b1[tid]; sv[tid] = g_vah[tid]; }
    if (tid < FD) swfa[tid] = g_wfa[tid];
    if (tid < HD) sbc[tid] = g_bcomb[tid];
    for (int i = tid; i < 64 * FD; i += 256) {
        int gr = n0 + (i >> 4);
        float v = (gr < NN) ? feat[gr * FD + (i & 15)] : 0.f;
        sfeat[i] = v;
        As2[(i >> 4) * 20 + (i & 15)] = f2tf32(v);
    }
    __syncthreads();

    // hid: thread owns row r, quarter q (j = 4i+q)
    {
        const int r = tid >> 2, q = tid & 3;
        const float4 f0 = *(const float4*)&sfeat[r * 16];
        const float4 f1 = *(const float4*)&sfeat[r * 16 + 4];
        const float4 f2 = *(const float4*)&sfeat[r * 16 + 8];
        const float4 f3 = *(const float4*)&sfeat[r * 16 + 12];
        float pa = 0.f;
        #pragma unroll
        for (int i = 0; i < 16; i++) {
            int j = 4 * i + q;
            const float4* wp = (const float4*)&sW1t[j * 20];
            float4 w0 = wp[0], w1 = wp[1], w2 = wp[2], w3 = wp[3];
            float acc = sb1[j]
                + f0.x*w0.x + f0.y*w0.y + f0.z*w0.z + f0.w*w0.w
                + f1.x*w1.x + f1.y*w1.y + f1.z*w1.z + f1.w*w1.w
                + f2.x*w2.x + f2.y*w2.y + f2.z*w2.z + f2.w*w2.w
                + f3.x*w3.x + f3.y*w3.y + f3.z*w3.z + f3.w*w3.w;
            acc = (acc >= 0.f) ? acc : 0.1f * acc;
            As1[r * 68 + j] = f2tf32(acc);
            pa += acc * sv[j];
        }
        pa += __shfl_xor_sync(0xffffffffu, pa, 1);
        pa += __shfl_xor_sync(0xffffffffu, pa, 2);
        int gn = n0 + r;
        if (gn < NN) {
            if (q == 0) g_ah[gn] = pa + g_vahb;
            else if (q == 1) {
                float af = f0.x*swfa[0] + f0.y*swfa[1] + f0.z*swfa[2] + f0.w*swfa[3]
                         + f1.x*swfa[4] + f1.y*swfa[5] + f1.z*swfa[6] + f1.w*swfa[7]
                         + f2.x*swfa[8] + f2.y*swfa[9] + f2.z*swfa[10] + f2.w*swfa[11]
                         + f3.x*swfa[12] + f3.y*swfa[13] + f3.z*swfa[14] + f3.w*swfa[15];
                g_af[gn] = af;
            } else if (q == 2) g_deg[gn] = 0;
        }
    }
    __syncthreads();

    const int w = tid >> 5;
    const int gy = lane >> 2, gx = lane & 3;
    const int mtb = (w >> 2) * 2;        // 2 M-tiles of 16
    const int ntb = (w & 3) * 4;         // 4 N-tiles of 8

    float c[2][4][4];
    unsigned a[2][4], b[4][2];

    // ---- hz = hid @ Wcomb + bcomb  (stored fp16) ----
    #pragma unroll
    for (int t = 0; t < 2; t++)
        #pragma unroll
        for (int j = 0; j < 4; j++) {
            int col = (ntb + j) * 8 + 2 * gx;
            c[t][j][0] = sbc[col];  c[t][j][1] = sbc[col + 1];
            c[t][j][2] = sbc[col];  c[t][j][3] = sbc[col + 1];
        }
    #pragma unroll
    for (int ks = 0; ks < 8; ks++) {
        int k0 = ks * 8;
        #pragma unroll
        for (int t = 0; t < 2; t++) {
            int m0 = (mtb + t) * 16;
            a[t][0] = As1[(m0 + gy) * 68 + k0 + gx];
            a[t][1] = As1[(m0 + gy + 8) * 68 + k0 + gx];
            a[t][2] = As1[(m0 + gy) * 68 + k0 + gx + 4];
            a[t][3] = As1[(m0 + gy + 8) * 68 + k0 + gx + 4];
        }
        #pragma unroll
        for (int j = 0; j < 4; j++) {
            int nn0 = (ntb + j) * 8;
            b[j][0] = __ldg(&g_wcomb_tf[(k0 + gx) * HD + nn0 + gy]);
            b[j][1] = __ldg(&g_wcomb_tf[(k0 + gx + 4) * HD + nn0 + gy]);
        }
        #pragma unroll
        for (int t = 0; t < 2; t++)
            #pragma unroll
            for (int j = 0; j < 4; j++) mma_tf32(c[t][j], a[t], b[j]);
    }
    #pragma unroll
    for (int t = 0; t < 2; t++)
        #pragma unroll
        for (int j = 0; j < 4; j++) {
            int r = (mtb + t) * 16 + gy;
            int col = (ntb + j) * 8 + 2 * gx;
            *(__half2*)&g_hz_h[(n0 + r) * HD + col]     = __floats2half2_rn(c[t][j][0], c[t][j][1]);
            *(__half2*)&g_hz_h[(n0 + r + 8) * HD + col] = __floats2half2_rn(c[t][j][2], c[t][j][3]);
        }

    // ---- fz = feat @ Wf  (stored fp16) ----
    #pragma unroll
    for (int t = 0; t < 2; t++)
        #pragma unroll
        for (int j = 0; j < 4; j++) {
            c[t][j][0] = 0.f; c[t][j][1] = 0.f; c[t][j][2] = 0.f; c[t][j][3] = 0.f;
        }
    #pragma unroll
    for (int ks = 0; ks < 2; ks++) {
        int k0 = ks * 8;
        #pragma unroll
        for (int t = 0; t < 2; t++) {
            int m0 = (mtb + t) * 16;
            a[t][0] = As2[(m0 + gy) * 20 + k0 + gx];
            a[t][1] = As2[(m0 + gy + 8) * 20 + k0 + gx];
            a[t][2] = As2[(m0 + gy) * 20 + k0 + gx + 4];
            a[t][3] = As2[(m0 + gy + 8) * 20 + k0 + gx + 4];
        }
        #pragma unroll
        for (int j = 0; j < 4; j++) {
            int nn0 = (ntb + j) * 8;
            b[j][0] = __ldg(&g_wf_tf[(k0 + gx) * HD + nn0 + gy]);
            b[j][1] = __ldg(&g_wf_tf[(k0 + gx + 4) * HD + nn0 + gy]);
        }
        #pragma unroll
        for (int t = 0; t < 2; t++)
            #pragma unroll
            for (int j = 0; j < 4; j++) mma_tf32(c[t][j], a[t], b[j]);
    }
    #pragma unroll
    for (int t = 0; t < 2; t++)
        #pragma unroll
        for (int j = 0; j < 4; j++) {
            int r = (mtb + t) * 16 + gy;
            int col = (ntb + j) * 8 + 2 * gx;
            *(__half2*)&g_fz_h[(n0 + r) * HD + col]     = __floats2half2_rn(c[t][j][0], c[t][j][1]);
            *(__half2*)&g_fz_h[(n0 + r + 8) * HD + col] = __floats2half2_rn(c[t][j][2], c[t][j][3]);
        }
}

// ---------------- K3: degree histogram ----------------
__global__ void hist_kernel(const int* __restrict__ dst) {
    int e = blockIdx.x * blockDim.x + threadIdx.x;
    if (e >= NE) return;
    atomicAdd(&g_deg[dst[e]], 1);
}

// ---------------- K4: exclusive scan of g_deg ----------------
__global__ void scan1_kernel() {
    __shared__ int wsum[32];
    int tid = threadIdx.x, lane = tid & 31, wid = tid >> 5;
    int gid = blockIdx.x * SCAN_T + tid;
    int v = (gid < NN) ? g_deg[gid] : 0;
    int x = v;
    #pragma unroll
    for (int o = 1; o < 32; o <<= 1) {
        int y = __shfl_up_sync(0xffffffffu, x, o);
        if (lane >= o) x += y;
    }
    if (lane == 31) wsum[wid] = x;
    __syncthreads();
    if (wid == 0) {
        int w = wsum[lane];
        #pragma unroll
        for (int o = 1; o < 32; o <<= 1) {
            int y = __shfl_up_sync(0xffffffffu, w, o);
            if (lane >= o) w += y;
        }
        wsum[lane] = w;
    }
    __syncthreads();
    int wpre = (wid == 0) ? 0 : wsum[wid - 1];
    if (gid < NN) g_off[gid] = wpre + x - v;
    if (tid == SCAN_T - 1) g_bsum[blockIdx.x] = wpre + x;
}

__global__ void scan2_kernel() {
    __shared__ int ws[4];
    int tid = threadIdx.x, lane = tid & 31, wid = tid >> 5;
    int v = (tid < SCAN_NB) ? g_bsum[tid] : 0;
    int x = v;
    #pragma unroll
    for (int o = 1; o < 32; o <<= 1) {
        int y = __shfl_up_sync(0xffffffffu, x, o);
        if (lane >= o) x += y;
    }
    if (lane == 31) ws[wid] = x;
    __syncthreads();
    int wpre = 0;
    #pragma unroll
    for (int i = 0; i < 4; i++) if (i < wid) wpre += ws[i];
    if (tid < SCAN_NB) g_bpre[tid] = wpre + x - v;
}

__global__ void scan3_kernel() {
    int gid = blockIdx.x * SCAN_T + threadIdx.x;
    if (gid < NN) {
        int o = g_off[gid] + g_bpre[gid >> 10];
        g_off[gid] = o;
        g_cursor[gid] = o;
    }
}

// ---------------- K5: permute edges into CSR order (8B records) ----------------
__global__ void scatter_kernel(const float* __restrict__ bit,
                               const int* __restrict__ src, const int* __restrict__ dst) {
    int e = blockIdx.x * blockDim.x + threadIdx.x;
    if (e >= NE) return;
    int s = src[e], d = dst[e];
    float b = bit[e];
    float ep = g_ah[s] + g_aw * b + g_ab;          // exact fp32 logit (pre-lrelu, pre-af)
    unsigned bq = (unsigned)(b * 32768.f);          // floor quantize, 15 bits (b < 1)
    if (bq > 32767u) bq = 32767u;
    unsigned packed = (unsigned)s | (bq << 17);
    int pos = atomicAdd(&g_cursor[d], 1);
    g_edge[pos] = make_float2(ep, __uint_as_float(packed));
}

// ---------------- K6: fused softmax + weighted fp16 gather + finalize + relu ----------------
__global__ void agg_kernel(const float* __restrict__ Wnm, const float* __restrict__ bnm) {
    int gw = (blockIdx.x * blockDim.x + threadIdx.x) >> 5;
    int lane = threadIdx.x & 31;
    if (gw >= NN) return;
    const int c4 = lane * 4;

    int deg = g_deg[gw];
    __half* tp = &g_t_h[gw * HD + c4];
    if (deg == 0) {
        *(uint2*)tp = make_uint2(0u, 0u);
        return;
    }
    int start = g_off[gw];
    float afd = g_af[gw];
    const float2* eb = &g_edge[start];

    float ax = 0.f, ay = 0.f, az = 0.f, aww = 0.f;
    float sbm;

    if (deg <= 32) {
        float2 ed = eb[lane < deg ? lane : 0];
        unsigned u = __float_as_uint(ed.y);
        float bitf = (float)(u >> 17) * (1.0f / 32768.0f);
        int si = (int)(u & 0x1FFFFu) * HD;
        float v = ed.x + afd;
        v = (v >= 0.f) ? v : 0.2f * v;
        float m = v;
        #pragma unroll
        for (int o = 16; o; o >>= 1) m = fmaxf(m, __shfl_xor_sync(0xffffffffu, m, o));
        float ee = (lane < deg) ? __expf(v - m) : 0.f;
        float s = ee, sb = ee * bitf;
        #pragma unroll
        for (int o = 16; o; o >>= 1) {
            s  += __shfl_xor_sync(0xffffffffu, s, o);
            sb += __shfl_xor_sync(0xffffffffu, sb, o);
        }
        float inv = 1.f / s;
        float wgt = ee * inv;

        for (int base = 0; base < deg; base += 8) {
            float w0 = __shfl_sync(0xffffffffu, wgt, base);
            float w1 = __shfl_sync(0xffffffffu, wgt, base + 1);
            float w2 = __shfl_sync(0xffffffffu, wgt, base + 2);
            float w3 = __shfl_sync(0xffffffffu, wgt, base + 3);
            float w4 = __shfl_sync(0xffffffffu, wgt, base + 4);
            float w5 = __shfl_sync(0xffffffffu, wgt, base + 5);
            float w6 = __shfl_sync(0xffffffffu, wgt, base + 6);
            float w7 = __shfl_sync(0xffffffffu, wgt, base + 7);
            int s0 = __shfl_sync(0xffffffffu, si, base);
            int s1 = __shfl_sync(0xffffffffu, si, base + 1);
            int s2 = __shfl_sync(0xffffffffu, si, base + 2);
            int s3 = __shfl_sync(0xffffffffu, si, base + 3);
            int s4 = __shfl_sync(0xffffffffu, si, base + 4);
            int s5 = __shfl_sync(0xffffffffu, si, base + 5);
            int s6 = __shfl_sync(0xffffffffu, si, base + 6);
            int s7 = __shfl_sync(0xffffffffu, si, base + 7);
            uint2 q0 = *(const uint2*)&g_hz_h[s0 + c4];
            uint2 q1 = *(const uint2*)&g_hz_h[s1 + c4];
            uint2 q2 = *(const uint2*)&g_hz_h[s2 + c4];
            uint2 q3 = *(const uint2*)&g_hz_h[s3 + c4];
            uint2 q4 = *(const uint2*)&g_hz_h[s4 + c4];
            uint2 q5 = *(const uint2*)&g_hz_h[s5 + c4];
            uint2 q6 = *(const uint2*)&g_hz_h[s6 + c4];
            uint2 q7 = *(const uint2*)&g_hz_h[s7 + c4];
            float2 a0 = __half22float2(*(__half2*)&q0.x), b0 = __half22float2(*(__half2*)&q0.y);
            float2 a1 = __half22float2(*(__half2*)&q1.x), b1 = __half22float2(*(__half2*)&q1.y);
            float2 a2 = __half22float2(*(__half2*)&q2.x), b2 = __half22float2(*(__half2*)&q2.y);
            float2 a3 = __half22float2(*(__half2*)&q3.x), b3 = __half22float2(*(__half2*)&q3.y);
            float2 a4 = __half22float2(*(__half2*)&q4.x), b4 = __half22float2(*(__half2*)&q4.y);
            float2 a5 = __half22float2(*(__half2*)&q5.x), b5 = __half22float2(*(__half2*)&q5.y);
            float2 a6 = __half22float2(*(__half2*)&q6.x), b6 = __half22float2(*(__half2*)&q6.y);
            float2 a7 = __half22float2(*(__half2*)&q7.x), b7 = __half22float2(*(__half2*)&q7.y);
            ax += w0*a0.x + w1*a1.x + w2*a2.x + w3*a3.x + w4*a4.x + w5*a5.x + w6*a6.x + w7*a7.x;
            ay += w0*a0.y + w1*a1.y + w2*a2.y + w3*a3.y + w4*a4.y + w5*a5.y + w6*a6.y + w7*a7.y;
            az += w0*b0.x + w1*b1.x + w2*b2.x + w3*b3.x + w4*b4.x + w5*b5.x + w6*b6.x + w7*b7.x;
            aww += w0*b0.y + w1*b1.y + w2*b2.y + w3*b3.y + w4*b4.y + w5*b5.y + w6*b6.y + w7*b7.y;
        }
        sbm = sb * inv;
    } else {
        // slow path (rare: deg > 32)
        float m = -INFINITY;
        for (int i = lane; i < deg; i += 32) {
            float v = eb[i].x + afd;
            v = (v >= 0.f) ? v : 0.2f * v;
            m = fmaxf(m, v);
        }
        #pragma unroll
        for (int o = 16; o; o >>= 1) m = fmaxf(m, __shfl_xor_sync(0xffffffffu, m, o));
        float s = 0.f, sb = 0.f;
        for (int i = lane; i < deg; i += 32) {
            float2 ed = eb[i];
            float v = ed.x + afd;
            v = (v >= 0.f) ? v : 0.2f * v;
            float ee = __expf(v - m);
            s += ee;
            sb += ee * ((float)(__float_as_uint(ed.y) >> 17) * (1.0f / 32768.0f));
        }
        #pragma unroll
        for (int o = 16; o; o >>= 1) {
            s  += __shfl_xor_sync(0xffffffffu, s, o);
            sb += __shfl_xor_sync(0xffffffffu, sb, o);
        }
        float inv = 1.f / s;
        for (int base = 0; base < deg; base += 4) {
            float2 E0 = eb[base];
            float2 E1 = eb[base + 1];
            float2 E2 = eb[base + 2];
            float2 E3 = eb[base + 3];
            int s0 = (int)(__float_as_uint(E0.y) & 0x1FFFFu) * HD;
            int s1 = (int)(__float_as_uint(E1.y) & 0x1FFFFu) * HD;
            int s2 = (int)(__float_as_uint(E2.y) & 0x1FFFFu) * HD;
            int s3 = (int)(__float_as_uint(E3.y) & 0x1FFFFu) * HD;
            uint2 q0 = *(const uint2*)&g_hz_h[s0 + c4];
            uint2 q1 = *(const uint2*)&g_hz_h[s1 + c4];
            uint2 q2 = *(const uint2*)&g_hz_h[s2 + c4];
            uint2 q3 = *(const uint2*)&g_hz_h[s3 + c4];
            float v0 = E0.x + afd; v0 = (v0 >= 0.f) ? v0 : 0.2f * v0;
            float v1 = E1.x + afd; v1 = (v1 >= 0.f) ? v1 : 0.2f * v1;
            float v2 = E2.x + afd; v2 = (v2 >= 0.f) ? v2 : 0.2f * v2;
            float v3 = E3.x + afd; v3 = (v3 >= 0.f) ? v3 : 0.2f * v3;
            float w0 = __expf(v0 - m) * inv;
            float w1 = (base + 1 < deg) ? __expf(v1 - m) * inv : 0.f;
            float w2 = (base + 2 < deg) ? __expf(v2 - m) * inv : 0.f;
            float w3 = (base + 3 < deg) ? __expf(v3 - m) * inv : 0.f;
            float2 a0 = __half22float2(*(__half2*)&q0.x), b0 = __half22float2(*(__half2*)&q0.y);
            float2 a1 = __half22float2(*(__half2*)&q1.x), b1 = __half22float2(*(__half2*)&q1.y);
            float2 a2 = __half22float2(*(__half2*)&q2.x), b2 = __half22float2(*(__half2*)&q2.y);
            float2 a3 = __half22float2(*(__half2*)&q3.x), b3 = __half22float2(*(__half2*)&q3.y);
            ax += w0 * a0.x + w1 * a1.x + w2 * a2.x + w3 * a3.x;
            ay += w0 * a0.y + w1 * a1.y + w2 * a2.y + w3 * a3.y;
            az += w0 * b0.x + w1 * b1.x + w2 * b2.x + w3 * b3.x;
            aww += w0 * b0.y + w1 * b1.y + w2 * b2.y + w3 * b3.y;
        }
        sbm = sb * inv;
    }

    float4 wb = *(const float4*)&Wnm[128 * HD + c4];
    float4 bn = *(const float4*)&bnm[c4];
    uint2 fzq = *(const uint2*)&g_fz_h[gw * HD + c4];
    float2 fz0 = __half22float2(*(__half2*)&fzq.x);
    float2 fz1 = __half22float2(*(__half2*)&fzq.y);
    float tx = ax + sbm * wb.x + fz0.x + bn.x;
    float ty = ay + sbm * wb.y + fz0.y + bn.y;
    float tz = az + sbm * wb.z + fz1.x + bn.z;
    float tw = aww + sbm * wb.w + fz1.y + bn.w;
    __half2 o0 = __floats2half2_rn(fmaxf(tx, 0.f), fmaxf(ty, 0.f));
    __half2 o1 = __floats2half2_rn(fmaxf(tz, 0.f), fmaxf(tw, 0.f));
    *(uint2*)tp = make_uint2(*(unsigned*)&o0, *(unsigned*)&o1);
}

// ---------------- K7: tf32 mlp_out on g_t -> out (B from global tf32) ----------------
__global__ void __launch_bounds__(256) out_kernel(const float* __restrict__ bo1,
                           const float* __restrict__ Wo2, const float* __restrict__ bo2,
                           float* __restrict__ out) {
    __shared__ unsigned sA[64 * 132];   // tf32 A; reused as fp32 U
    __shared__ float sb1o[128];
    __shared__ float sw2o[128];

    const int tid = threadIdx.x;
    const int n0 = blockIdx.x * 64;

    for (int i = tid; i < 64 * 64; i += 256) {
        int r = i >> 6, c2 = i & 63;
        __half2 h = *(const __half2*)&g_t_h[(n0 + r) * HD + 2 * c2];
        float2 f = __half22float2(h);
        sA[r * 132 + 2 * c2]     = f2tf32(f.x);
        sA[r * 132 + 2 * c2 + 1] = f2tf32(f.y);
    }
    if (tid < 128) { sb1o[tid] = bo1[tid]; sw2o[tid] = Wo2[tid]; }
    __syncthreads();

    const int w = tid >> 5, lane = tid & 31;
    const int gy = lane >> 2, gx = lane & 3;
    const int mtb = (w >> 2) * 2;
    const int ntb = (w & 3) * 4;

    float c[2][4][4];
    unsigned a[2][4], b[4][2];
    #pragma unroll
    for (int t = 0; t < 2; t++)
        #pragma unroll
        for (int j = 0; j < 4; j++) {
            int col = (ntb + j) * 8 + 2 * gx;
            c[t][j][0] = sb1o[col];  c[t][j][1] = sb1o[col + 1];
            c[t][j][2] = sb1o[col];  c[t][j][3] = sb1o[col + 1];
        }
    #pragma unroll
    for (int ks = 0; ks < 16; ks++) {
        int k0 = ks * 8;
        #pragma unroll
        for (int t = 0; t < 2; t++) {
            int m0 = (mtb + t) * 16;
            a[t][0] = sA[(m0 + gy) * 132 + k0 + gx];
            a[t][1] = sA[(m0 + gy + 8) * 132 + k0 + gx];
            a[t][2] = sA[(m0 + gy) * 132 + k0 + gx + 4];
            a[t][3] = sA[(m0 + gy + 8) * 132 + k0 + gx + 4];
        }
        #pragma unroll
        for (int j = 0; j < 4; j++) {
            int nn0 = (ntb + j) * 8;
            b[j][0] = __ldg(&g_wo1_tf[(k0 + gx) * HD + nn0 + gy]);
            b[j][1] = __ldg(&g_wo1_tf[(k0 + gx + 4) * HD + nn0 + gy]);
        }
        #pragma unroll
        for (int t = 0; t < 2; t++)
            #pragma unroll
            for (int j = 0; j < 4; j++) mma_tf32(c[t][j], a[t], b[j]);
    }
    __syncthreads();   // all mma reads of sA done; reuse as fp32 U

    float* U = (float*)sA;
    #define LR(x) ((x) >= 0.f ? (x) : 0.1f * (x))
    #pragma unroll
    for (int t = 0; t < 2; t++)
        #pragma unroll
        for (int j = 0; j < 4; j++) {
            int r = (mtb + t) * 16 + gy;
            int col = (ntb + j) * 8 + 2 * gx;
            *(float2*)&U[r * 132 + col]       = make_float2(LR(c[t][j][0]), LR(c[t][j][1]));
            *(float2*)&U[(r + 8) * 132 + col] = make_float2(LR(c[t][j][2]), LR(c[t][j][3]));
        }
    #undef LR
    __syncthreads();

    float b2v = bo2[0];
    #pragma unroll
    for (int rr = 0; rr < 8; rr++) {
        int r = w * 8 + rr;
        float p = U[r * 132 + lane]       * sw2o[lane]
                + U[r * 132 + lane + 32]  * sw2o[lane + 32]
                + U[r * 132 + lane + 64]  * sw2o[lane + 64]
                + U[r * 132 + lane + 96]  * sw2o[lane + 96];
        #pragma unroll
        for (int o = 16; o; o >>= 1) p += __shfl_xor_sync(0xffffffffu, p, o);
        int gr = n0 + r;
        if (lane == 0 && gr < NN) out[gr] = p + b2v;
    }
}

// ---------------- launch ----------------
extern "C" void kernel_launch(void* const* d_in, const int* in_sizes, int n_in,
                              void* d_out, int out_size) {
    const float* feat = (const float*)d_in[0];
    const float* bit  = (const float*)d_in[1];
    const int*   src  = (const int*)d_in[2];
    const int*   dst  = (const int*)d_in[3];
    const float* W1   = (const float*)d_in[4];
    const float* b1   = (const float*)d_in[5];
    const float* W2   = (const float*)d_in[6];
    const float* b2   = (const float*)d_in[7];
    const float* Wnm  = (const float*)d_in[8];
    const float* bnm  = (const float*)d_in[9];
    const float* attn = (const float*)d_in[10];
    const float* Wo1  = (const float*)d_in[11];
    const float* bo1  = (const float*)d_in[12];
    const float* Wo2  = (const float*)d_in[13];
    const float* bo2  = (const float*)d_in[14];
    float* out = (float*)d_out;

    precompute_kernel<<<1, 256>>>(Wnm, bnm, attn, W2, b2);
    wcomb_kernel<<<64, 128>>>(W2, Wnm);
    wo1tf_kernel<<<64, 256>>>(Wo1);
    node_kernel<<<NB64, 256>>>(feat, W1, b1);
    hist_kernel<<<NE / 256, 256>>>(dst);
    scan1_kernel<<<SCAN_NB, SCAN_T>>>();
    scan2_kernel<<<1, 128>>>();
    scan3_kernel<<<SCAN_NB, SCAN_T>>>();
    scatter_kernel<<<NE / 256, 256>>>(bit, src, dst);
    agg_kernel<<<(NN + 7) / 8, 256>>>(Wnm, bnm);
    out_kernel<<<NB64, 256>>>(bo1, Wo2, bo2, out);
}

// round 15
// speedup vs baseline: 4.1114x; 1.0966x over previous
#include <cuda_runtime.h>
#include <cuda_fp16.h>
#include <math.h>

#define NN 100000
#define NE 1600000
#define FD 16
#define HD 128
#define NB64 1563                 // ceil(NN/64)
#define SCAN_T 1024
#define SCAN_NB ((NN + SCAN_T - 1) / SCAN_T)   // 98

// ---------------- scratch (static device globals; no allocation) ----------------
__device__ __half g_hz_h[(NN + 64) * HD];   // fp16 hz payload for the gather
__device__ __half g_fz_h[(NN + 64) * HD];   // fp16 fz
__device__ __half g_t_h[(NN + 64) * HD];    // fp16 t (relu'd neigh final)
__device__ float g_ah[NN];
__device__ float g_af[NN];
__device__ unsigned g_wcomb_h2[32 * HD];   // half2-packed (k-pairs) W2@Wh
__device__ unsigned g_wf_h2[8 * HD];       // half2-packed feat rows of Wnm
__device__ unsigned g_wo1_h2[64 * HD];     // half2-packed Wo1
__device__ float g_bcomb[HD];              // b2 @ Wh
__device__ float g_vah[64];                // W2 @ wha
__device__ float g_vahb;                   // b2 . wha
__device__ float g_wfa[FD];
__device__ float g_aw;
__device__ float g_ab;
// CSR build
__device__ int   g_deg[NN];
__device__ int   g_off[NN];
__device__ int   g_cursor[NN];
__device__ int   g_bsum[SCAN_NB];
__device__ int   g_bpre[SCAN_NB];
// permuted edges (8B): x = logit (fp32, exact bit folded in), y = bits{src:17 | bitq:15<<17}
__device__ float2 g_edge[NE + 8];

// ---------------- mma helper (fp16 inputs, fp32 accum) ----------------
__device__ __forceinline__ void mma_f16(float c[4], const unsigned a[4], const unsigned b[2]) {
    asm("mma.sync.aligned.m16n8k16.row.col.f32.f16.f16.f32 "
        "{%0,%1,%2,%3},{%4,%5,%6,%7},{%8,%9},{%0,%1,%2,%3};"
        : "+f"(c[0]), "+f"(c[1]), "+f"(c[2]), "+f"(c[3])
        : "r"(a[0]), "r"(a[1]), "r"(a[2]), "r"(a[3]), "r"(b[0]), "r"(b[1]));
}

// ---------------- K0: fold attn into weights + derived vectors + fp16 feat-W ----------------
__global__ void precompute_kernel(const float* __restrict__ Wnm,
                                  const float* __restrict__ bnm,
                                  const float* __restrict__ attn,
                                  const float* __restrict__ W2,
                                  const float* __restrict__ b2) {
    __shared__ float sattn[HD];
    __shared__ float swha[HD];
    int tid = threadIdx.x;
    if (tid < HD) sattn[tid] = attn[tid];
    __syncthreads();
    if (tid < HD) {
        float s = 0.f;
        #pragma unroll 8
        for (int j = 0; j < HD; j++) s += Wnm[tid * HD + j] * sattn[j];
        swha[tid] = s;
    } else if (tid < HD + FD) {
        int i = tid - HD;
        float s = 0.f;
        #pragma unroll 8
        for (int j = 0; j < HD; j++) s += Wnm[(129 + i) * HD + j] * sattn[j];
        g_wfa[i] = s;
    } else if (tid == HD + FD) {
        float s = 0.f;
        for (int j = 0; j < HD; j++) s += Wnm[128 * HD + j] * sattn[j];
        g_aw = s;
    } else if (tid == HD + FD + 1) {
        float s = 0.f;
        for (int j = 0; j < HD; j++) s += bnm[j] * sattn[j];
        g_ab = s;
    } else if (tid < HD + FD + 10) {
        g_edge[NE + (tid - HD - FD - 2)] = make_float2(0.f, 0.f);
    }
    __syncthreads();
    if (tid < 64) {
        float s = 0.f;
        #pragma unroll 8
        for (int k = 0; k < HD; k++) s += W2[tid * HD + k] * swha[k];
        g_vah[tid] = s;
    } else if (tid == 64) {
        float s = 0.f;
        for (int k = 0; k < HD; k++) s += b2[k] * swha[k];
        g_vahb = s;
    }
    if (tid < HD) {
        float s = 0.f;
        #pragma unroll 8
        for (int k = 0; k < HD; k++) s += b2[k] * Wnm[k * HD + tid];
        g_bcomb[tid] = s;
    }
    // half2-packed feat rows of Wnm (rows 129..144, k-pairs)
    for (int i = tid; i < 8 * HD; i += 256) {
        int kp = i >> 7, c = i & 127;
        __half2 h = __floats2half2_rn(Wnm[(129 + 2 * kp) * HD + c],
                                      Wnm[(129 + 2 * kp + 1) * HD + c]);
        g_wf_h2[i] = *(unsigned*)&h;
    }
}

// ---------------- K0b: Wcomb = half2(W2 @ Wh), k-pair packed ----------------
__global__ void wcomb_kernel(const float* __restrict__ W2, const float* __restrict__ Wnm) {
    int kp = blockIdx.x;         // 0..31 (pairs of hid-dim rows)
    int c = threadIdx.x;         // 0..127
    float s0 = 0.f, s1 = 0.f;
    #pragma unroll 8
    for (int k = 0; k < HD; k++) {
        float w = Wnm[k * HD + c];
        s0 += W2[(2 * kp) * HD + k] * w;
        s1 += W2[(2 * kp + 1) * HD + k] * w;
    }
    __half2 h = __floats2half2_rn(s0, s1);
    g_wcomb_h2[kp * HD + c] = *(unsigned*)&h;
}

// ---------------- K0c: half2-packed Wo1 ----------------
__global__ void wo1h_kernel(const float* __restrict__ Wo1) {
    int i = blockIdx.x * 256 + threadIdx.x;   // 64*128 = 8192
    int kp = i >> 7, c = i & 127;
    __half2 h = __floats2half2_rn(Wo1[(2 * kp) * HD + c], Wo1[(2 * kp + 1) * HD + c]);
    g_wo1_h2[i] = *(unsigned*)&h;
}

// ---------------- K1: fused node kernel (fp16 mma) ----------------
__global__ void __launch_bounds__(256, 4) node_kernel(const float* __restrict__ feat,
                            const float* __restrict__ W1, const float* __restrict__ b1) {
    __shared__ float sW1t[64 * 20];     // transposed W1: sW1t[j*20+k]
    __shared__ float sb1[64];
    __shared__ float sv[64];
    __shared__ float swfa[FD];
    __shared__ float sbc[HD];
    __shared__ float sfeat[64 * FD];
    __shared__ unsigned As1[64 * 36];   // fp16 hid, half2 rows stride 36 (72 halves)
    __shared__ unsigned As2[64 * 12];   // fp16 feat, half2 rows stride 12 (24 halves)

    const int tid = threadIdx.x;
    const int n0 = blockIdx.x * 64;
    const int lane = tid & 31;
    __half* As1h = (__half*)As1;
    __half* As2h = (__half*)As2;

    for (int i = tid; i < 1024; i += 256) sW1t[(i & 63) * 20 + (i >> 6)] = W1[i];
    if (tid < 64) { sb1[tid] = b1[tid]; sv[tid] = g_vah[tid]; }
    if (tid < FD) swfa[tid] = g_wfa[tid];
    if (tid < HD) sbc[tid] = g_bcomb[tid];
    for (int i = tid; i < 64 * FD; i += 256) {
        int gr = n0 + (i >> 4);
        float v = (gr < NN) ? feat[gr * FD + (i & 15)] : 0.f;
        sfeat[i] = v;
        As2h[(i >> 4) * 24 + (i & 15)] = __float2half_rn(v);
    }
    __syncthreads();

    // hid: thread owns row r, quarter q (j = 4i+q)
    {
        const int r = tid >> 2, q = tid & 3;
        const float4 f0 = *(const float4*)&sfeat[r * 16];
        const float4 f1 = *(const float4*)&sfeat[r * 16 + 4];
        const float4 f2 = *(const float4*)&sfeat[r * 16 + 8];
        const float4 f3 = *(const float4*)&sfeat[r * 16 + 12];
        float pa = 0.f;
        #pragma unroll
        for (int i = 0; i < 16; i++) {
            int j = 4 * i + q;
            const float4* wp = (const float4*)&sW1t[j * 20];
            float4 w0 = wp[0], w1 = wp[1], w2 = wp[2], w3 = wp[3];
            float acc = sb1[j]
                + f0.x*w0.x + f0.y*w0.y + f0.z*w0.z + f0.w*w0.w
                + f1.x*w1.x + f1.y*w1.y + f1.z*w1.z + f1.w*w1.w
                + f2.x*w2.x + f2.y*w2.y + f2.z*w2.z + f2.w*w2.w
                + f3.x*w3.x + f3.y*w3.y + f3.z*w3.z + f3.w*w3.w;
            acc = (acc >= 0.f) ? acc : 0.1f * acc;
            As1h[r * 72 + j] = __float2half_rn(acc);
            pa += acc * sv[j];
        }
        pa += __shfl_xor_sync(0xffffffffu, pa, 1);
        pa += __shfl_xor_sync(0xffffffffu, pa, 2);
        int gn = n0 + r;
        if (gn < NN) {
            if (q == 0) g_ah[gn] = pa + g_vahb;
            else if (q == 1) {
                float af = f0.x*swfa[0] + f0.y*swfa[1] + f0.z*swfa[2] + f0.w*swfa[3]
                         + f1.x*swfa[4] + f1.y*swfa[5] + f1.z*swfa[6] + f1.w*swfa[7]
                         + f2.x*swfa[8] + f2.y*swfa[9] + f2.z*swfa[10] + f2.w*swfa[11]
                         + f3.x*swfa[12] + f3.y*swfa[13] + f3.z*swfa[14] + f3.w*swfa[15];
                g_af[gn] = af;
            } else if (q == 2) g_deg[gn] = 0;
        }
    }
    __syncthreads();

    const int w = tid >> 5;
    const int gy = lane >> 2, gx = lane & 3;
    const int mtb = (w >> 2) * 2;        // 2 M-tiles of 16
    const int ntb = (w & 3) * 4;         // 4 N-tiles of 8

    float c[2][4][4];
    unsigned a[2][4], b[4][2];

    // ---- hz = hid @ Wcomb + bcomb  (fp16 mma, K=64 -> 4 k16 steps; stored fp16) ----
    #pragma unroll
    for (int t = 0; t < 2; t++)
        #pragma unroll
        for (int j = 0; j < 4; j++) {
            int col = (ntb + j) * 8 + 2 * gx;
            c[t][j][0] = sbc[col];  c[t][j][1] = sbc[col + 1];
            c[t][j][2] = sbc[col];  c[t][j][3] = sbc[col + 1];
        }
    #pragma unroll
    for (int ks = 0; ks < 4; ks++) {
        int k0p = ks * 8;
        #pragma unroll
        for (int t = 0; t < 2; t++) {
            int m0 = (mtb + t) * 16;
            a[t][0] = As1[(m0 + gy) * 36 + k0p + gx];
            a[t][1] = As1[(m0 + gy + 8) * 36 + k0p + gx];
            a[t][2] = As1[(m0 + gy) * 36 + k0p + gx + 4];
            a[t][3] = As1[(m0 + gy + 8) * 36 + k0p + gx + 4];
        }
        #pragma unroll
        for (int j = 0; j < 4; j++) {
            int nn0 = (ntb + j) * 8;
            b[j][0] = __ldg(&g_wcomb_h2[(k0p + gx) * HD + nn0 + gy]);
            b[j][1] = __ldg(&g_wcomb_h2[(k0p + gx + 4) * HD + nn0 + gy]);
        }
        #pragma unroll
        for (int t = 0; t < 2; t++)
            #pragma unroll
            for (int j = 0; j < 4; j++) mma_f16(c[t][j], a[t], b[j]);
    }
    #pragma unroll
    for (int t = 0; t < 2; t++)
        #pragma unroll
        for (int j = 0; j < 4; j++) {
            int r = (mtb + t) * 16 + gy;
            int col = (ntb + j) * 8 + 2 * gx;
            *(__half2*)&g_hz_h[(n0 + r) * HD + col]     = __floats2half2_rn(c[t][j][0], c[t][j][1]);
            *(__half2*)&g_hz_h[(n0 + r + 8) * HD + col] = __floats2half2_rn(c[t][j][2], c[t][j][3]);
        }

    // ---- fz = feat @ Wf  (fp16 mma, K=16 -> 1 step; stored fp16) ----
    #pragma unroll
    for (int t = 0; t < 2; t++)
        #pragma unroll
        for (int j = 0; j < 4; j++) {
            c[t][j][0] = 0.f; c[t][j][1] = 0.f; c[t][j][2] = 0.f; c[t][j][3] = 0.f;
        }
    #pragma unroll
    for (int t = 0; t < 2; t++) {
        int m0 = (mtb + t) * 16;
        a[t][0] = As2[(m0 + gy) * 12 + gx];
        a[t][1] = As2[(m0 + gy + 8) * 12 + gx];
        a[t][2] = As2[(m0 + gy) * 12 + gx + 4];
        a[t][3] = As2[(m0 + gy + 8) * 12 + gx + 4];
    }
    #pragma unroll
    for (int j = 0; j < 4; j++) {
        int nn0 = (ntb + j) * 8;
        b[j][0] = __ldg(&g_wf_h2[gx * HD + nn0 + gy]);
        b[j][1] = __ldg(&g_wf_h2[(gx + 4) * HD + nn0 + gy]);
    }
    #pragma unroll
    for (int t = 0; t < 2; t++)
        #pragma unroll
        for (int j = 0; j < 4; j++) mma_f16(c[t][j], a[t], b[j]);
    #pragma unroll
    for (int t = 0; t < 2; t++)
        #pragma unroll
        for (int j = 0; j < 4; j++) {
            int r = (mtb + t) * 16 + gy;
            int col = (ntb + j) * 8 + 2 * gx;
            *(__half2*)&g_fz_h[(n0 + r) * HD + col]     = __floats2half2_rn(c[t][j][0], c[t][j][1]);
            *(__half2*)&g_fz_h[(n0 + r + 8) * HD + col] = __floats2half2_rn(c[t][j][2], c[t][j][3]);
        }
}

// ---------------- K3: degree histogram ----------------
__global__ void hist_kernel(const int* __restrict__ dst) {
    int e = blockIdx.x * blockDim.x + threadIdx.x;
    if (e >= NE) return;
    atomicAdd(&g_deg[dst[e]], 1);
}

// ---------------- K4: exclusive scan of g_deg ----------------
__global__ void scan1_kernel() {
    __shared__ int wsum[32];
    int tid = threadIdx.x, lane = tid & 31, wid = tid >> 5;
    int gid = blockIdx.x * SCAN_T + tid;
    int v = (gid < NN) ? g_deg[gid] : 0;
    int x = v;
    #pragma unroll
    for (int o = 1; o < 32; o <<= 1) {
        int y = __shfl_up_sync(0xffffffffu, x, o);
        if (lane >= o) x += y;
    }
    if (lane == 31) wsum[wid] = x;
    __syncthreads();
    if (wid == 0) {
        int w = wsum[lane];
        #pragma unroll
        for (int o = 1; o < 32; o <<= 1) {
            int y = __shfl_up_sync(0xffffffffu, w, o);
            if (lane >= o) w += y;
        }
        wsum[lane] = w;
    }
    __syncthreads();
    int wpre = (wid == 0) ? 0 : wsum[wid - 1];
    if (gid < NN) g_off[gid] = wpre + x - v;
    if (tid == SCAN_T - 1) g_bsum[blockIdx.x] = wpre + x;
}

__global__ void scan2_kernel() {
    __shared__ int ws[4];
    int tid = threadIdx.x, lane = tid & 31, wid = tid >> 5;
    int v = (tid < SCAN_NB) ? g_bsum[tid] : 0;
    int x = v;
    #pragma unroll
    for (int o = 1; o < 32; o <<= 1) {
        int y = __shfl_up_sync(0xffffffffu, x, o);
        if (lane >= o) x += y;
    }
    if (lane == 31) ws[wid] = x;
    __syncthreads();
    int wpre = 0;
    #pragma unroll
    for (int i = 0; i < 4; i++) if (i < wid) wpre += ws[i];
    if (tid < SCAN_NB) g_bpre[tid] = wpre + x - v;
}

__global__ void scan3_kernel() {
    int gid = blockIdx.x * SCAN_T + threadIdx.x;
    if (gid < NN) {
        int o = g_off[gid] + g_bpre[gid >> 10];
        g_off[gid] = o;
        g_cursor[gid] = o;
    }
}

// ---------------- K5: permute edges into CSR order (8B records) ----------------
__global__ void scatter_kernel(const float* __restrict__ bit,
                               const int* __restrict__ src, const int* __restrict__ dst) {
    int e = blockIdx.x * blockDim.x + threadIdx.x;
    if (e >= NE) return;
    int s = src[e], d = dst[e];
    float b = bit[e];
    float ep = g_ah[s] + g_aw * b + g_ab;          // exact fp32 logit (pre-lrelu, pre-af)
    unsigned bq = (unsigned)(b * 32768.f);          // floor quantize, 15 bits (b < 1)
    if (bq > 32767u) bq = 32767u;
    unsigned packed = (unsigned)s | (bq << 17);
    int pos = atomicAdd(&g_cursor[d], 1);
    g_edge[pos] = make_float2(ep, __uint_as_float(packed));
}

// ---------------- K6: fused softmax + weighted fp16 gather + finalize + relu ----------------
__global__ void agg_kernel(const float* __restrict__ Wnm, const float* __restrict__ bnm) {
    int gw = (blockIdx.x * blockDim.x + threadIdx.x) >> 5;
    int lane = threadIdx.x & 31;
    if (gw >= NN) return;
    const int c4 = lane * 4;

    int deg = g_deg[gw];
    __half* tp = &g_t_h[gw * HD + c4];
    if (deg == 0) {
        *(uint2*)tp = make_uint2(0u, 0u);
        return;
    }
    int start = g_off[gw];
    float afd = g_af[gw];
    const float2* eb = &g_edge[start];

    float ax = 0.f, ay = 0.f, az = 0.f, aww = 0.f;
    float sbm;

    if (deg <= 32) {
        float2 ed = eb[lane < deg ? lane : 0];
        unsigned u = __float_as_uint(ed.y);
        float bitf = (float)(u >> 17) * (1.0f / 32768.0f);
        int si = (int)(u & 0x1FFFFu) * HD;
        float v = ed.x + afd;
        v = (v >= 0.f) ? v : 0.2f * v;
        float m = v;
        #pragma unroll
        for (int o = 16; o; o >>= 1) m = fmaxf(m, __shfl_xor_sync(0xffffffffu, m, o));
        float ee = (lane < deg) ? __expf(v - m) : 0.f;
        float s = ee, sb = ee * bitf;
        #pragma unroll
        for (int o = 16; o; o >>= 1) {
            s  += __shfl_xor_sync(0xffffffffu, s, o);
            sb += __shfl_xor_sync(0xffffffffu, sb, o);
        }
        float inv = 1.f / s;
        float wgt = ee * inv;

        for (int base = 0; base < deg; base += 8) {
            float w0 = __shfl_sync(0xffffffffu, wgt, base);
            float w1 = __shfl_sync(0xffffffffu, wgt, base + 1);
            float w2 = __shfl_sync(0xffffffffu, wgt, base + 2);
            float w3 = __shfl_sync(0xffffffffu, wgt, base + 3);
            float w4 = __shfl_sync(0xffffffffu, wgt, base + 4);
            float w5 = __shfl_sync(0xffffffffu, wgt, base + 5);
            float w6 = __shfl_sync(0xffffffffu, wgt, base + 6);
            float w7 = __shfl_sync(0xffffffffu, wgt, base + 7);
            int s0 = __shfl_sync(0xffffffffu, si, base);
            int s1 = __shfl_sync(0xffffffffu, si, base + 1);
            int s2 = __shfl_sync(0xffffffffu, si, base + 2);
            int s3 = __shfl_sync(0xffffffffu, si, base + 3);
            int s4 = __shfl_sync(0xffffffffu, si, base + 4);
            int s5 = __shfl_sync(0xffffffffu, si, base + 5);
            int s6 = __shfl_sync(0xffffffffu, si, base + 6);
            int s7 = __shfl_sync(0xffffffffu, si, base + 7);
            uint2 q0 = *(const uint2*)&g_hz_h[s0 + c4];
            uint2 q1 = *(const uint2*)&g_hz_h[s1 + c4];
            uint2 q2 = *(const uint2*)&g_hz_h[s2 + c4];
            uint2 q3 = *(const uint2*)&g_hz_h[s3 + c4];
            uint2 q4 = *(const uint2*)&g_hz_h[s4 + c4];
            uint2 q5 = *(const uint2*)&g_hz_h[s5 + c4];
            uint2 q6 = *(const uint2*)&g_hz_h[s6 + c4];
            uint2 q7 = *(const uint2*)&g_hz_h[s7 + c4];
            float2 a0 = __half22float2(*(__half2*)&q0.x), b0 = __half22float2(*(__half2*)&q0.y);
            float2 a1 = __half22float2(*(__half2*)&q1.x), b1 = __half22float2(*(__half2*)&q1.y);
            float2 a2 = __half22float2(*(__half2*)&q2.x), b2 = __half22float2(*(__half2*)&q2.y);
            float2 a3 = __half22float2(*(__half2*)&q3.x), b3 = __half22float2(*(__half2*)&q3.y);
            float2 a4 = __half22float2(*(__half2*)&q4.x), b4 = __half22float2(*(__half2*)&q4.y);
            float2 a5 = __half22float2(*(__half2*)&q5.x), b5 = __half22float2(*(__half2*)&q5.y);
            float2 a6 = __half22float2(*(__half2*)&q6.x), b6 = __half22float2(*(__half2*)&q6.y);
            float2 a7 = __half22float2(*(__half2*)&q7.x), b7 = __half22float2(*(__half2*)&q7.y);
            ax += w0*a0.x + w1*a1.x + w2*a2.x + w3*a3.x + w4*a4.x + w5*a5.x + w6*a6.x + w7*a7.x;
            ay += w0*a0.y + w1*a1.y + w2*a2.y + w3*a3.y + w4*a4.y + w5*a5.y + w6*a6.y + w7*a7.y;
            az += w0*b0.x + w1*b1.x + w2*b2.x + w3*b3.x + w4*b4.x + w5*b5.x + w6*b6.x + w7*b7.x;
            aww += w0*b0.y + w1*b1.y + w2*b2.y + w3*b3.y + w4*b4.y + w5*b5.y + w6*b6.y + w7*b7.y;
        }
        sbm = sb * inv;
    } else {
        // slow path (rare: deg > 32)
        float m = -INFINITY;
        for (int i = lane; i < deg; i += 32) {
            float v = eb[i].x + afd;
            v = (v >= 0.f) ? v : 0.2f * v;
            m = fmaxf(m, v);
        }
        #pragma unroll
        for (int o = 16; o; o >>= 1) m = fmaxf(m, __shfl_xor_sync(0xffffffffu, m, o));
        float s = 0.f, sb = 0.f;
        for (int i = lane; i < deg; i += 32) {
            float2 ed = eb[i];
            float v = ed.x + afd;
            v = (v >= 0.f) ? v : 0.2f * v;
            float ee = __expf(v - m);
            s += ee;
            sb += ee * ((float)(__float_as_uint(ed.y) >> 17) * (1.0f / 32768.0f));
        }
        #pragma unroll
        for (int o = 16; o; o >>= 1) {
            s  += __shfl_xor_sync(0xffffffffu, s, o);
            sb += __shfl_xor_sync(0xffffffffu, sb, o);
        }
        float inv = 1.f / s;
        for (int base = 0; base < deg; base += 4) {
            float2 E0 = eb[base];
            float2 E1 = eb[base + 1];
            float2 E2 = eb[base + 2];
            float2 E3 = eb[base + 3];
            int s0 = (int)(__float_as_uint(E0.y) & 0x1FFFFu) * HD;
            int s1 = (int)(__float_as_uint(E1.y) & 0x1FFFFu) * HD;
            int s2 = (int)(__float_as_uint(E2.y) & 0x1FFFFu) * HD;
            int s3 = (int)(__float_as_uint(E3.y) & 0x1FFFFu) * HD;
            uint2 q0 = *(const uint2*)&g_hz_h[s0 + c4];
            uint2 q1 = *(const uint2*)&g_hz_h[s1 + c4];
            uint2 q2 = *(const uint2*)&g_hz_h[s2 + c4];
            uint2 q3 = *(const uint2*)&g_hz_h[s3 + c4];
            float v0 = E0.x + afd; v0 = (v0 >= 0.f) ? v0 : 0.2f * v0;
            float v1 = E1.x + afd; v1 = (v1 >= 0.f) ? v1 : 0.2f * v1;
            float v2 = E2.x + afd; v2 = (v2 >= 0.f) ? v2 : 0.2f * v2;
            float v3 = E3.x + afd; v3 = (v3 >= 0.f) ? v3 : 0.2f * v3;
            float w0 = __expf(v0 - m) * inv;
            float w1 = (base + 1 < deg) ? __expf(v1 - m) * inv : 0.f;
            float w2 = (base + 2 < deg) ? __expf(v2 - m) * inv : 0.f;
            float w3 = (base + 3 < deg) ? __expf(v3 - m) * inv : 0.f;
            float2 a0 = __half22float2(*(__half2*)&q0.x), b0 = __half22float2(*(__half2*)&q0.y);
            float2 a1 = __half22float2(*(__half2*)&q1.x), b1 = __half22float2(*(__half2*)&q1.y);
            float2 a2 = __half22float2(*(__half2*)&q2.x), b2 = __half22float2(*(__half2*)&q2.y);
            float2 a3 = __half22float2(*(__half2*)&q3.x), b3 = __half22float2(*(__half2*)&q3.y);
            ax += w0 * a0.x + w1 * a1.x + w2 * a2.x + w3 * a3.x;
            ay += w0 * a0.y + w1 * a1.y + w2 * a2.y + w3 * a3.y;
            az += w0 * b0.x + w1 * b1.x + w2 * b2.x + w3 * b3.x;
            aww += w0 * b0.y + w1 * b1.y + w2 * b2.y + w3 * b3.y;
        }
        sbm = sb * inv;
    }

    float4 wb = *(const float4*)&Wnm[128 * HD + c4];
    float4 bn = *(const float4*)&bnm[c4];
    uint2 fzq = *(const uint2*)&g_fz_h[gw * HD + c4];
    float2 fz0 = __half22float2(*(__half2*)&fzq.x);
    float2 fz1 = __half22float2(*(__half2*)&fzq.y);
    float tx = ax + sbm * wb.x + fz0.x + bn.x;
    float ty = ay + sbm * wb.y + fz0.y + bn.y;
    float tz = az + sbm * wb.z + fz1.x + bn.z;
    float tw = aww + sbm * wb.w + fz1.y + bn.w;
    __half2 o0 = __floats2half2_rn(fmaxf(tx, 0.f), fmaxf(ty, 0.f));
    __half2 o1 = __floats2half2_rn(fmaxf(tz, 0.f), fmaxf(tw, 0.f));
    *(uint2*)tp = make_uint2(*(unsigned*)&o0, *(unsigned*)&o1);
}

// ---------------- K7: fp16-mma mlp_out on g_t_h -> out ----------------
__global__ void __launch_bounds__(256) out_kernel(const float* __restrict__ bo1,
                           const float* __restrict__ Wo2, const float* __restrict__ bo2,
                           float* __restrict__ out) {
    __shared__ unsigned sA[64 * 132];   // first 64*68 used as half2 A; reused as fp32 U
    __shared__ float sb1o[128];
    __shared__ float sw2o[128];

    const int tid = threadIdx.x;
    const int n0 = blockIdx.x * 64;
    const unsigned* tsrc = (const unsigned*)g_t_h;

    for (int i = tid; i < 64 * 64; i += 256) {
        int r = i >> 6, kp = i & 63;
        sA[r * 68 + kp] = tsrc[(n0 + r) * 64 + kp];
    }
    if (tid < 128) { sb1o[tid] = bo1[tid]; sw2o[tid] = Wo2[tid]; }
    __syncthreads();

    const int w = tid >> 5, lane = tid & 31;
    const int gy = lane >> 2, gx = lane & 3;
    const int mtb = (w >> 2) * 2;
    const int ntb = (w & 3) * 4;

    float c[2][4][4];
    unsigned a[2][4], b[4][2];
    #pragma unroll
    for (int t = 0; t < 2; t++)
        #pragma unroll
        for (int j = 0; j < 4; j++) {
            int col = (ntb + j) * 8 + 2 * gx;
            c[t][j][0] = sb1o[col];  c[t][j][1] = sb1o[col + 1];
            c[t][j][2] = sb1o[col];  c[t][j][3] = sb1o[col + 1];
        }
    #pragma unroll
    for (int ks = 0; ks < 8; ks++) {
        int k0p = ks * 8;
        #pragma unroll
        for (int t = 0; t < 2; t++) {
            int m0 = (mtb + t) * 16;
            a[t][0] = sA[(m0 + gy) * 68 + k0p + gx];
            a[t][1] = sA[(m0 + gy + 8) * 68 + k0p + gx];
            a[t][2] = sA[(m0 + gy) * 68 + k0p + gx + 4];
            a[t][3] = sA[(m0 + gy + 8) * 68 + k0p + gx + 4];
        }
        #pragma unroll
        for (int j = 0; j < 4; j++) {
            int nn0 = (ntb + j) * 8;
            b[j][0] = __ldg(&g_wo1_h2[(k0p + gx) * HD + nn0 + gy]);
            b[j][1] = __ldg(&g_wo1_h2[(k0p + gx + 4) * HD + nn0 + gy]);
        }
        #pragma unroll
        for (int t = 0; t < 2; t++)
            #pragma unroll
            for (int j = 0; j < 4; j++) mma_f16(c[t][j], a[t], b[j]);
    }
    __syncthreads();   // all mma reads of sA done; reuse as fp32 U

    float* U = (float*)sA;
    #define LR(x) ((x) >= 0.f ? (x) : 0.1f * (x))
    #pragma unroll
    for (int t = 0; t < 2; t++)
        #pragma unroll
        for (int j = 0; j < 4; j++) {
            int r = (mtb + t) * 16 + gy;
            int col = (ntb + j) * 8 + 2 * gx;
            *(float2*)&U[r * 132 + col]       = make_float2(LR(c[t][j][0]), LR(c[t][j][1]));
            *(float2*)&U[(r + 8) * 132 + col] = make_float2(LR(c[t][j][2]), LR(c[t][j][3]));
        }
    #undef LR
    __syncthreads();

    float b2v = bo2[0];
    #pragma unroll
    for (int rr = 0; rr < 8; rr++) {
        int r = w * 8 + rr;
        float p = U[r * 132 + lane]       * sw2o[lane]
                + U[r * 132 + lane + 32]  * sw2o[lane + 32]
                + U[r * 132 + lane + 64]  * sw2o[lane + 64]
                + U[r * 132 + lane + 96]  * sw2o[lane + 96];
        #pragma unroll
        for (int o = 16; o; o >>= 1) p += __shfl_xor_sync(0xffffffffu, p, o);
        int gr = n0 + r;
        if (lane == 0 && gr < NN) out[gr] = p + b2v;
    }
}

// ---------------- launch ----------------
extern "C" void kernel_launch(void* const* d_in, const int* in_sizes, int n_in,
                              void* d_out, int out_size) {
    const float* feat = (const float*)d_in[0];
    const float* bit  = (const float*)d_in[1];
    const int*   src  = (const int*)d_in[2];
    const int*   dst  = (const int*)d_in[3];
    const float* W1   = (const float*)d_in[4];
    const float* b1   = (const float*)d_in[5];
    const float* W2   = (const float*)d_in[6];
    const float* b2   = (const float*)d_in[7];
    const float* Wnm  = (const float*)d_in[8];
    const float* bnm  = (const float*)d_in[9];
    const float* attn = (const float*)d_in[10];
    const float* Wo1  = (const float*)d_in[11];
    const float* bo1  = (const float*)d_in[12];
    const float* Wo2  = (const float*)d_in[13];
    const float* bo2  = (const float*)d_in[14];
    float* out = (float*)d_out;

    precompute_kernel<<<1, 256>>>(Wnm, bnm, attn, W2, b2);
    wcomb_kernel<<<32, 128>>>(W2, Wnm);
    wo1h_kernel<<<32, 256>>>(Wo1);
    node_kernel<<<NB64, 256>>>(feat, W1, b1);
    hist_kernel<<<NE / 256, 256>>>(dst);
    scan1_kernel<<<SCAN_NB, SCAN_T>>>();
    scan2_kernel<<<1, 128>>>();
    scan3_kernel<<<SCAN_NB, SCAN_T>>>();
    scatter_kernel<<<NE / 256, 256>>>(bit, src, dst);
    agg_kernel<<<(NN + 7) / 8, 256>>>(Wnm, bnm);
    out_kernel<<<NB64, 256>>>(bo1, Wo2, bo2, out);
}

// round 16
// speedup vs baseline: 4.4739x; 1.0882x over previous
#include <cuda_runtime.h>
#include <cuda_fp16.h>
#include <math.h>

#define NN 100000
#define NE 1600000
#define FD 16
#define HD 128
#define NB64 1563                 // ceil(NN/64)
#define SCAN_T 1024
#define SCAN_NB ((NN + SCAN_T - 1) / SCAN_T)   // 98

// ---------------- scratch (static device globals; no allocation) ----------------
__device__ __half g_hz_h[(NN + 64) * HD];   // fp16 hz payload for the gather
__device__ __half g_fz_h[(NN + 64) * HD];   // fp16 fz
__device__ __half g_t_h[(NN + 64) * HD];    // fp16 t (relu'd neigh final)
__device__ float g_ah[NN];
__device__ float g_af[NN];
__device__ unsigned g_wcomb_h2[32 * HD];   // half2-packed (k-pairs) W2@Wh
__device__ unsigned g_wf_tf[FD * HD];      // tf32 feat rows of Wnm
__device__ unsigned g_wo1_h2[64 * HD];     // half2-packed Wo1
__device__ float g_bcomb[HD];              // b2 @ Wh
__device__ float g_vah[64];                // W2 @ wha
__device__ float g_vahb;                   // b2 . wha
__device__ float g_wfa[FD];
__device__ float g_aw;
__device__ float g_ab;
// CSR build
__device__ int   g_deg[NN];
__device__ int   g_off[NN];
__device__ int   g_cursor[NN];
__device__ int   g_bsum[SCAN_NB];
__device__ int   g_bpre[SCAN_NB];
// permuted edges (8B): x = logit (fp32, exact bit folded in), y = bits{src:17 | bitq:15<<17}
__device__ float2 g_edge[NE + 8];

// ---------------- mma helpers ----------------
__device__ __forceinline__ unsigned f2tf32(float x) {
    unsigned r;
    asm("cvt.rna.tf32.f32 %0, %1;" : "=r"(r) : "f"(x));
    return r;
}
__device__ __forceinline__ void mma_tf32(float c[4], const unsigned a[4], const unsigned b[2]) {
    asm("mma.sync.aligned.m16n8k8.row.col.f32.tf32.tf32.f32 "
        "{%0,%1,%2,%3},{%4,%5,%6,%7},{%8,%9},{%0,%1,%2,%3};"
        : "+f"(c[0]), "+f"(c[1]), "+f"(c[2]), "+f"(c[3])
        : "r"(a[0]), "r"(a[1]), "r"(a[2]), "r"(a[3]), "r"(b[0]), "r"(b[1]));
}
__device__ __forceinline__ void mma_f16(float c[4], const unsigned a[4], const unsigned b[2]) {
    asm("mma.sync.aligned.m16n8k16.row.col.f32.f16.f16.f32 "
        "{%0,%1,%2,%3},{%4,%5,%6,%7},{%8,%9},{%0,%1,%2,%3};"
        : "+f"(c[0]), "+f"(c[1]), "+f"(c[2]), "+f"(c[3])
        : "r"(a[0]), "r"(a[1]), "r"(a[2]), "r"(a[3]), "r"(b[0]), "r"(b[1]));
}

// ---------------- K0 fused: attn folding + wcomb + wo1 packing ----------------
__global__ void prep_kernel(const float* __restrict__ Wnm,
                            const float* __restrict__ bnm,
                            const float* __restrict__ attn,
                            const float* __restrict__ W2,
                            const float* __restrict__ b2,
                            const float* __restrict__ Wo1) {
    int tid = threadIdx.x;
    int blk = blockIdx.x;
    if (blk == 0) {
        __shared__ float sattn[HD];
        __shared__ float swha[HD];
        if (tid < HD) sattn[tid] = attn[tid];
        __syncthreads();
        if (tid < HD) {
            float s = 0.f;
            #pragma unroll 8
            for (int j = 0; j < HD; j++) s += Wnm[tid * HD + j] * sattn[j];
            swha[tid] = s;
        } else if (tid < HD + FD) {
            int i = tid - HD;
            float s = 0.f;
            #pragma unroll 8
            for (int j = 0; j < HD; j++) s += Wnm[(129 + i) * HD + j] * sattn[j];
            g_wfa[i] = s;
        } else if (tid == HD + FD) {
            float s = 0.f;
            for (int j = 0; j < HD; j++) s += Wnm[128 * HD + j] * sattn[j];
            g_aw = s;
        } else if (tid == HD + FD + 1) {
            float s = 0.f;
            for (int j = 0; j < HD; j++) s += bnm[j] * sattn[j];
            g_ab = s;
        } else if (tid < HD + FD + 10) {
            g_edge[NE + (tid - HD - FD - 2)] = make_float2(0.f, 0.f);
        }
        __syncthreads();
        if (tid < 64) {
            float s = 0.f;
            #pragma unroll 8
            for (int k = 0; k < HD; k++) s += W2[tid * HD + k] * swha[k];
            g_vah[tid] = s;
        } else if (tid == 64) {
            float s = 0.f;
            for (int k = 0; k < HD; k++) s += b2[k] * swha[k];
            g_vahb = s;
        }
        if (tid < HD) {
            float s = 0.f;
            #pragma unroll 8
            for (int k = 0; k < HD; k++) s += b2[k] * Wnm[k * HD + tid];
            g_bcomb[tid] = s;
        }
        for (int i = tid; i < FD * HD; i += 256)
            g_wf_tf[i] = f2tf32(Wnm[(129 + (i >> 7)) * HD + (i & 127)]);
    } else if (blk <= 32) {
        // wcomb: half2(W2 @ Wh), k-pair packed
        int kp = blk - 1;            // 0..31
        if (tid < 128) {
            int c = tid;
            float s0 = 0.f, s1 = 0.f;
            #pragma unroll 8
            for (int k = 0; k < HD; k++) {
                float w = Wnm[k * HD + c];
                s0 += W2[(2 * kp) * HD + k] * w;
                s1 += W2[(2 * kp + 1) * HD + k] * w;
            }
            __half2 h = __floats2half2_rn(s0, s1);
            g_wcomb_h2[kp * HD + c] = *(unsigned*)&h;
        }
    } else {
        // wo1 half2 packing
        int i = (blk - 33) * 256 + tid;   // < 8192
        int kp = i >> 7, c = i & 127;
        __half2 h = __floats2half2_rn(Wo1[(2 * kp) * HD + c], Wo1[(2 * kp + 1) * HD + c]);
        g_wo1_h2[i] = *(unsigned*)&h;
    }
}

// ---------------- K1: fused node kernel (all-mma) ----------------
#define LR01(x) ((x) >= 0.f ? (x) : 0.1f * (x))
__global__ void __launch_bounds__(256, 4) node_kernel(const float* __restrict__ feat,
                            const float* __restrict__ W1, const float* __restrict__ b1) {
    __shared__ unsigned sW1tf[16 * 68];   // tf32 W1 [k][j], stride 68
    __shared__ unsigned As2tf[64 * 20];   // tf32 feat [r][k], stride 20
    __shared__ unsigned As1[64 * 36];     // fp16 hid half2 [r][jp], stride 36 words
    __shared__ float sb1[64];
    __shared__ float sv[64];
    __shared__ float swfa[FD];
    __shared__ float sbc[HD];
    __shared__ float sah[64];

    const int tid = threadIdx.x;
    const int n0 = blockIdx.x * 64;
    const int lane = tid & 31;

    for (int i = tid; i < 1024; i += 256) sW1tf[(i >> 6) * 68 + (i & 63)] = f2tf32(W1[i]);
    if (tid < 64) { sb1[tid] = b1[tid]; sv[tid] = g_vah[tid]; sah[tid] = 0.f; }
    if (tid < FD) swfa[tid] = g_wfa[tid];
    if (tid < HD) sbc[tid] = g_bcomb[tid];
    for (int i = tid; i < 64 * FD; i += 256) {
        int gr = n0 + (i >> 4);
        float v = (gr < NN) ? feat[gr * FD + (i & 15)] : 0.f;
        As2tf[(i >> 4) * 20 + (i & 15)] = f2tf32(v);
    }
    __syncthreads();

    const int w = tid >> 5;
    const int gy = lane >> 2, gx = lane & 3;

    // ---- hid = lrelu(feat @ W1 + b1): tf32 mma, M=64 N=64 K=16 ----
    {
        const int mt = w >> 1, ng = w & 1;
        const int m0 = mt * 16;
        float c2[4][4];
        #pragma unroll
        for (int j = 0; j < 4; j++) {
            int col = ng * 32 + j * 8 + 2 * gx;
            c2[j][0] = sb1[col];  c2[j][1] = sb1[col + 1];
            c2[j][2] = sb1[col];  c2[j][3] = sb1[col + 1];
        }
        unsigned a2[4], bb[2];
        #pragma unroll
        for (int ks = 0; ks < 2; ks++) {
            int k0 = ks * 8;
            a2[0] = As2tf[(m0 + gy) * 20 + k0 + gx];
            a2[1] = As2tf[(m0 + gy + 8) * 20 + k0 + gx];
            a2[2] = As2tf[(m0 + gy) * 20 + k0 + gx + 4];
            a2[3] = As2tf[(m0 + gy + 8) * 20 + k0 + gx + 4];
            #pragma unroll
            for (int j = 0; j < 4; j++) {
                int col0 = ng * 32 + j * 8;
                bb[0] = sW1tf[(k0 + gx) * 68 + col0 + gy];
                bb[1] = sW1tf[(k0 + gx + 4) * 68 + col0 + gy];
                mma_tf32(c2[j], a2, bb);
            }
        }
        // lrelu + fp16 store + ah partials (fp32, from accumulators)
        float pa0 = 0.f, pa8 = 0.f;
        #pragma unroll
        for (int j = 0; j < 4; j++) {
            int col = ng * 32 + j * 8 + 2 * gx;
            float l0 = LR01(c2[j][0]), l1 = LR01(c2[j][1]);
            float l2 = LR01(c2[j][2]), l3 = LR01(c2[j][3]);
            __half2 h0 = __floats2half2_rn(l0, l1);
            __half2 h1 = __floats2half2_rn(l2, l3);
            As1[(m0 + gy) * 36 + (col >> 1)]     = *(unsigned*)&h0;
            As1[(m0 + gy + 8) * 36 + (col >> 1)] = *(unsigned*)&h1;
            pa0 += l0 * sv[col] + l1 * sv[col + 1];
            pa8 += l2 * sv[col] + l3 * sv[col + 1];
        }
        pa0 += __shfl_xor_sync(0xffffffffu, pa0, 1);
        pa0 += __shfl_xor_sync(0xffffffffu, pa0, 2);
        pa8 += __shfl_xor_sync(0xffffffffu, pa8, 1);
        pa8 += __shfl_xor_sync(0xffffffffu, pa8, 2);
        if (gx == 0) {
            atomicAdd(&sah[m0 + gy], pa0);
            atomicAdd(&sah[m0 + gy + 8], pa8);
        }
    }
    __syncthreads();

    // per-node scalars
    if (tid < 64) {
        int gn = n0 + tid;
        if (gn < NN) {
            g_ah[gn] = sah[tid] + g_vahb;
            const float4* fp4 = (const float4*)&feat[gn * FD];
            float4 f0 = fp4[0], f1 = fp4[1], f2v = fp4[2], f3 = fp4[3];
            float af = f0.x*swfa[0] + f0.y*swfa[1] + f0.z*swfa[2] + f0.w*swfa[3]
                     + f1.x*swfa[4] + f1.y*swfa[5] + f1.z*swfa[6] + f1.w*swfa[7]
                     + f2v.x*swfa[8] + f2v.y*swfa[9] + f2v.z*swfa[10] + f2v.w*swfa[11]
                     + f3.x*swfa[12] + f3.y*swfa[13] + f3.z*swfa[14] + f3.w*swfa[15];
            g_af[gn] = af;
            g_deg[gn] = 0;
        }
    }

    const int mtb = (w >> 2) * 2;        // 2 M-tiles of 16
    const int ntb = (w & 3) * 4;         // 4 N-tiles of 8

    float c[2][4][4];
    unsigned a[2][4], b[4][2];

    // ---- hz = hid @ Wcomb + bcomb  (fp16 mma, K=64 -> 4 k16 steps; stored fp16) ----
    #pragma unroll
    for (int t = 0; t < 2; t++)
        #pragma unroll
        for (int j = 0; j < 4; j++) {
            int col = (ntb + j) * 8 + 2 * gx;
            c[t][j][0] = sbc[col];  c[t][j][1] = sbc[col + 1];
            c[t][j][2] = sbc[col];  c[t][j][3] = sbc[col + 1];
        }
    #pragma unroll
    for (int ks = 0; ks < 4; ks++) {
        int k0p = ks * 8;
        #pragma unroll
        for (int t = 0; t < 2; t++) {
            int m0 = (mtb + t) * 16;
            a[t][0] = As1[(m0 + gy) * 36 + k0p + gx];
            a[t][1] = As1[(m0 + gy + 8) * 36 + k0p + gx];
            a[t][2] = As1[(m0 + gy) * 36 + k0p + gx + 4];
            a[t][3] = As1[(m0 + gy + 8) * 36 + k0p + gx + 4];
        }
        #pragma unroll
        for (int j = 0; j < 4; j++) {
            int nn0 = (ntb + j) * 8;
            b[j][0] = __ldg(&g_wcomb_h2[(k0p + gx) * HD + nn0 + gy]);
            b[j][1] = __ldg(&g_wcomb_h2[(k0p + gx + 4) * HD + nn0 + gy]);
        }
        #pragma unroll
        for (int t = 0; t < 2; t++)
            #pragma unroll
            for (int j = 0; j < 4; j++) mma_f16(c[t][j], a[t], b[j]);
    }
    #pragma unroll
    for (int t = 0; t < 2; t++)
        #pragma unroll
        for (int j = 0; j < 4; j++) {
            int r = (mtb + t) * 16 + gy;
            int col = (ntb + j) * 8 + 2 * gx;
            *(__half2*)&g_hz_h[(n0 + r) * HD + col]     = __floats2half2_rn(c[t][j][0], c[t][j][1]);
            *(__half2*)&g_hz_h[(n0 + r + 8) * HD + col] = __floats2half2_rn(c[t][j][2], c[t][j][3]);
        }

    // ---- fz = feat @ Wf  (tf32 mma, K=16 -> 2 k8 steps; stored fp16) ----
    #pragma unroll
    for (int t = 0; t < 2; t++)
        #pragma unroll
        for (int j = 0; j < 4; j++) {
            c[t][j][0] = 0.f; c[t][j][1] = 0.f; c[t][j][2] = 0.f; c[t][j][3] = 0.f;
        }
    #pragma unroll
    for (int ks = 0; ks < 2; ks++) {
        int k0 = ks * 8;
        #pragma unroll
        for (int t = 0; t < 2; t++) {
            int m0 = (mtb + t) * 16;
            a[t][0] = As2tf[(m0 + gy) * 20 + k0 + gx];
            a[t][1] = As2tf[(m0 + gy + 8) * 20 + k0 + gx];
            a[t][2] = As2tf[(m0 + gy) * 20 + k0 + gx + 4];
            a[t][3] = As2tf[(m0 + gy + 8) * 20 + k0 + gx + 4];
        }
        #pragma unroll
        for (int j = 0; j < 4; j++) {
            int nn0 = (ntb + j) * 8;
            b[j][0] = __ldg(&g_wf_tf[(k0 + gx) * HD + nn0 + gy]);
            b[j][1] = __ldg(&g_wf_tf[(k0 + gx + 4) * HD + nn0 + gy]);
        }
        #pragma unroll
        for (int t = 0; t < 2; t++)
            #pragma unroll
            for (int j = 0; j < 4; j++) mma_tf32(c[t][j], a[t], b[j]);
    }
    #pragma unroll
    for (int t = 0; t < 2; t++)
        #pragma unroll
        for (int j = 0; j < 4; j++) {
            int r = (mtb + t) * 16 + gy;
            int col = (ntb + j) * 8 + 2 * gx;
            *(__half2*)&g_fz_h[(n0 + r) * HD + col]     = __floats2half2_rn(c[t][j][0], c[t][j][1]);
            *(__half2*)&g_fz_h[(n0 + r + 8) * HD + col] = __floats2half2_rn(c[t][j][2], c[t][j][3]);
        }
}

// ---------------- K3: degree histogram (4 edges/thread) ----------------
__global__ void hist_kernel(const int* __restrict__ dst) {
    int t = blockIdx.x * blockDim.x + threadIdx.x;
    if (t >= NE / 4) return;
    int4 d = ((const int4*)dst)[t];
    atomicAdd(&g_deg[d.x], 1);
    atomicAdd(&g_deg[d.y], 1);
    atomicAdd(&g_deg[d.z], 1);
    atomicAdd(&g_deg[d.w], 1);
}

// ---------------- K4: exclusive scan of g_deg ----------------
__global__ void scan1_kernel() {
    __shared__ int wsum[32];
    int tid = threadIdx.x, lane = tid & 31, wid = tid >> 5;
    int gid = blockIdx.x * SCAN_T + tid;
    int v = (gid < NN) ? g_deg[gid] : 0;
    int x = v;
    #pragma unroll
    for (int o = 1; o < 32; o <<= 1) {
        int y = __shfl_up_sync(0xffffffffu, x, o);
        if (lane >= o) x += y;
    }
    if (lane == 31) wsum[wid] = x;
    __syncthreads();
    if (wid == 0) {
        int w = wsum[lane];
        #pragma unroll
        for (int o = 1; o < 32; o <<= 1) {
            int y = __shfl_up_sync(0xffffffffu, w, o);
            if (lane >= o) w += y;
        }
        wsum[lane] = w;
    }
    __syncthreads();
    int wpre = (wid == 0) ? 0 : wsum[wid - 1];
    if (gid < NN) g_off[gid] = wpre + x - v;
    if (tid == SCAN_T - 1) g_bsum[blockIdx.x] = wpre + x;
}

__global__ void scan2_kernel() {
    __shared__ int ws[4];
    int tid = threadIdx.x, lane = tid & 31, wid = tid >> 5;
    int v = (tid < SCAN_NB) ? g_bsum[tid] : 0;
    int x = v;
    #pragma unroll
    for (int o = 1; o < 32; o <<= 1) {
        int y = __shfl_up_sync(0xffffffffu, x, o);
        if (lane >= o) x += y;
    }
    if (lane == 31) ws[wid] = x;
    __syncthreads();
    int wpre = 0;
    #pragma unroll
    for (int i = 0; i < 4; i++) if (i < wid) wpre += ws[i];
    if (tid < SCAN_NB) g_bpre[tid] = wpre + x - v;
}

__global__ void scan3_kernel() {
    int gid = blockIdx.x * SCAN_T + threadIdx.x;
    if (gid < NN) {
        int o = g_off[gid] + g_bpre[gid >> 10];
        g_off[gid] = o;
        g_cursor[gid] = o;
    }
}

// ---------------- K5: permute edges into CSR order (2 edges/thread) ----------------
__global__ void scatter_kernel(const float* __restrict__ bit,
                               const int* __restrict__ src, const int* __restrict__ dst) {
    int t = blockIdx.x * blockDim.x + threadIdx.x;   // t < NE/2
    int2 s2 = ((const int2*)src)[t];
    int2 d2 = ((const int2*)dst)[t];
    float2 bb = ((const float2*)bit)[t];
    float ah0 = g_ah[s2.x], ah1 = g_ah[s2.y];
    float ep0 = ah0 + g_aw * bb.x + g_ab;
    float ep1 = ah1 + g_aw * bb.y + g_ab;
    unsigned bq0 = (unsigned)(bb.x * 32768.f); if (bq0 > 32767u) bq0 = 32767u;
    unsigned bq1 = (unsigned)(bb.y * 32768.f); if (bq1 > 32767u) bq1 = 32767u;
    unsigned p0 = (unsigned)s2.x | (bq0 << 17);
    unsigned p1 = (unsigned)s2.y | (bq1 << 17);
    int pos0 = atomicAdd(&g_cursor[d2.x], 1);
    int pos1 = atomicAdd(&g_cursor[d2.y], 1);
    g_edge[pos0] = make_float2(ep0, __uint_as_float(p0));
    g_edge[pos1] = make_float2(ep1, __uint_as_float(p1));
}

// ---------------- K6: fused softmax + weighted fp16 gather + finalize + relu ----------------
__global__ void agg_kernel(const float* __restrict__ Wnm, const float* __restrict__ bnm) {
    int gw = (blockIdx.x * blockDim.x + threadIdx.x) >> 5;
    int lane = threadIdx.x & 31;
    if (gw >= NN) return;
    const int c4 = lane * 4;

    int deg = g_deg[gw];
    __half* tp = &g_t_h[gw * HD + c4];
    if (deg == 0) {
        *(uint2*)tp = make_uint2(0u, 0u);
        return;
    }
    int start = g_off[gw];
    float afd = g_af[gw];
    const float2* eb = &g_edge[start];

    float ax = 0.f, ay = 0.f, az = 0.f, aww = 0.f;
    float sbm;

    if (deg <= 32) {
        float2 ed = eb[lane < deg ? lane : 0];
        unsigned u = __float_as_uint(ed.y);
        float bitf = (float)(u >> 17) * (1.0f / 32768.0f);
        int si = (int)(u & 0x1FFFFu) * HD;
        float v = ed.x + afd;
        v = (v >= 0.f) ? v : 0.2f * v;
        float m = v;
        #pragma unroll
        for (int o = 16; o; o >>= 1) m = fmaxf(m, __shfl_xor_sync(0xffffffffu, m, o));
        float ee = (lane < deg) ? __expf(v - m) : 0.f;
        float s = ee, sb = ee * bitf;
        #pragma unroll
        for (int o = 16; o; o >>= 1) {
            s  += __shfl_xor_sync(0xffffffffu, s, o);
            sb += __shfl_xor_sync(0xffffffffu, sb, o);
        }
        float inv = 1.f / s;
        float wgt = ee * inv;

        for (int base = 0; base < deg; base += 8) {
            float w0 = __shfl_sync(0xffffffffu, wgt, base);
            float w1 = __shfl_sync(0xffffffffu, wgt, base + 1);
            float w2 = __shfl_sync(0xffffffffu, wgt, base + 2);
            float w3 = __shfl_sync(0xffffffffu, wgt, base + 3);
            float w4 = __shfl_sync(0xffffffffu, wgt, base + 4);
            float w5 = __shfl_sync(0xffffffffu, wgt, base + 5);
            float w6 = __shfl_sync(0xffffffffu, wgt, base + 6);
            float w7 = __shfl_sync(0xffffffffu, wgt, base + 7);
            int s0 = __shfl_sync(0xffffffffu, si, base);
            int s1 = __shfl_sync(0xffffffffu, si, base + 1);
            int s2 = __shfl_sync(0xffffffffu, si, base + 2);
            int s3 = __shfl_sync(0xffffffffu, si, base + 3);
            int s4 = __shfl_sync(0xffffffffu, si, base + 4);
            int s5 = __shfl_sync(0xffffffffu, si, base + 5);
            int s6 = __shfl_sync(0xffffffffu, si, base + 6);
            int s7 = __shfl_sync(0xffffffffu, si, base + 7);
            uint2 q0 = *(const uint2*)&g_hz_h[s0 + c4];
            uint2 q1 = *(const uint2*)&g_hz_h[s1 + c4];
            uint2 q2 = *(const uint2*)&g_hz_h[s2 + c4];
            uint2 q3 = *(const uint2*)&g_hz_h[s3 + c4];
            uint2 q4 = *(const uint2*)&g_hz_h[s4 + c4];
            uint2 q5 = *(const uint2*)&g_hz_h[s5 + c4];
            uint2 q6 = *(const uint2*)&g_hz_h[s6 + c4];
            uint2 q7 = *(const uint2*)&g_hz_h[s7 + c4];
            float2 a0 = __half22float2(*(__half2*)&q0.x), b0 = __half22float2(*(__half2*)&q0.y);
            float2 a1 = __half22float2(*(__half2*)&q1.x), b1 = __half22float2(*(__half2*)&q1.y);
            float2 a2 = __half22float2(*(__half2*)&q2.x), b2 = __half22float2(*(__half2*)&q2.y);
            float2 a3 = __half22float2(*(__half2*)&q3.x), b3 = __half22float2(*(__half2*)&q3.y);
            float2 a4 = __half22float2(*(__half2*)&q4.x), b4 = __half22float2(*(__half2*)&q4.y);
            float2 a5 = __half22float2(*(__half2*)&q5.x), b5 = __half22float2(*(__half2*)&q5.y);
            float2 a6 = __half22float2(*(__half2*)&q6.x), b6 = __half22float2(*(__half2*)&q6.y);
            float2 a7 = __half22float2(*(__half2*)&q7.x), b7 = __half22float2(*(__half2*)&q7.y);
            ax += w0*a0.x + w1*a1.x + w2*a2.x + w3*a3.x + w4*a4.x + w5*a5.x + w6*a6.x + w7*a7.x;
            ay += w0*a0.y + w1*a1.y + w2*a2.y + w3*a3.y + w4*a4.y + w5*a5.y + w6*a6.y + w7*a7.y;
            az += w0*b0.x + w1*b1.x + w2*b2.x + w3*b3.x + w4*b4.x + w5*b5.x + w6*b6.x + w7*b7.x;
            aww += w0*b0.y + w1*b1.y + w2*b2.y + w3*b3.y + w4*b4.y + w5*b5.y + w6*b6.y + w7*b7.y;
        }
        sbm = sb * inv;
    } else {
        // slow path (rare: deg > 32)
        float m = -INFINITY;
        for (int i = lane; i < deg; i += 32) {
            float v = eb[i].x + afd;
            v = (v >= 0.f) ? v : 0.2f * v;
            m = fmaxf(m, v);
        }
        #pragma unroll
        for (int o = 16; o; o >>= 1) m = fmaxf(m, __shfl_xor_sync(0xffffffffu, m, o));
        float s = 0.f, sb = 0.f;
        for (int i = lane; i < deg; i += 32) {
            float2 ed = eb[i];
            float v = ed.x + afd;
            v = (v >= 0.f) ? v : 0.2f * v;
            float ee = __expf(v - m);
            s += ee;
            sb += ee * ((float)(__float_as_uint(ed.y) >> 17) * (1.0f / 32768.0f));
        }
        #pragma unroll
        for (int o = 16; o; o >>= 1) {
            s  += __shfl_xor_sync(0xffffffffu, s, o);
            sb += __shfl_xor_sync(0xffffffffu, sb, o);
        }
        float inv = 1.f / s;
        for (int base = 0; base < deg; base += 4) {
            float2 E0 = eb[base];
            float2 E1 = eb[base + 1];
            float2 E2 = eb[base + 2];
            float2 E3 = eb[base + 3];
            int s0 = (int)(__float_as_uint(E0.y) & 0x1FFFFu) * HD;
            int s1 = (int)(__float_as_uint(E1.y) & 0x1FFFFu) * HD;
            int s2 = (int)(__float_as_uint(E2.y) & 0x1FFFFu) * HD;
            int s3 = (int)(__float_as_uint(E3.y) & 0x1FFFFu) * HD;
            uint2 q0 = *(const uint2*)&g_hz_h[s0 + c4];
            uint2 q1 = *(const uint2*)&g_hz_h[s1 + c4];
            uint2 q2 = *(const uint2*)&g_hz_h[s2 + c4];
            uint2 q3 = *(const uint2*)&g_hz_h[s3 + c4];
            float v0 = E0.x + afd; v0 = (v0 >= 0.f) ? v0 : 0.2f * v0;
            float v1 = E1.x + afd; v1 = (v1 >= 0.f) ? v1 : 0.2f * v1;
            float v2 = E2.x + afd; v2 = (v2 >= 0.f) ? v2 : 0.2f * v2;
            float v3 = E3.x + afd; v3 = (v3 >= 0.f) ? v3 : 0.2f * v3;
            float w0 = __expf(v0 - m) * inv;
            float w1 = (base + 1 < deg) ? __expf(v1 - m) * inv : 0.f;
            float w2 = (base + 2 < deg) ? __expf(v2 - m) * inv : 0.f;
            float w3 = (base + 3 < deg) ? __expf(v3 - m) * inv : 0.f;
            float2 a0 = __half22float2(*(__half2*)&q0.x), b0 = __half22float2(*(__half2*)&q0.y);
            float2 a1 = __half22float2(*(__half2*)&q1.x), b1 = __half22float2(*(__half2*)&q1.y);
            float2 a2 = __half22float2(*(__half2*)&q2.x), b2 = __half22float2(*(__half2*)&q2.y);
            float2 a3 = __half22float2(*(__half2*)&q3.x), b3 = __half22float2(*(__half2*)&q3.y);
            ax += w0 * a0.x + w1 * a1.x + w2 * a2.x + w3 * a3.x;
            ay += w0 * a0.y + w1 * a1.y + w2 * a2.y + w3 * a3.y;
            az += w0 * b0.x + w1 * b1.x + w2 * b2.x + w3 * b3.x;
            aww += w0 * b0.y + w1 * b1.y + w2 * b2.y + w3 * b3.y;
        }
        sbm = sb * inv;
    }

    float4 wb = *(const float4*)&Wnm[128 * HD + c4];
    float4 bn = *(const float4*)&bnm[c4];
    uint2 fzq = *(const uint2*)&g_fz_h[gw * HD + c4];
    float2 fz0 = __half22float2(*(__half2*)&fzq.x);
    float2 fz1 = __half22float2(*(__half2*)&fzq.y);
    float tx = ax + sbm * wb.x + fz0.x + bn.x;
    float ty = ay + sbm * wb.y + fz0.y + bn.y;
    float tz = az + sbm * wb.z + fz1.x + bn.z;
    float tw = aww + sbm * wb.w + fz1.y + bn.w;
    __half2 o0 = __floats2half2_rn(fmaxf(tx, 0.f), fmaxf(ty, 0.f));
    __half2 o1 = __floats2half2_rn(fmaxf(tz, 0.f), fmaxf(tw, 0.f));
    *(uint2*)tp = make_uint2(*(unsigned*)&o0, *(unsigned*)&o1);
}

// ---------------- K7: fp16-mma mlp_out on g_t_h -> out ----------------
__global__ void __launch_bounds__(256) out_kernel(const float* __restrict__ bo1,
                           const float* __restrict__ Wo2, const float* __restrict__ bo2,
                           float* __restrict__ out) {
    __shared__ unsigned sA[64 * 132];   // first 64*68 used as half2 A; reused as fp32 U
    __shared__ float sb1o[128];
    __shared__ float sw2o[128];

    const int tid = threadIdx.x;
    const int n0 = blockIdx.x * 64;
    const unsigned* tsrc = (const unsigned*)g_t_h;

    for (int i = tid; i < 64 * 64; i += 256) {
        int r = i >> 6, kp = i & 63;
        sA[r * 68 + kp] = tsrc[(n0 + r) * 64 + kp];
    }
    if (tid < 128) { sb1o[tid] = bo1[tid]; sw2o[tid] = Wo2[tid]; }
    __syncthreads();

    const int w = tid >> 5, lane = tid & 31;
    const int gy = lane >> 2, gx = lane & 3;
    const int mtb = (w >> 2) * 2;
    const int ntb = (w & 3) * 4;

    float c[2][4][4];
    unsigned a[2][4], b[4][2];
    #pragma unroll
    for (int t = 0; t < 2; t++)
        #pragma unroll
        for (int j = 0; j < 4; j++) {
            int col = (ntb + j) * 8 + 2 * gx;
            c[t][j][0] = sb1o[col];  c[t][j][1] = sb1o[col + 1];
            c[t][j][2] = sb1o[col];  c[t][j][3] = sb1o[col + 1];
        }
    #pragma unroll
    for (int ks = 0; ks < 8; ks++) {
        int k0p = ks * 8;
        #pragma unroll
        for (int t = 0; t < 2; t++) {
            int m0 = (mtb + t) * 16;
            a[t][0] = sA[(m0 + gy) * 68 + k0p + gx];
            a[t][1] = sA[(m0 + gy + 8) * 68 + k0p + gx];
            a[t][2] = sA[(m0 + gy) * 68 + k0p + gx + 4];
            a[t][3] = sA[(m0 + gy + 8) * 68 + k0p + gx + 4];
        }
        #pragma unroll
        for (int j = 0; j < 4; j++) {
            int nn0 = (ntb + j) * 8;
            b[j][0] = __ldg(&g_wo1_h2[(k0p + gx) * HD + nn0 + gy]);
            b[j][1] = __ldg(&g_wo1_h2[(k0p + gx + 4) * HD + nn0 + gy]);
        }
        #pragma unroll
        for (int t = 0; t < 2; t++)
            #pragma unroll
            for (int j = 0; j < 4; j++) mma_f16(c[t][j], a[t], b[j]);
    }
    __syncthreads();   // all mma reads of sA done; reuse as fp32 U

    float* U = (float*)sA;
    #pragma unroll
    for (int t = 0; t < 2; t++)
        #pragma unroll
        for (int j = 0; j < 4; j++) {
            int r = (mtb + t) * 16 + gy;
            int col = (ntb + j) * 8 + 2 * gx;
            *(float2*)&U[r * 132 + col]       = make_float2(LR01(c[t][j][0]), LR01(c[t][j][1]));
            *(float2*)&U[(r + 8) * 132 + col] = make_float2(LR01(c[t][j][2]), LR01(c[t][j][3]));
        }
    __syncthreads();

    float b2v = bo2[0];
    #pragma unroll
    for (int rr = 0; rr < 8; rr++) {
        int r = w * 8 + rr;
        float p = U[r * 132 + lane]       * sw2o[lane]
                + U[r * 132 + lane + 32]  * sw2o[lane + 32]
                + U[r * 132 + lane + 64]  * sw2o[lane + 64]
                + U[r * 132 + lane + 96]  * sw2o[lane + 96];
        #pragma unroll
        for (int o = 16; o; o >>= 1) p += __shfl_xor_sync(0xffffffffu, p, o);
        int gr = n0 + r;
        if (lane == 0 && gr < NN) out[gr] = p + b2v;
    }
}

// ---------------- launch ----------------
extern "C" void kernel_launch(void* const* d_in, const int* in_sizes, int n_in,
                              void* d_out, int out_size) {
    const float* feat = (const float*)d_in[0];
    const float* bit  = (const float*)d_in[1];
    const int*   src  = (const int*)d_in[2];
    const int*   dst  = (const int*)d_in[3];
    const float* W1   = (const float*)d_in[4];
    const float* b1   = (const float*)d_in[5];
    const float* W2   = (const float*)d_in[6];
    const float* b2   = (const float*)d_in[7];
    const float* Wnm  = (const float*)d_in[8];
    const float* bnm  = (const float*)d_in[9];
    const float* attn = (const float*)d_in[10];
    const float* Wo1  = (const float*)d_in[11];
    const float* bo1  = (const float*)d_in[12];
    const float* Wo2  = (const float*)d_in[13];
    const float* bo2  = (const float*)d_in[14];
    float* out = (float*)d_out;

    prep_kernel<<<65, 256>>>(Wnm, bnm, attn, W2, b2, Wo1);
    node_kernel<<<NB64, 256>>>(feat, W1, b1);
    hist_kernel<<<(NE / 4 + 255) / 256, 256>>>(dst);
    scan1_kernel<<<SCAN_NB, SCAN_T>>>();
    scan2_kernel<<<1, 128>>>();
    scan3_kernel<<<SCAN_NB, SCAN_T>>>();
    scatter_kernel<<<NE / 512, 256>>>(bit, src, dst);
    agg_kernel<<<(NN + 7) / 8, 256>>>(Wnm, bnm);
    out_kernel<<<NB64, 256>>>(bo1, Wo2, bo2, out);
}